// round 2
// baseline (speedup 1.0000x reference)
#include <cuda_runtime.h>
#include <math.h>

#define NA    4096
#define NB    8192
#define FDIM  133
#define BFDIM 147
#define HD    256
#define APM   64
#define NMOL  64
#define MAXNB 6

// ---------------- scratch (static device globals; no allocs allowed) ----------------
__device__ float g_qa[NA * FDIM];
__device__ float g_ka[NA * FDIM];
__device__ float g_va[NA * FDIM];
__device__ float g_fe[NA * FDIM];
__device__ float g_inputs[NB * HD];
__device__ float g_msg[NB * HD];
__device__ float g_amsg[NA * HD];
__device__ float g_tmp[NB * HD];     // dmpnn pre-activation / concat buffer (4096*389 fits)
__device__ float g_dmpnn[NB * HD];
__device__ float g_Q[NB * HD];
__device__ float g_K[NB * HD];
__device__ float g_V[NB * HD];
__device__ float g_attV[NB * HD];
__device__ float g_attm[NB * HD];
__device__ float g_atomh[NA * HD];
__device__ float g_hmwa[NA * HD];

// ---------------- generic fp32 GEMM: C[M,N] = A[M,K] @ B[K,N] (+bias)(+relu) -------
template <int RELU, int HASBIAS>
__global__ __launch_bounds__(256) void gemm_k(const float* __restrict__ A,
                                              const float* __restrict__ B,
                                              const float* __restrict__ bias,
                                              float* __restrict__ C,
                                              int Mm, int Nn, int Kk) {
    __shared__ float As[16 * 68];  // As[k][m], padded
    __shared__ float Bs[16 * 68];  // Bs[k][n], padded
    const int tid = threadIdx.x;
    const int tm = tid >> 4, tn = tid & 15;
    const int m0 = blockIdx.y * 64;
    const int n0 = blockIdx.x * 64;
    float acc[4][4] = {};
    for (int k0 = 0; k0 < Kk; k0 += 16) {
#pragma unroll
        for (int i = 0; i < 4; i++) {
            int idx = tid + i * 256;
            int row = idx >> 4, col = idx & 15;
            float vA = 0.f;
            if (m0 + row < Mm && k0 + col < Kk) vA = A[(size_t)(m0 + row) * Kk + k0 + col];
            As[col * 68 + row] = vA;
        }
#pragma unroll
        for (int i = 0; i < 4; i++) {
            int idx = tid + i * 256;
            int row = idx >> 6, col = idx & 63;
            float vB = 0.f;
            if (k0 + row < Kk && n0 + col < Nn) vB = B[(size_t)(k0 + row) * Nn + n0 + col];
            Bs[row * 68 + col] = vB;
        }
        __syncthreads();
#pragma unroll
        for (int kk = 0; kk < 16; kk++) {
            float4 a4 = *(const float4*)&As[kk * 68 + tm * 4];
            float4 b4 = *(const float4*)&Bs[kk * 68 + tn * 4];
            float av[4] = {a4.x, a4.y, a4.z, a4.w};
            float bv[4] = {b4.x, b4.y, b4.z, b4.w};
#pragma unroll
            for (int i = 0; i < 4; i++)
#pragma unroll
                for (int j = 0; j < 4; j++) acc[i][j] += av[i] * bv[j];
        }
        __syncthreads();
    }
#pragma unroll
    for (int i = 0; i < 4; i++) {
        int m = m0 + tm * 4 + i;
        if (m >= Mm) continue;
#pragma unroll
        for (int j = 0; j < 4; j++) {
            int n = n0 + tn * 4 + j;
            if (n >= Nn) continue;
            float v = acc[i][j];
            if (HASBIAS) v += bias[n];
            if (RELU) v = fmaxf(v, 0.f);
            C[(size_t)m * Nn + n] = v;
        }
    }
}

// ---------------- flash attention over bonds: attV = softmax(QK^T/16) @ V ----------
#define FL_SMEM_FLOATS (256 * 68 * 2 + 64 * 256 + 64 * 64 + 192)
__global__ __launch_bounds__(256, 1) void flash_k() {
    extern __shared__ float sm[];
    float* QsT = sm;                 // [256][68] (k-major, padded)
    float* KsT = QsT + 256 * 68;     // [256][68]
    float* Vs = KsT + 256 * 68;      // [64][256]
    float* Sb = Vs + 64 * 256;       // [64][64]
    float* mrow = Sb + 64 * 64;      // 64
    float* lrow = mrow + 64;         // 64
    float* fsc = lrow + 64;          // 64
    const int tid = threadIdx.x;
    const int row0 = blockIdx.x * 64;

    for (int idx = tid; idx < 64 * 256; idx += 256) {
        int a = idx >> 8, k = idx & 255;
        QsT[k * 68 + a] = g_Q[(size_t)(row0 + a) * HD + k];
    }
    if (tid < 64) { mrow[tid] = -1e30f; lrow[tid] = 0.f; }

    const int pr = tid >> 3;
    const int cg = tid & 7;
    const int r0 = pr * 2, r1 = r0 + 1;
    float acc0[32], acc1[32];
#pragma unroll
    for (int c = 0; c < 32; c++) { acc0[c] = 0.f; acc1[c] = 0.f; }
    const int ty = tid >> 4, tx = tid & 15;
    __syncthreads();

    for (int kb = 0; kb < NB; kb += 64) {
        for (int idx = tid; idx < 64 * 256; idx += 256) {
            int b = idx >> 8, k = idx & 255;
            KsT[k * 68 + b] = g_K[(size_t)(kb + b) * HD + k];
        }
        for (int idx = tid * 4; idx < 64 * 256; idx += 1024) {
            *(float4*)&Vs[idx] = *(const float4*)&g_V[(size_t)kb * HD + idx];
        }
        __syncthreads();
        // S = Q K^T * (1/16)
        {
            float sa[4][4] = {};
#pragma unroll 4
            for (int k = 0; k < 256; k++) {
                float4 qa = *(const float4*)&QsT[k * 68 + ty * 4];
                float4 kv = *(const float4*)&KsT[k * 68 + tx * 4];
                float av[4] = {qa.x, qa.y, qa.z, qa.w};
                float bv[4] = {kv.x, kv.y, kv.z, kv.w};
#pragma unroll
                for (int i = 0; i < 4; i++)
#pragma unroll
                    for (int j = 0; j < 4; j++) sa[i][j] += av[i] * bv[j];
            }
#pragma unroll
            for (int i = 0; i < 4; i++)
#pragma unroll
                for (int j = 0; j < 4; j++)
                    Sb[(ty * 4 + i) * 64 + tx * 4 + j] = sa[i][j] * 0.0625f;
        }
        __syncthreads();
        if (tid < 64) {
            float mc = -1e30f;
#pragma unroll 8
            for (int j = 0; j < 64; j++) mc = fmaxf(mc, Sb[tid * 64 + j]);
            float mn = fmaxf(mrow[tid], mc);
            fsc[tid] = __expf(mrow[tid] - mn);
            mrow[tid] = mn;
        }
        __syncthreads();
#pragma unroll
        for (int i = 0; i < 4; i++) {
            float mi = mrow[ty * 4 + i];
#pragma unroll
            for (int j = 0; j < 4; j++) {
                int off = (ty * 4 + i) * 64 + tx * 4 + j;
                Sb[off] = __expf(Sb[off] - mi);
            }
        }
        __syncthreads();
        if (tid < 64) {
            float s = 0.f;
#pragma unroll 8
            for (int j = 0; j < 64; j++) s += Sb[tid * 64 + j];
            lrow[tid] = lrow[tid] * fsc[tid] + s;
        }
        // O rescale + accumulate P@V
        {
            float f0 = fsc[r0], f1 = fsc[r1];
#pragma unroll
            for (int c = 0; c < 32; c++) { acc0[c] *= f0; acc1[c] *= f1; }
#pragma unroll 2
            for (int j = 0; j < 64; j++) {
                float p0 = Sb[r0 * 64 + j], p1 = Sb[r1 * 64 + j];
#pragma unroll
                for (int i = 0; i < 8; i++) {
                    float4 v = *(const float4*)&Vs[j * 256 + cg * 32 + i * 4];
                    acc0[i * 4 + 0] += p0 * v.x; acc0[i * 4 + 1] += p0 * v.y;
                    acc0[i * 4 + 2] += p0 * v.z; acc0[i * 4 + 3] += p0 * v.w;
                    acc1[i * 4 + 0] += p1 * v.x; acc1[i * 4 + 1] += p1 * v.y;
                    acc1[i * 4 + 2] += p1 * v.z; acc1[i * 4 + 3] += p1 * v.w;
                }
            }
        }
        __syncthreads();
    }
    float li0 = 1.f / lrow[r0], li1 = 1.f / lrow[r1];
#pragma unroll
    for (int c = 0; c < 32; c++) {
        g_attV[(size_t)(row0 + r0) * HD + cg * 32 + c] = acc0[c] * li0;
        g_attV[(size_t)(row0 + r1) * HD + cg * 32 + c] = acc1[c] * li1;
    }
}

// ---------------- per-molecule atom self-attention + residual + LayerNorm ----------
#define AT_SMEM_FLOATS (4 * 64 * 136 + 64 * 64 + 512 + 128)
__global__ __launch_bounds__(256, 1) void atom_attn_ln_k(const float* __restrict__ xg,
                                                         const float* __restrict__ gw,
                                                         const float* __restrict__ bw) {
    extern __shared__ float sm[];
    float* sx = sm;                 // [64][136]
    float* sq = sx + 64 * 136;
    float* sk = sq + 64 * 136;
    float* sv = sk + 64 * 136;
    float* ss = sv + 64 * 136;      // [64][64]
    float* sred = ss + 4096;        // 512
    float* srow = sred + 512;       // 128 (mu, rstd)
    const int tid = threadIdx.x;
    const int base = blockIdx.x * 64;

    for (int idx = tid; idx < 64 * FDIM; idx += 256) {
        int a = idx / FDIM, f = idx - a * FDIM;
        size_t go = (size_t)(base + a) * FDIM + f;
        sx[a * 136 + f] = xg[go];
        sq[a * 136 + f] = g_qa[go];
        sk[a * 136 + f] = g_ka[go];
        sv[a * 136 + f] = g_va[go];
    }
    __syncthreads();
    {
        int ty = tid >> 4, tx = tid & 15;
        float acc[4][4] = {};
        for (int h = 0; h < FDIM; h++) {
            float qv[4], kv[4];
#pragma unroll
            for (int i = 0; i < 4; i++) {
                qv[i] = sq[(ty * 4 + i) * 136 + h];
                kv[i] = sk[(tx * 4 + i) * 136 + h];
            }
#pragma unroll
            for (int i = 0; i < 4; i++)
#pragma unroll
                for (int j = 0; j < 4; j++) acc[i][j] += qv[i] * kv[j];
        }
        float scl = rsqrtf(133.0f);
#pragma unroll
        for (int i = 0; i < 4; i++)
#pragma unroll
            for (int j = 0; j < 4; j++)
                ss[(ty * 4 + i) * 64 + tx * 4 + j] = acc[i][j] * scl;
    }
    __syncthreads();
    if (tid < 64) {
        float mx = -1e30f;
        for (int j = 0; j < 64; j++) mx = fmaxf(mx, ss[tid * 64 + j]);
        float s = 0.f;
        for (int j = 0; j < 64; j++) {
            float e = __expf(ss[tid * 64 + j] - mx);
            ss[tid * 64 + j] = e; s += e;
        }
        float inv = 1.f / s;
        for (int j = 0; j < 64; j++) ss[tid * 64 + j] *= inv;
    }
    __syncthreads();
    const int r = tid >> 2, qd = tid & 3;
    const int f0 = qd * 34;
    float tv[34];
#pragma unroll
    for (int f = 0; f < 34; f++) tv[f] = 0.f;
    for (int b = 0; b < 64; b++) {
        float p = ss[r * 64 + b];
        const float* vb = &sv[b * 136 + f0];
#pragma unroll
        for (int f = 0; f < 34; f++)
            if (f0 + f < FDIM) tv[f] += p * vb[f];
    }
    float s1 = 0.f;
#pragma unroll
    for (int f = 0; f < 34; f++)
        if (f0 + f < FDIM) { tv[f] += sx[r * 136 + f0 + f]; s1 += tv[f]; }
    sred[tid] = s1;
    __syncthreads();
    if (qd == 0) {
        float mu = (sred[tid] + sred[tid + 1] + sred[tid + 2] + sred[tid + 3]) * (1.f / 133.f);
        srow[r] = mu;
    }
    __syncthreads();
    float mu = srow[r];
    float s2 = 0.f;
#pragma unroll
    for (int f = 0; f < 34; f++)
        if (f0 + f < FDIM) { float d = tv[f] - mu; s2 += d * d; }
    sred[tid] = s2;
    __syncthreads();
    if (qd == 0) {
        float var = (sred[tid] + sred[tid + 1] + sred[tid + 2] + sred[tid + 3]) * (1.f / 133.f);
        srow[64 + r] = rsqrtf(var + 1e-5f);
    }
    __syncthreads();
    float rstd = srow[64 + r];
#pragma unroll
    for (int f = 0; f < 34; f++) {
        int fg = f0 + f;
        if (fg < FDIM)
            g_fe[(size_t)(base + r) * FDIM + fg] = (tv[f] - mu) * rstd * gw[fg] + bw[fg];
    }
}

// ---------------- elementwise / gather kernels --------------------------------------
__global__ void relu_copy_k(const float* __restrict__ in, float* __restrict__ out, int n) {
    int i = blockIdx.x * blockDim.x + threadIdx.x;
    if (i < n) out[i] = fmaxf(in[i], 0.f);
}

__global__ void gather_sum_k(const int* __restrict__ a2b) {
    __shared__ int idx[MAXNB];
    int a = blockIdx.x, t = threadIdx.x;
    if (t < MAXNB) idx[t] = a2b[a * MAXNB + t];
    __syncthreads();
    float s = 0.f;
#pragma unroll
    for (int j = 0; j < MAXNB; j++) s += g_msg[(size_t)idx[j] * HD + t];
    g_amsg[(size_t)a * HD + t] = s;
}

__global__ void dmpnn_pre_k(const int* __restrict__ b2a, const int* __restrict__ b2revb) {
    int b = blockIdx.x, t = threadIdx.x;
    int ia = __ldg(&b2a[b]), ir = __ldg(&b2revb[b]);
    g_tmp[(size_t)b * HD + t] = g_amsg[(size_t)ia * HD + t] - g_msg[(size_t)ir * HD + t];
}

__global__ void combine_k(const float* __restrict__ wal, const float* __restrict__ walb) {
    __shared__ float red[256];
    __shared__ float salpha;
    int b = blockIdx.x, t = threadIdx.x;
    size_t o = (size_t)b * HD + t;
    float d = g_dmpnn[o], am = g_attm[o];
    red[t] = d * wal[t] + am * wal[256 + t];
    __syncthreads();
    for (int s = 128; s > 0; s >>= 1) {
        if (t < s) red[t] += red[t + s];
        __syncthreads();
    }
    if (t == 0) salpha = 1.f / (1.f + __expf(-(red[0] + walb[0])));
    __syncthreads();
    float al = salpha;
    g_msg[o] = fmaxf(g_inputs[o] + al * d + (1.f - al) * am, 0.f);
}

__global__ void concat_k() {
    int i = blockIdx.x * blockDim.x + threadIdx.x;
    if (i >= NA * (FDIM + HD)) return;
    int row = i / (FDIM + HD), c = i - row * (FDIM + HD);
    g_tmp[i] = (c < FDIM) ? g_fe[(size_t)row * FDIM + c]
                          : g_amsg[(size_t)row * HD + (c - FDIM)];
}

// ---------------- per-molecule attentive pooling -------------------------------------
#define MP_SMEM_FLOATS (2 * 64 * 260 + 4096)
__global__ __launch_bounds__(256, 1) void mol_pool_k(const float* __restrict__ Wb,
                                                     const float* __restrict__ bb,
                                                     float* __restrict__ outg) {
    extern __shared__ float sm[];
    float* shm = sm;                 // [64][260]  (atom_h)
    float* sw = shm + 64 * 260;      // [64][260]  (hm@Wa, later t=aw@hm)
    float* ssc = sw + 64 * 260;      // [64][64]
    const int tid = threadIdx.x;
    const int base = blockIdx.x * 64;
    for (int idx = tid; idx < 64 * HD; idx += 256) {
        int a = idx >> 8, c = idx & 255;
        shm[a * 260 + c] = g_atomh[(size_t)(base + a) * HD + c];
        sw[a * 260 + c] = g_hmwa[(size_t)(base + a) * HD + c];
    }
    __syncthreads();
    {
        int ty = tid >> 4, tx = tid & 15;
        float acc[4][4] = {};
        for (int h = 0; h < HD; h++) {
            float qv[4], kv[4];
#pragma unroll
            for (int i = 0; i < 4; i++) {
                qv[i] = sw[(ty * 4 + i) * 260 + h];
                kv[i] = shm[(tx * 4 + i) * 260 + h];
            }
#pragma unroll
            for (int i = 0; i < 4; i++)
#pragma unroll
                for (int j = 0; j < 4; j++) acc[i][j] += qv[i] * kv[j];
        }
#pragma unroll
        for (int i = 0; i < 4; i++)
#pragma unroll
            for (int j = 0; j < 4; j++)
                ssc[(ty * 4 + i) * 64 + tx * 4 + j] = acc[i][j];
    }
    __syncthreads();
    if (tid < 64) {
        float mx = -1e30f;
        for (int j = 0; j < 64; j++) mx = fmaxf(mx, ssc[tid * 64 + j]);
        float s = 0.f;
        for (int j = 0; j < 64; j++) {
            float e = __expf(ssc[tid * 64 + j] - mx);
            ssc[tid * 64 + j] = e; s += e;
        }
        float inv = 1.f / s;
        for (int j = 0; j < 64; j++) ssc[tid * 64 + j] *= inv;
    }
    __syncthreads();
    const int c = tid;
    float acc[64];
#pragma unroll
    for (int a = 0; a < 64; a++) acc[a] = 0.f;
    for (int b = 0; b < 64; b++) {
        float hv = shm[b * 260 + c];
#pragma unroll 16
        for (int a = 0; a < 64; a++) acc[a] += ssc[a * 64 + b] * hv;
    }
    __syncthreads();
    for (int a = 0; a < 64; a++) sw[a * 260 + c] = acc[a];
    __syncthreads();
#pragma unroll
    for (int a = 0; a < 64; a++) acc[a] = 0.f;
    for (int k = 0; k < HD; k++) {
        float wv = Wb[(size_t)k * HD + c];
#pragma unroll 16
        for (int a = 0; a < 64; a++) acc[a] += sw[a * 260 + k] * wv;
    }
    float bv = bb[c];
    float s = 0.f;
    for (int a = 0; a < 64; a++) {
        float t = fmaxf(acc[a] + bv, 0.f);
        s += shm[a * 260 + c] + t;
    }
    outg[(size_t)blockIdx.x * HD + c] = s * (1.f / 64.f);
}

// ---------------- host driver --------------------------------------------------------
static float* symf(const void* s) {
    void* p = nullptr;
    cudaGetSymbolAddress(&p, s);
    return (float*)p;
}

extern "C" void kernel_launch(void* const* d_in, const int* in_sizes, int n_in,
                              void* d_out, int out_size) {
    const float* f_atoms = (const float*)d_in[0];
    const float* f_bonds = (const float*)d_in[1];
    const float* Wq_atom = (const float*)d_in[2];
    const float* Wk_atom = (const float*)d_in[3];
    const float* Wv_atom = (const float*)d_in[4];
    const float* ln_g = (const float*)d_in[5];
    const float* ln_b = (const float*)d_in[6];
    const float* Wi = (const float*)d_in[7];
    const float* Wh = (const float*)d_in[8];
    const float* Wq = (const float*)d_in[9];
    const float* Wk = (const float*)d_in[10];
    const float* Wv = (const float*)d_in[11];
    const float* Wa = (const float*)d_in[12];
    const float* Walw = (const float*)d_in[13];
    const float* Walb = (const float*)d_in[14];
    const float* Wow = (const float*)d_in[15];
    const float* Wob = (const float*)d_in[16];
    const float* Wbw = (const float*)d_in[17];
    const float* Wbb = (const float*)d_in[18];
    const int* a2b = (const int*)d_in[19];
    const int* b2a = (const int*)d_in[20];
    const int* b2revb = (const int*)d_in[21];
    float* out = (float*)d_out;

    float* p_qa = symf(g_qa);
    float* p_ka = symf(g_ka);
    float* p_va = symf(g_va);
    float* p_inputs = symf(g_inputs);
    float* p_msg = symf(g_msg);
    float* p_tmp = symf(g_tmp);
    float* p_dmpnn = symf(g_dmpnn);
    float* p_Q = symf(g_Q);
    float* p_K = symf(g_K);
    float* p_V = symf(g_V);
    float* p_attV = symf(g_attV);
    float* p_attm = symf(g_attm);
    float* p_atomh = symf(g_atomh);
    float* p_hmwa = symf(g_hmwa);

    const int FL_SMEM = FL_SMEM_FLOATS * 4;
    const int AT_SMEM = AT_SMEM_FLOATS * 4;
    const int MP_SMEM = MP_SMEM_FLOATS * 4;
    cudaFuncSetAttribute(flash_k, cudaFuncAttributeMaxDynamicSharedMemorySize, FL_SMEM);
    cudaFuncSetAttribute(atom_attn_ln_k, cudaFuncAttributeMaxDynamicSharedMemorySize, AT_SMEM);
    cudaFuncSetAttribute(mol_pool_k, cudaFuncAttributeMaxDynamicSharedMemorySize, MP_SMEM);

    // --- atom enhancement ---
    dim3 gqa((FDIM + 63) / 64, (NA + 63) / 64);
    gemm_k<0, 0><<<gqa, 256>>>(f_atoms, Wq_atom, nullptr, p_qa, NA, FDIM, FDIM);
    gemm_k<0, 0><<<gqa, 256>>>(f_atoms, Wk_atom, nullptr, p_ka, NA, FDIM, FDIM);
    gemm_k<0, 0><<<gqa, 256>>>(f_atoms, Wv_atom, nullptr, p_va, NA, FDIM, FDIM);
    atom_attn_ln_k<<<NMOL, 256, AT_SMEM>>>(f_atoms, ln_g, ln_b);

    // --- bond message init ---
    dim3 gb(HD / 64, NB / 64);
    gemm_k<0, 0><<<gb, 256>>>(f_bonds, Wi, nullptr, p_inputs, NB, HD, BFDIM);
    relu_copy_k<<<(NB * HD + 255) / 256, 256>>>(p_inputs, p_msg, NB * HD);

    // --- depth loop (DEPTH-1 = 3 iterations) ---
    for (int it = 0; it < 3; it++) {
        gather_sum_k<<<NA, 256>>>(a2b);
        dmpnn_pre_k<<<NB, 256>>>(b2a, b2revb);
        gemm_k<0, 0><<<gb, 256>>>(p_tmp, Wh, nullptr, p_dmpnn, NB, HD, HD);
        gemm_k<0, 0><<<gb, 256>>>(p_msg, Wq, nullptr, p_Q, NB, HD, HD);
        gemm_k<0, 0><<<gb, 256>>>(p_msg, Wk, nullptr, p_K, NB, HD, HD);
        gemm_k<0, 0><<<gb, 256>>>(p_msg, Wv, nullptr, p_V, NB, HD, HD);
        flash_k<<<NB / 64, 256, FL_SMEM>>>();
        gemm_k<0, 0><<<gb, 256>>>(p_attV, Wa, nullptr, p_attm, NB, HD, HD);
        combine_k<<<NB, 256>>>(Walw, Walb);
    }

    // --- readout ---
    gather_sum_k<<<NA, 256>>>(a2b);
    concat_k<<<(NA * (FDIM + HD) + 255) / 256, 256>>>();
    dim3 ga(HD / 64, NA / 64);
    gemm_k<1, 1><<<ga, 256>>>(p_tmp, Wow, Wob, p_atomh, NA, HD, FDIM + HD);

    // --- pooling ---
    gemm_k<0, 0><<<ga, 256>>>(p_atomh, Wa, nullptr, p_hmwa, NA, HD, HD);
    mol_pool_k<<<NMOL, 256, MP_SMEM>>>(Wbw, Wbb, out);
}

// round 4
// speedup vs baseline: 9.2632x; 9.2632x over previous
#include <cuda_runtime.h>
#include <cuda_bf16.h>
#include <math.h>
#include <stdint.h>

#define NA 4096
#define NB 8192
#define FDIM 133
#define BFDIM 147
#define HD 256
#define NMOL 64
#define MAXNB 6

__device__ __align__(16) float g_qa[NA*FDIM];
__device__ __align__(16) float g_ka[NA*FDIM];
__device__ __align__(16) float g_va[NA*FDIM];
__device__ __align__(16) float g_fe[NA*FDIM];
__device__ __align__(16) float g_inputs[NB*HD];
__device__ __align__(16) float g_msg[NB*HD];
__device__ __align__(16) float g_amsg[NA*HD];
__device__ __align__(16) float g_tmp[NB*HD];
__device__ __align__(16) float g_dmpnn[NB*HD];
__device__ __align__(16) float g_Q[NB*HD];
__device__ __align__(16) float g_K[NB*HD];
__device__ __align__(16) float g_V[NB*HD];
__device__ __align__(16) float g_attV[NB*HD];
__device__ __align__(16) float g_attm[NB*HD];
__device__ __align__(16) float g_atomh[NA*HD];
__device__ __align__(16) float g_hmwa[NA*HD];
__device__ __align__(16) __nv_bfloat16 g_Qhi[NB*HD];
__device__ __align__(16) __nv_bfloat16 g_Qlo[NB*HD];
__device__ __align__(16) __nv_bfloat16 g_Khi[NB*HD];
__device__ __align__(16) __nv_bfloat16 g_Klo[NB*HD];
__device__ __align__(16) __nv_bfloat16 g_Vthi[HD*NB];
__device__ __align__(16) __nv_bfloat16 g_Vtlo[HD*NB];
__device__ __align__(16) float g_Opart[2*NB*HD];   // unnormalized O, per key-half
__device__ __align__(16) float g_lpart[2*NB];      // softmax denominators per key-half

// ---- mma.sync bf16 m16n8k16 (plain sm_103-compatible HMMA path) ----
__device__ __forceinline__ void mma_bf16(float* c, uint32_t a0, uint32_t a1, uint32_t a2,
                                         uint32_t a3, uint32_t b0, uint32_t b1) {
    asm volatile(
        "mma.sync.aligned.m16n8k16.row.col.f32.bf16.bf16.f32 "
        "{%0,%1,%2,%3}, {%4,%5,%6,%7}, {%8,%9}, {%0,%1,%2,%3};\n"
        : "+f"(c[0]), "+f"(c[1]), "+f"(c[2]), "+f"(c[3])
        : "r"(a0), "r"(a1), "r"(a2), "r"(a3), "r"(b0), "r"(b1));
}
__device__ __forceinline__ uint32_t packbf(float x, float y) {
    __nv_bfloat16 h0 = __float2bfloat16(x), h1 = __float2bfloat16(y);
    return ((uint32_t)__bfloat16_as_ushort(h1) << 16) | (uint32_t)__bfloat16_as_ushort(h0);
}

// ---------------- fp32 GEMM ----------------
template <int RELU, int HASBIAS>
__global__ __launch_bounds__(256) void gemm_k(const float* __restrict__ A, const float* __restrict__ B,
                                              const float* __restrict__ bias, float* __restrict__ C,
                                              int Mm, int Nn, int Kk){
    __shared__ float As[16*68];
    __shared__ float Bs[16*68];
    const int tid=threadIdx.x, tm=tid>>4, tn=tid&15;
    const int m0=blockIdx.y*64, n0=blockIdx.x*64;
    float acc[4][4]={};
    for(int k0=0;k0<Kk;k0+=16){
#pragma unroll
        for(int i=0;i<4;i++){int idx=tid+i*256,row=idx>>4,col=idx&15;float v=0.f;
            if(m0+row<Mm&&k0+col<Kk)v=A[(size_t)(m0+row)*Kk+k0+col];As[col*68+row]=v;}
#pragma unroll
        for(int i=0;i<4;i++){int idx=tid+i*256,row=idx>>6,col=idx&63;float v=0.f;
            if(k0+row<Kk&&n0+col<Nn)v=B[(size_t)(k0+row)*Nn+n0+col];Bs[row*68+col]=v;}
        __syncthreads();
#pragma unroll
        for(int kk=0;kk<16;kk++){
            float4 a4=*(const float4*)&As[kk*68+tm*4];
            float4 b4=*(const float4*)&Bs[kk*68+tn*4];
            float av[4]={a4.x,a4.y,a4.z,a4.w},bv[4]={b4.x,b4.y,b4.z,b4.w};
#pragma unroll
            for(int i=0;i<4;i++)
#pragma unroll
                for(int j=0;j<4;j++)acc[i][j]+=av[i]*bv[j];
        }
        __syncthreads();
    }
#pragma unroll
    for(int i=0;i<4;i++){int m=m0+tm*4+i;if(m>=Mm)continue;
#pragma unroll
        for(int j=0;j<4;j++){int n=n0+tn*4+j;if(n>=Nn)continue;
            float v=acc[i][j];if(HASBIAS)v+=bias[n];if(RELU)v=fmaxf(v,0.f);
            C[(size_t)m*Nn+n]=v;}}
}

// ---------------- split / transpose ----------------
__global__ void split_qk_k(const float* __restrict__ src, __nv_bfloat16* __restrict__ hi,
                           __nv_bfloat16* __restrict__ lo, float scale){
    int i=blockIdx.x*blockDim.x+threadIdx.x;
    float x=src[i]*scale;
    __nv_bfloat16 h=__float2bfloat16(x);
    hi[i]=h; lo[i]=__float2bfloat16(x-__bfloat162float(h));
}
__global__ void vt_split_k(const float* __restrict__ V){
    __shared__ float t[32][33];
    int bx=blockIdx.x, by=blockIdx.y, tx=threadIdx.x, ty=threadIdx.y;
    for(int i=ty;i<32;i+=8) t[i][tx]=V[(size_t)(bx*32+i)*HD+by*32+tx];
    __syncthreads();
    for(int i=ty;i<32;i+=8){
        float x=t[tx][i];
        __nv_bfloat16 h=__float2bfloat16(x);
        size_t o=(size_t)(by*32+i)*NB+bx*32+tx;
        g_Vthi[o]=h; g_Vtlo[o]=__float2bfloat16(x-__bfloat162float(h));
    }
}

// ---------------- mma.sync flash attention -------------------------------------------
// BM=128 rows/CTA (8 warps x 16), BN=32 keys/tile, keys split over blockIdx.y halves.
// S = (Q/16)K^T in bf16 hi/lo (3 combos), softmax shifted by exact self-logit,
// O += P V with P hi/lo (3 combos). O unnormalized + l written per half; merged after.
#define FL_BF 104960
#define SQH 0
#define SQL 33792
#define SKH 67584
#define SKL 76032
#define SVH 84480
#define SVL 94720
__global__ __launch_bounds__(256, 1) void flash_mma(){
    extern __shared__ __nv_bfloat16 sm[];
    const int tid = threadIdx.x, wid = tid >> 5, lane = tid & 31;
    const int r = lane >> 2, cq = (lane & 3) * 2;
    const int row0 = blockIdx.x * 128;
    const int half = blockIdx.y;
    const int kb0 = half * (NB / 2);

    // exact self-logit per row (fp32): cs0 for row r, cs1 for row r+8
    float cs0 = 0.f, cs1 = 0.f;
    {
        int rg = row0 + wid * 16 + r;
        const float* q0 = &g_Q[(size_t)rg * HD];
        const float* k0 = &g_K[(size_t)rg * HD];
        const float* q1 = &g_Q[(size_t)(rg + 8) * HD];
        const float* k1 = &g_K[(size_t)(rg + 8) * HD];
        int f0 = (lane & 3) * 64;
#pragma unroll 16
        for (int f = 0; f < 64; f++) {
            cs0 += q0[f0 + f] * k0[f0 + f];
            cs1 += q1[f0 + f] * k1[f0 + f];
        }
        cs0 += __shfl_xor_sync(0xffffffffu, cs0, 1);
        cs0 += __shfl_xor_sync(0xffffffffu, cs0, 2);
        cs1 += __shfl_xor_sync(0xffffffffu, cs1, 1);
        cs1 += __shfl_xor_sync(0xffffffffu, cs1, 2);
        cs0 *= 0.0625f; cs1 *= 0.0625f;
    }

    // load Q hi/lo into smem [128][264]
#pragma unroll
    for (int i = 0; i < 16; i++) {
        int idx = tid + i * 256, row = idx >> 5, c8 = (idx & 31) * 8;
        *(uint4*)(sm + SQH + row * 264 + c8) = *(const uint4*)(g_Qhi + (size_t)(row0 + row) * HD + c8);
        *(uint4*)(sm + SQL + row * 264 + c8) = *(const uint4*)(g_Qlo + (size_t)(row0 + row) * HD + c8);
    }

    float Oc[32][4];
#pragma unroll
    for (int t = 0; t < 32; t++) { Oc[t][0]=0.f; Oc[t][1]=0.f; Oc[t][2]=0.f; Oc[t][3]=0.f; }
    float l0 = 0.f, l1 = 0.f;

    for (int kt = 0; kt < 128; kt++) {
        const int kb = kb0 + kt * 32;
        __syncthreads();
#pragma unroll
        for (int i = 0; i < 4; i++) {
            int idx = tid + i * 256, row = idx >> 5, c8 = (idx & 31) * 8;
            *(uint4*)(sm + SKH + row * 264 + c8) = *(const uint4*)(g_Khi + (size_t)(kb + row) * HD + c8);
            *(uint4*)(sm + SKL + row * 264 + c8) = *(const uint4*)(g_Klo + (size_t)(kb + row) * HD + c8);
        }
#pragma unroll
        for (int i = 0; i < 4; i++) {
            int idx = tid + i * 256, n = idx >> 2, k8 = (idx & 3) * 8;
            *(uint4*)(sm + SVH + n * 40 + k8) = *(const uint4*)(g_Vthi + (size_t)n * NB + kb + k8);
            *(uint4*)(sm + SVL + n * 40 + k8) = *(const uint4*)(g_Vtlo + (size_t)n * NB + kb + k8);
        }
        __syncthreads();

        // ---- S = Q K^T (3 combos) ----
        float Sc[4][4];
#pragma unroll
        for (int t = 0; t < 4; t++) { Sc[t][0]=0.f; Sc[t][1]=0.f; Sc[t][2]=0.f; Sc[t][3]=0.f; }
        const __nv_bfloat16* qh = sm + SQH + (wid * 16 + r) * 264 + cq;
        const __nv_bfloat16* ql = sm + SQL + (wid * 16 + r) * 264 + cq;
#pragma unroll
        for (int ks = 0; ks < 16; ks++) {
            uint32_t aH0 = *(const uint32_t*)(qh + ks * 16);
            uint32_t aH1 = *(const uint32_t*)(qh + 8 * 264 + ks * 16);
            uint32_t aH2 = *(const uint32_t*)(qh + ks * 16 + 8);
            uint32_t aH3 = *(const uint32_t*)(qh + 8 * 264 + ks * 16 + 8);
            uint32_t aL0 = *(const uint32_t*)(ql + ks * 16);
            uint32_t aL1 = *(const uint32_t*)(ql + 8 * 264 + ks * 16);
            uint32_t aL2 = *(const uint32_t*)(ql + ks * 16 + 8);
            uint32_t aL3 = *(const uint32_t*)(ql + 8 * 264 + ks * 16 + 8);
#pragma unroll
            for (int t = 0; t < 4; t++) {
                const __nv_bfloat16* kh = sm + SKH + (t * 8 + r) * 264 + ks * 16 + cq;
                const __nv_bfloat16* kl = sm + SKL + (t * 8 + r) * 264 + ks * 16 + cq;
                uint32_t bH0 = *(const uint32_t*)kh, bH1 = *(const uint32_t*)(kh + 8);
                uint32_t bL0 = *(const uint32_t*)kl, bL1 = *(const uint32_t*)(kl + 8);
                mma_bf16(Sc[t], aH0, aH1, aH2, aH3, bH0, bH1);
                mma_bf16(Sc[t], aH0, aH1, aH2, aH3, bL0, bL1);
                mma_bf16(Sc[t], aL0, aL1, aL2, aL3, bH0, bH1);
            }
        }
        // ---- softmax: exp(S - cself), accumulate l, build P fragments ----
        uint32_t pH[2][4], pL[2][4];
        float rs0 = 0.f, rs1 = 0.f;
#pragma unroll
        for (int t = 0; t < 4; t++) {
            float e0 = __expf(Sc[t][0] - cs0);
            float e1 = __expf(Sc[t][1] - cs0);
            float e2 = __expf(Sc[t][2] - cs1);
            float e3 = __expf(Sc[t][3] - cs1);
            rs0 += e0 + e1; rs1 += e2 + e3;
            __nv_bfloat16 h0=__float2bfloat16(e0), h1=__float2bfloat16(e1);
            __nv_bfloat16 h2=__float2bfloat16(e2), h3=__float2bfloat16(e3);
            float q0=e0-__bfloat162float(h0), q1=e1-__bfloat162float(h1);
            float q2=e2-__bfloat162float(h2), q3=e3-__bfloat162float(h3);
            int ksp = t >> 1, hi2 = (t & 1) * 2;
            pH[ksp][hi2]     = ((uint32_t)__bfloat16_as_ushort(h1) << 16) | (uint32_t)__bfloat16_as_ushort(h0);
            pH[ksp][hi2 + 1] = ((uint32_t)__bfloat16_as_ushort(h3) << 16) | (uint32_t)__bfloat16_as_ushort(h2);
            pL[ksp][hi2]     = packbf(q0, q1);
            pL[ksp][hi2 + 1] = packbf(q2, q3);
        }
        rs0 += __shfl_xor_sync(0xffffffffu, rs0, 1);
        rs0 += __shfl_xor_sync(0xffffffffu, rs0, 2);
        rs1 += __shfl_xor_sync(0xffffffffu, rs1, 1);
        rs1 += __shfl_xor_sync(0xffffffffu, rs1, 2);
        l0 += rs0; l1 += rs1;

        // ---- O += P V (3 combos) ----
#pragma unroll
        for (int ks2 = 0; ks2 < 2; ks2++) {
#pragma unroll
            for (int t = 0; t < 32; t++) {
                const __nv_bfloat16* vh = sm + SVH + (t * 8 + r) * 40 + ks2 * 16 + cq;
                const __nv_bfloat16* vl = sm + SVL + (t * 8 + r) * 40 + ks2 * 16 + cq;
                uint32_t bH0 = *(const uint32_t*)vh, bH1 = *(const uint32_t*)(vh + 8);
                uint32_t bL0 = *(const uint32_t*)vl, bL1 = *(const uint32_t*)(vl + 8);
                mma_bf16(Oc[t], pH[ks2][0], pH[ks2][1], pH[ks2][2], pH[ks2][3], bH0, bH1);
                mma_bf16(Oc[t], pH[ks2][0], pH[ks2][1], pH[ks2][2], pH[ks2][3], bL0, bL1);
                mma_bf16(Oc[t], pL[ks2][0], pL[ks2][1], pL[ks2][2], pL[ks2][3], bH0, bH1);
            }
        }
    }

    // write unnormalized partial O + l
    {
        int rg = row0 + wid * 16 + r;
        float* O = g_Opart + (size_t)half * NB * HD;
#pragma unroll
        for (int t = 0; t < 32; t++) {
            int col = t * 8 + cq;
            O[(size_t)rg * HD + col]       = Oc[t][0];
            O[(size_t)rg * HD + col + 1]   = Oc[t][1];
            O[(size_t)(rg + 8) * HD + col]     = Oc[t][2];
            O[(size_t)(rg + 8) * HD + col + 1] = Oc[t][3];
        }
        if ((lane & 3) == 0) {
            g_lpart[half * NB + rg] = l0;
            g_lpart[half * NB + rg + 8] = l1;
        }
    }
}

__global__ void flash_merge_k(){
    int row = blockIdx.x, c = threadIdx.x;
    float li = 1.f / (g_lpart[row] + g_lpart[NB + row]);
    size_t o = (size_t)row * HD + c;
    g_attV[o] = (g_Opart[o] + g_Opart[(size_t)NB * HD + o]) * li;
}

// ---------------- atom self-attn + LN ----------------
#define AT_SMEM_FLOATS (4*64*136+64*64+512+128)
__global__ __launch_bounds__(256,1) void atom_attn_ln_k(const float* __restrict__ xg,
                                                        const float* __restrict__ gw,
                                                        const float* __restrict__ bw){
    extern __shared__ float smf[];
    float* sx=smf; float* sq=sx+64*136; float* sk=sq+64*136; float* sv=sk+64*136;
    float* ss=sv+64*136; float* sred=ss+4096; float* srow=sred+512;
    const int tid=threadIdx.x; const int base=blockIdx.x*64;
    for(int idx=tid;idx<64*FDIM;idx+=256){
        int a=idx/FDIM,f=idx-a*FDIM; size_t go=(size_t)(base+a)*FDIM+f;
        sx[a*136+f]=xg[go]; sq[a*136+f]=g_qa[go]; sk[a*136+f]=g_ka[go]; sv[a*136+f]=g_va[go];
    }
    __syncthreads();
    {
        int ty=tid>>4,tx=tid&15; float acc[4][4]={};
        for(int h=0;h<FDIM;h++){
            float qv[4],kv[4];
#pragma unroll
            for(int i=0;i<4;i++){qv[i]=sq[(ty*4+i)*136+h];kv[i]=sk[(tx*4+i)*136+h];}
#pragma unroll
            for(int i=0;i<4;i++)
#pragma unroll
                for(int j=0;j<4;j++)acc[i][j]+=qv[i]*kv[j];
        }
        float scl=rsqrtf(133.0f);
#pragma unroll
        for(int i=0;i<4;i++)
#pragma unroll
            for(int j=0;j<4;j++)ss[(ty*4+i)*64+tx*4+j]=acc[i][j]*scl;
    }
    __syncthreads();
    if(tid<64){
        float mx=-1e30f;
        for(int j=0;j<64;j++)mx=fmaxf(mx,ss[tid*64+j]);
        float s=0.f;
        for(int j=0;j<64;j++){float e=__expf(ss[tid*64+j]-mx);ss[tid*64+j]=e;s+=e;}
        float inv=1.f/s;
        for(int j=0;j<64;j++)ss[tid*64+j]*=inv;
    }
    __syncthreads();
    const int r=tid>>2,qd=tid&3,f0=qd*34;
    float tv[34];
#pragma unroll
    for(int f=0;f<34;f++)tv[f]=0.f;
    for(int b=0;b<64;b++){
        float p=ss[r*64+b]; const float* vb=&sv[b*136+f0];
#pragma unroll
        for(int f=0;f<34;f++)if(f0+f<FDIM)tv[f]+=p*vb[f];
    }
    float s1=0.f;
#pragma unroll
    for(int f=0;f<34;f++)if(f0+f<FDIM){tv[f]+=sx[r*136+f0+f];s1+=tv[f];}
    sred[tid]=s1; __syncthreads();
    if(qd==0)srow[r]=(sred[tid]+sred[tid+1]+sred[tid+2]+sred[tid+3])*(1.f/133.f);
    __syncthreads();
    float mu=srow[r],s2=0.f;
#pragma unroll
    for(int f=0;f<34;f++)if(f0+f<FDIM){float d=tv[f]-mu;s2+=d*d;}
    sred[tid]=s2; __syncthreads();
    if(qd==0){float var=(sred[tid]+sred[tid+1]+sred[tid+2]+sred[tid+3])*(1.f/133.f);srow[64+r]=rsqrtf(var+1e-5f);}
    __syncthreads();
    float rstd=srow[64+r];
#pragma unroll
    for(int f=0;f<34;f++){int fg=f0+f;
        if(fg<FDIM)g_fe[(size_t)(base+r)*FDIM+fg]=(tv[f]-mu)*rstd*gw[fg]+bw[fg];}
}

// ---------------- elementwise / gather ----------------
__global__ void relu_copy_k(const float* __restrict__ in, float* __restrict__ out, int n){
    int i=blockIdx.x*blockDim.x+threadIdx.x; if(i<n)out[i]=fmaxf(in[i],0.f);
}
__global__ void gather_sum_k(const int* __restrict__ a2b){
    __shared__ int idx[MAXNB];
    int a=blockIdx.x,t=threadIdx.x;
    if(t<MAXNB)idx[t]=a2b[a*MAXNB+t];
    __syncthreads();
    float s=0.f;
#pragma unroll
    for(int j=0;j<MAXNB;j++)s+=g_msg[(size_t)idx[j]*HD+t];
    g_amsg[(size_t)a*HD+t]=s;
}
__global__ void dmpnn_pre_k(const int* __restrict__ b2a, const int* __restrict__ b2revb){
    int b=blockIdx.x,t=threadIdx.x;
    int ia=__ldg(&b2a[b]),ir=__ldg(&b2revb[b]);
    g_tmp[(size_t)b*HD+t]=g_amsg[(size_t)ia*HD+t]-g_msg[(size_t)ir*HD+t];
}
__global__ void combine_k(const float* __restrict__ wal, const float* __restrict__ walb){
    __shared__ float red[256];
    __shared__ float salpha;
    int b=blockIdx.x,t=threadIdx.x;
    size_t o=(size_t)b*HD+t;
    float d=g_dmpnn[o],am=g_attm[o];
    red[t]=d*wal[t]+am*wal[256+t];
    __syncthreads();
    for(int s=128;s>0;s>>=1){if(t<s)red[t]+=red[t+s];__syncthreads();}
    if(t==0)salpha=1.f/(1.f+__expf(-(red[0]+walb[0])));
    __syncthreads();
    float al=salpha;
    g_msg[o]=fmaxf(g_inputs[o]+al*d+(1.f-al)*am,0.f);
}
__global__ void concat_k(){
    int i=blockIdx.x*blockDim.x+threadIdx.x;
    if(i>=NA*(FDIM+HD))return;
    int row=i/(FDIM+HD),c=i-row*(FDIM+HD);
    g_tmp[i]=(c<FDIM)?g_fe[(size_t)row*FDIM+c]:g_amsg[(size_t)row*HD+(c-FDIM)];
}

// ---------------- molecule pooling ----------------
#define MP_SMEM_FLOATS (2*64*260+4096)
__global__ __launch_bounds__(256,1) void mol_pool_k(const float* __restrict__ Wb,
                                                    const float* __restrict__ bb,
                                                    float* __restrict__ outg){
    extern __shared__ float smf[];
    float* shm=smf; float* sw=shm+64*260; float* ssc=sw+64*260;
    const int tid=threadIdx.x; const int base=blockIdx.x*64;
    for(int idx=tid;idx<64*HD;idx+=256){
        int a=idx>>8,c=idx&255;
        shm[a*260+c]=g_atomh[(size_t)(base+a)*HD+c];
        sw[a*260+c]=g_hmwa[(size_t)(base+a)*HD+c];
    }
    __syncthreads();
    {
        int ty=tid>>4,tx=tid&15; float acc[4][4]={};
        for(int h=0;h<HD;h++){
            float qv[4],kv[4];
#pragma unroll
            for(int i=0;i<4;i++){qv[i]=sw[(ty*4+i)*260+h];kv[i]=shm[(tx*4+i)*260+h];}
#pragma unroll
            for(int i=0;i<4;i++)
#pragma unroll
                for(int j=0;j<4;j++)acc[i][j]+=qv[i]*kv[j];
        }
#pragma unroll
        for(int i=0;i<4;i++)
#pragma unroll
            for(int j=0;j<4;j++)ssc[(ty*4+i)*64+tx*4+j]=acc[i][j];
    }
    __syncthreads();
    if(tid<64){
        float mx=-1e30f;
        for(int j=0;j<64;j++)mx=fmaxf(mx,ssc[tid*64+j]);
        float s=0.f;
        for(int j=0;j<64;j++){float e=__expf(ssc[tid*64+j]-mx);ssc[tid*64+j]=e;s+=e;}
        float inv=1.f/s;
        for(int j=0;j<64;j++)ssc[tid*64+j]*=inv;
    }
    __syncthreads();
    const int c=tid;
    float acc[64];
#pragma unroll
    for(int a=0;a<64;a++)acc[a]=0.f;
    for(int b=0;b<64;b++){
        float hv=shm[b*260+c];
#pragma unroll 16
        for(int a=0;a<64;a++)acc[a]+=ssc[a*64+b]*hv;
    }
    __syncthreads();
    for(int a=0;a<64;a++)sw[a*260+c]=acc[a];
    __syncthreads();
#pragma unroll
    for(int a=0;a<64;a++)acc[a]=0.f;
    for(int k=0;k<HD;k++){
        float wv=Wb[(size_t)k*HD+c];
#pragma unroll 16
        for(int a=0;a<64;a++)acc[a]+=sw[a*260+k]*wv;
    }
    float bv=bb[c],s=0.f;
    for(int a=0;a<64;a++){
        float t=fmaxf(acc[a]+bv,0.f);
        s+=shm[a*260+c]+t;
    }
    outg[(size_t)blockIdx.x*HD+c]=s*(1.f/64.f);
}

// ---------------- host driver ----------------
static float* symf(const void* s){ void* p=nullptr; cudaGetSymbolAddress(&p,s); return (float*)p; }
static __nv_bfloat16* symb(const void* s){ void* p=nullptr; cudaGetSymbolAddress(&p,s); return (__nv_bfloat16*)p; }

extern "C" void kernel_launch(void* const* d_in, const int* in_sizes, int n_in,
                              void* d_out, int out_size){
    const float* f_atoms=(const float*)d_in[0];
    const float* f_bonds=(const float*)d_in[1];
    const float* Wq_atom=(const float*)d_in[2];
    const float* Wk_atom=(const float*)d_in[3];
    const float* Wv_atom=(const float*)d_in[4];
    const float* ln_g=(const float*)d_in[5];
    const float* ln_b=(const float*)d_in[6];
    const float* Wi=(const float*)d_in[7];
    const float* Wh=(const float*)d_in[8];
    const float* Wq=(const float*)d_in[9];
    const float* Wk=(const float*)d_in[10];
    const float* Wv=(const float*)d_in[11];
    const float* Wa=(const float*)d_in[12];
    const float* Walw=(const float*)d_in[13];
    const float* Walb=(const float*)d_in[14];
    const float* Wow=(const float*)d_in[15];
    const float* Wob=(const float*)d_in[16];
    const float* Wbw=(const float*)d_in[17];
    const float* Wbb=(const float*)d_in[18];
    const int* a2b=(const int*)d_in[19];
    const int* b2a=(const int*)d_in[20];
    const int* b2revb=(const int*)d_in[21];
    float* out=(float*)d_out;

    float* p_qa=symf(g_qa); float* p_ka=symf(g_ka); float* p_va=symf(g_va);
    float* p_inputs=symf(g_inputs); float* p_msg=symf(g_msg); float* p_tmp=symf(g_tmp);
    float* p_dmpnn=symf(g_dmpnn); float* p_Q=symf(g_Q); float* p_K=symf(g_K);
    float* p_V=symf(g_V); float* p_attV=symf(g_attV); float* p_attm=symf(g_attm);
    float* p_atomh=symf(g_atomh); float* p_hmwa=symf(g_hmwa);
    __nv_bfloat16* p_Qhi=symb(g_Qhi); __nv_bfloat16* p_Qlo=symb(g_Qlo);
    __nv_bfloat16* p_Khi=symb(g_Khi); __nv_bfloat16* p_Klo=symb(g_Klo);

    const int AT_SMEM=AT_SMEM_FLOATS*4, MP_SMEM=MP_SMEM_FLOATS*4;
    const int FL_SMEM=FL_BF*2;
    cudaFuncSetAttribute(flash_mma,cudaFuncAttributeMaxDynamicSharedMemorySize,FL_SMEM);
    cudaFuncSetAttribute(atom_attn_ln_k,cudaFuncAttributeMaxDynamicSharedMemorySize,AT_SMEM);
    cudaFuncSetAttribute(mol_pool_k,cudaFuncAttributeMaxDynamicSharedMemorySize,MP_SMEM);

    dim3 gqa((FDIM+63)/64,(NA+63)/64);
    gemm_k<0,0><<<gqa,256>>>(f_atoms,Wq_atom,nullptr,p_qa,NA,FDIM,FDIM);
    gemm_k<0,0><<<gqa,256>>>(f_atoms,Wk_atom,nullptr,p_ka,NA,FDIM,FDIM);
    gemm_k<0,0><<<gqa,256>>>(f_atoms,Wv_atom,nullptr,p_va,NA,FDIM,FDIM);
    atom_attn_ln_k<<<NMOL,256,AT_SMEM>>>(f_atoms,ln_g,ln_b);

    dim3 gb(HD/64,NB/64);
    gemm_k<0,0><<<gb,256>>>(f_bonds,Wi,nullptr,p_inputs,NB,HD,BFDIM);
    relu_copy_k<<<(NB*HD+255)/256,256>>>(p_inputs,p_msg,NB*HD);

    dim3 vtg(NB/32,HD/32), vtb(32,8);
    for(int it=0;it<3;it++){
        gather_sum_k<<<NA,256>>>(a2b);
        dmpnn_pre_k<<<NB,256>>>(b2a,b2revb);
        gemm_k<0,0><<<gb,256>>>(p_tmp,Wh,nullptr,p_dmpnn,NB,HD,HD);
        gemm_k<0,0><<<gb,256>>>(p_msg,Wq,nullptr,p_Q,NB,HD,HD);
        gemm_k<0,0><<<gb,256>>>(p_msg,Wk,nullptr,p_K,NB,HD,HD);
        gemm_k<0,0><<<gb,256>>>(p_msg,Wv,nullptr,p_V,NB,HD,HD);
        split_qk_k<<<NB*HD/256,256>>>(p_Q,p_Qhi,p_Qlo,0.0625f);
        split_qk_k<<<NB*HD/256,256>>>(p_K,p_Khi,p_Klo,1.0f);
        vt_split_k<<<vtg,vtb>>>(p_V);
        flash_mma<<<dim3(NB/128,2),256,FL_SMEM>>>();
        flash_merge_k<<<NB,256>>>();
        gemm_k<0,0><<<gb,256>>>(p_attV,Wa,nullptr,p_attm,NB,HD,HD);
        combine_k<<<NB,256>>>(Walw,Walb);
    }

    gather_sum_k<<<NA,256>>>(a2b);
    concat_k<<<(NA*(FDIM+HD)+255)/256,256>>>();
    dim3 ga(HD/64,NA/64);
    gemm_k<1,1><<<ga,256>>>(p_tmp,Wow,Wob,p_atomh,NA,HD,FDIM+HD);
    gemm_k<0,0><<<ga,256>>>(p_atomh,Wa,nullptr,p_hmwa,NA,HD,HD);
    mol_pool_k<<<NMOL,256,MP_SMEM>>>(Wbw,Wbb,out);
}

// round 5
// speedup vs baseline: 10.8333x; 1.1695x over previous
#include <cuda_runtime.h>
#include <cuda_bf16.h>
#include <math.h>
#include <stdint.h>

#define NA 4096
#define NB 8192
#define FDIM 133
#define BFDIM 147
#define HD 256
#define NMOL 64
#define MAXNB 6
#define KP_WI 160
#define KP_WO 416

typedef __nv_bfloat16 bf16;

// ---------------- device scratch ----------------
__device__ __align__(16) float g_qa[NA*FDIM];
__device__ __align__(16) float g_ka[NA*FDIM];
__device__ __align__(16) float g_va[NA*FDIM];
__device__ __align__(16) float g_fe[NA*FDIM];
__device__ __align__(16) float g_inputs[NB*HD];
__device__ __align__(16) float g_msg[NB*HD];
__device__ __align__(16) float g_amsg[NA*HD];
__device__ __align__(16) float g_dmpnn[NB*HD];
__device__ __align__(16) float g_V[NB*HD];
__device__ __align__(16) float g_attm[NB*HD];
__device__ __align__(16) float g_atomh[NA*HD];
__device__ __align__(16) float g_hmwa[NA*HD];
__device__ __align__(16) float g_Opart[2*NB*HD];
__device__ __align__(16) float g_lpart[2*NB];

__device__ __align__(16) bf16 g_Qhi[NB*HD];
__device__ __align__(16) bf16 g_Qlo[NB*HD];
__device__ __align__(16) bf16 g_Khi[NB*HD];
__device__ __align__(16) bf16 g_Klo[NB*HD];
__device__ __align__(16) bf16 g_Vthi[HD*NB];
__device__ __align__(16) bf16 g_Vtlo[HD*NB];
__device__ __align__(16) bf16 g_msghi[NB*HD];
__device__ __align__(16) bf16 g_msglo[NB*HD];
__device__ __align__(16) bf16 g_tmphi[NB*HD];
__device__ __align__(16) bf16 g_tmplo[NB*HD];
__device__ __align__(16) bf16 g_avhi[NB*HD];
__device__ __align__(16) bf16 g_avlo[NB*HD];
__device__ __align__(16) bf16 g_fbhi[NB*KP_WI];
__device__ __align__(16) bf16 g_fblo[NB*KP_WI];
__device__ __align__(16) bf16 g_cathi[NA*KP_WO];
__device__ __align__(16) bf16 g_catlo[NA*KP_WO];
__device__ __align__(16) bf16 g_ahhi[NA*HD];
__device__ __align__(16) bf16 g_ahlo[NA*HD];
// transposed+split weights [N][KP]
__device__ __align__(16) bf16 g_Withi[HD*KP_WI];
__device__ __align__(16) bf16 g_Witlo[HD*KP_WI];
__device__ __align__(16) bf16 g_Whthi[HD*HD];
__device__ __align__(16) bf16 g_Whtlo[HD*HD];
__device__ __align__(16) bf16 g_Wqthi[HD*HD];
__device__ __align__(16) bf16 g_Wqtlo[HD*HD];
__device__ __align__(16) bf16 g_Wkthi[HD*HD];
__device__ __align__(16) bf16 g_Wktlo[HD*HD];
__device__ __align__(16) bf16 g_Wvthi[HD*HD];
__device__ __align__(16) bf16 g_Wvtlo[HD*HD];
__device__ __align__(16) bf16 g_Wathi[HD*HD];
__device__ __align__(16) bf16 g_Watlo[HD*HD];
__device__ __align__(16) bf16 g_Wothi[HD*KP_WO];
__device__ __align__(16) bf16 g_Wotlo[HD*KP_WO];

// ---------------- mma.sync helpers ----------------
__device__ __forceinline__ void mma_bf16(float* c, uint32_t a0, uint32_t a1, uint32_t a2,
                                         uint32_t a3, uint32_t b0, uint32_t b1) {
    asm volatile(
        "mma.sync.aligned.m16n8k16.row.col.f32.bf16.bf16.f32 "
        "{%0,%1,%2,%3}, {%4,%5,%6,%7}, {%8,%9}, {%0,%1,%2,%3};\n"
        : "+f"(c[0]), "+f"(c[1]), "+f"(c[2]), "+f"(c[3])
        : "r"(a0), "r"(a1), "r"(a2), "r"(a3), "r"(b0), "r"(b1));
}
__device__ __forceinline__ uint32_t packbf(float x, float y) {
    bf16 h0 = __float2bfloat16(x), h1 = __float2bfloat16(y);
    return ((uint32_t)__bfloat16_as_ushort(h1) << 16) | (uint32_t)__bfloat16_as_ushort(h0);
}
__device__ __forceinline__ void split1(float x, bf16& h, bf16& l) {
    h = __float2bfloat16(x);
    l = __float2bfloat16(x - __bfloat162float(h));
}

// ---------------- bf16 hi/lo tensor GEMM: C[M,256] = A[M,K] @ Bt[256,K]^T ------------
// A hi/lo row-major [M][K], B transposed+split [256][K]. 3-combo hi/lo mma.
template <int RELU, int HASBIAS, int SCALEQ, int OUTF32, int OUTSPLIT, int PREAUX>
__global__ __launch_bounds__(256) void tgemm(
    const bf16* __restrict__ Ah, const bf16* __restrict__ Al,
    const bf16* __restrict__ Bh, const bf16* __restrict__ Bl,
    const float* __restrict__ bias,
    float* __restrict__ Cf, bf16* __restrict__ Chi, bf16* __restrict__ Clo,
    float* __restrict__ Caux, int M, int K) {
    __shared__ bf16 sAh[128*40], sAl[128*40], sBh[64*40], sBl[64*40];
    const int tid = threadIdx.x, wid = tid >> 5, lane = tid & 31;
    const int r = lane >> 2, cq = (lane & 3) * 2;
    const int wm = wid >> 1, wn = wid & 1;
    const int m0 = blockIdx.y * 128, n0 = blockIdx.x * 64;
    float acc[2][4][4] = {};
    for (int kc = 0; kc < K; kc += 32) {
        __syncthreads();
#pragma unroll
        for (int i = 0; i < 2; i++) {
            int idx = tid + i * 256, row = idx >> 2, q8 = (idx & 3) * 8;
            *(uint4*)(sAh + row * 40 + q8) = *(const uint4*)(Ah + (size_t)(m0 + row) * K + kc + q8);
            *(uint4*)(sAl + row * 40 + q8) = *(const uint4*)(Al + (size_t)(m0 + row) * K + kc + q8);
        }
        {
            int row = tid >> 2, q8 = (tid & 3) * 8;
            *(uint4*)(sBh + row * 40 + q8) = *(const uint4*)(Bh + (size_t)(n0 + row) * K + kc + q8);
            *(uint4*)(sBl + row * 40 + q8) = *(const uint4*)(Bl + (size_t)(n0 + row) * K + kc + q8);
        }
        __syncthreads();
#pragma unroll
        for (int ks = 0; ks < 2; ks++) {
            uint32_t aH[2][4], aL[2][4];
#pragma unroll
            for (int mf = 0; mf < 2; mf++) {
                const bf16* pa = sAh + (wm * 32 + mf * 16 + r) * 40 + ks * 16 + cq;
                const bf16* pl = sAl + (wm * 32 + mf * 16 + r) * 40 + ks * 16 + cq;
                aH[mf][0] = *(const uint32_t*)pa;       aH[mf][1] = *(const uint32_t*)(pa + 8 * 40);
                aH[mf][2] = *(const uint32_t*)(pa + 8); aH[mf][3] = *(const uint32_t*)(pa + 8 * 40 + 8);
                aL[mf][0] = *(const uint32_t*)pl;       aL[mf][1] = *(const uint32_t*)(pl + 8 * 40);
                aL[mf][2] = *(const uint32_t*)(pl + 8); aL[mf][3] = *(const uint32_t*)(pl + 8 * 40 + 8);
            }
#pragma unroll
            for (int nf = 0; nf < 4; nf++) {
                const bf16* pb = sBh + (wn * 32 + nf * 8 + r) * 40 + ks * 16 + cq;
                const bf16* pq = sBl + (wn * 32 + nf * 8 + r) * 40 + ks * 16 + cq;
                uint32_t bH0 = *(const uint32_t*)pb, bH1 = *(const uint32_t*)(pb + 8);
                uint32_t bL0 = *(const uint32_t*)pq, bL1 = *(const uint32_t*)(pq + 8);
#pragma unroll
                for (int mf = 0; mf < 2; mf++) {
                    mma_bf16(acc[mf][nf], aH[mf][0], aH[mf][1], aH[mf][2], aH[mf][3], bH0, bH1);
                    mma_bf16(acc[mf][nf], aH[mf][0], aH[mf][1], aH[mf][2], aH[mf][3], bL0, bL1);
                    mma_bf16(acc[mf][nf], aL[mf][0], aL[mf][1], aL[mf][2], aL[mf][3], bH0, bH1);
                }
            }
        }
    }
#pragma unroll
    for (int mf = 0; mf < 2; mf++) {
#pragma unroll
        for (int nf = 0; nf < 4; nf++) {
            int mrow = m0 + wm * 32 + mf * 16 + r;
            int col = n0 + wn * 32 + nf * 8 + cq;
            float c0 = acc[mf][nf][0], c1 = acc[mf][nf][1], c2 = acc[mf][nf][2], c3 = acc[mf][nf][3];
            if (HASBIAS) { float b0 = bias[col], b1 = bias[col + 1]; c0 += b0; c1 += b1; c2 += b0; c3 += b1; }
            if (SCALEQ) { c0 *= 0.0625f; c1 *= 0.0625f; c2 *= 0.0625f; c3 *= 0.0625f; }
            if (PREAUX) {
                Caux[(size_t)mrow * HD + col] = c0; Caux[(size_t)mrow * HD + col + 1] = c1;
                Caux[(size_t)(mrow + 8) * HD + col] = c2; Caux[(size_t)(mrow + 8) * HD + col + 1] = c3;
            }
            if (RELU) { c0 = fmaxf(c0, 0.f); c1 = fmaxf(c1, 0.f); c2 = fmaxf(c2, 0.f); c3 = fmaxf(c3, 0.f); }
            if (OUTF32) {
                Cf[(size_t)mrow * HD + col] = c0; Cf[(size_t)mrow * HD + col + 1] = c1;
                Cf[(size_t)(mrow + 8) * HD + col] = c2; Cf[(size_t)(mrow + 8) * HD + col + 1] = c3;
            }
            if (OUTSPLIT) {
                bf16 h0, l0b, h1, l1b, h2, l2b, h3, l3b;
                split1(c0, h0, l0b); split1(c1, h1, l1b); split1(c2, h2, l2b); split1(c3, h3, l3b);
                *(uint32_t*)(Chi + (size_t)mrow * HD + col) = ((uint32_t)__bfloat16_as_ushort(h1) << 16) | __bfloat16_as_ushort(h0);
                *(uint32_t*)(Clo + (size_t)mrow * HD + col) = ((uint32_t)__bfloat16_as_ushort(l1b) << 16) | __bfloat16_as_ushort(l0b);
                *(uint32_t*)(Chi + (size_t)(mrow + 8) * HD + col) = ((uint32_t)__bfloat16_as_ushort(h3) << 16) | __bfloat16_as_ushort(h2);
                *(uint32_t*)(Clo + (size_t)(mrow + 8) * HD + col) = ((uint32_t)__bfloat16_as_ushort(l3b) << 16) | __bfloat16_as_ushort(l2b);
            }
        }
    }
}

// ---------------- weight transpose + split: W[K][N] -> Wt hi/lo [N][KP] --------------
__global__ void wsplit_k(const float* __restrict__ W, bf16* __restrict__ th,
                         bf16* __restrict__ tl, int K, int N, int KPp) {
    int idx = blockIdx.x * blockDim.x + threadIdx.x;
    if (idx >= N * KPp) return;
    int k = idx % KPp, n = idx / KPp;
    float x = (k < K) ? W[(size_t)k * N + n] : 0.f;
    bf16 h, l; split1(x, h, l);
    th[idx] = h; tl[idx] = l;
}
// A[M][K] fp32 -> hi/lo [M][KP] (zero pad)
__global__ void asplit_k(const float* __restrict__ A, bf16* __restrict__ hi,
                         bf16* __restrict__ lo, int K, int KPp) {
    int idx = blockIdx.x * blockDim.x + threadIdx.x;
    int k = idx % KPp, m = idx / KPp;
    float x = (k < K) ? A[(size_t)m * K + k] : 0.f;
    bf16 h, l; split1(x, h, l);
    hi[idx] = h; lo[idx] = l;
}

// ---------------- fp32 GEMM (atom-side small matmuls) ----------------
template <int RELU, int HASBIAS>
__global__ __launch_bounds__(256) void gemm_k(const float* __restrict__ A, const float* __restrict__ B,
                                              const float* __restrict__ bias, float* __restrict__ C,
                                              int Mm, int Nn, int Kk){
    __shared__ float As[16*68];
    __shared__ float Bs[16*68];
    const int tid=threadIdx.x, tm=tid>>4, tn=tid&15;
    const int m0=blockIdx.y*64, n0=blockIdx.x*64;
    float acc[4][4]={};
    for(int k0=0;k0<Kk;k0+=16){
#pragma unroll
        for(int i=0;i<4;i++){int idx=tid+i*256,row=idx>>4,col=idx&15;float v=0.f;
            if(m0+row<Mm&&k0+col<Kk)v=A[(size_t)(m0+row)*Kk+k0+col];As[col*68+row]=v;}
#pragma unroll
        for(int i=0;i<4;i++){int idx=tid+i*256,row=idx>>6,col=idx&63;float v=0.f;
            if(k0+row<Kk&&n0+col<Nn)v=B[(size_t)(k0+row)*Nn+n0+col];Bs[row*68+col]=v;}
        __syncthreads();
#pragma unroll
        for(int kk=0;kk<16;kk++){
            float4 a4=*(const float4*)&As[kk*68+tm*4];
            float4 b4=*(const float4*)&Bs[kk*68+tn*4];
            float av[4]={a4.x,a4.y,a4.z,a4.w},bv[4]={b4.x,b4.y,b4.z,b4.w};
#pragma unroll
            for(int i=0;i<4;i++)
#pragma unroll
                for(int j=0;j<4;j++)acc[i][j]+=av[i]*bv[j];
        }
        __syncthreads();
    }
#pragma unroll
    for(int i=0;i<4;i++){int m=m0+tm*4+i;if(m>=Mm)continue;
#pragma unroll
        for(int j=0;j<4;j++){int n=n0+tn*4+j;if(n>=Nn)continue;
            float v=acc[i][j];if(HASBIAS)v+=bias[n];if(RELU)v=fmaxf(v,0.f);
            C[(size_t)m*Nn+n]=v;}}
}

// ---------------- V transpose + split ----------------
__global__ void vt_split_k(const float* __restrict__ V){
    __shared__ float t[32][33];
    int bx=blockIdx.x, by=blockIdx.y, tx=threadIdx.x, ty=threadIdx.y;
    for(int i=ty;i<32;i+=8) t[i][tx]=V[(size_t)(bx*32+i)*HD+by*32+tx];
    __syncthreads();
    for(int i=ty;i<32;i+=8){
        float x=t[tx][i];
        bf16 h,l; split1(x,h,l);
        size_t o=(size_t)(by*32+i)*NB+bx*32+tx;
        g_Vthi[o]=h; g_Vtlo[o]=l;
    }
}

// ---------------- mma.sync flash attention (validated R4 structure) -------------------
#define FL_BF 104960
#define SQH 0
#define SQL 33792
#define SKH 67584
#define SKL 76032
#define SVH 84480
#define SVL 94720
__global__ __launch_bounds__(256, 1) void flash_mma(){
    extern __shared__ bf16 sm[];
    const int tid = threadIdx.x, wid = tid >> 5, lane = tid & 31;
    const int r = lane >> 2, cq = (lane & 3) * 2;
    const int row0 = blockIdx.x * 128;
    const int half = blockIdx.y;
    const int kb0 = half * (NB / 2);

    // exact self-logit per row, reconstructed from hi+lo (Q already scaled 1/16)
    float cs0 = 0.f, cs1 = 0.f;
    {
        int rg = row0 + wid * 16 + r;
        const bf16 *q0h=&g_Qhi[(size_t)rg*HD], *q0l=&g_Qlo[(size_t)rg*HD];
        const bf16 *k0h=&g_Khi[(size_t)rg*HD], *k0l=&g_Klo[(size_t)rg*HD];
        const bf16 *q1h=&g_Qhi[(size_t)(rg+8)*HD], *q1l=&g_Qlo[(size_t)(rg+8)*HD];
        const bf16 *k1h=&g_Khi[(size_t)(rg+8)*HD], *k1l=&g_Klo[(size_t)(rg+8)*HD];
        int f0 = (lane & 3) * 64;
#pragma unroll 16
        for (int f = 0; f < 64; f++) {
            float q0 = __bfloat162float(q0h[f0+f]) + __bfloat162float(q0l[f0+f]);
            float k0 = __bfloat162float(k0h[f0+f]) + __bfloat162float(k0l[f0+f]);
            float q1 = __bfloat162float(q1h[f0+f]) + __bfloat162float(q1l[f0+f]);
            float k1 = __bfloat162float(k1h[f0+f]) + __bfloat162float(k1l[f0+f]);
            cs0 += q0 * k0; cs1 += q1 * k1;
        }
        cs0 += __shfl_xor_sync(0xffffffffu, cs0, 1);
        cs0 += __shfl_xor_sync(0xffffffffu, cs0, 2);
        cs1 += __shfl_xor_sync(0xffffffffu, cs1, 1);
        cs1 += __shfl_xor_sync(0xffffffffu, cs1, 2);
    }

#pragma unroll
    for (int i = 0; i < 16; i++) {
        int idx = tid + i * 256, row = idx >> 5, c8 = (idx & 31) * 8;
        *(uint4*)(sm + SQH + row * 264 + c8) = *(const uint4*)(g_Qhi + (size_t)(row0 + row) * HD + c8);
        *(uint4*)(sm + SQL + row * 264 + c8) = *(const uint4*)(g_Qlo + (size_t)(row0 + row) * HD + c8);
    }

    float Oc[32][4];
#pragma unroll
    for (int t = 0; t < 32; t++) { Oc[t][0]=0.f; Oc[t][1]=0.f; Oc[t][2]=0.f; Oc[t][3]=0.f; }
    float l0 = 0.f, l1 = 0.f;

    for (int kt = 0; kt < 128; kt++) {
        const int kb = kb0 + kt * 32;
        __syncthreads();
#pragma unroll
        for (int i = 0; i < 4; i++) {
            int idx = tid + i * 256, row = idx >> 5, c8 = (idx & 31) * 8;
            *(uint4*)(sm + SKH + row * 264 + c8) = *(const uint4*)(g_Khi + (size_t)(kb + row) * HD + c8);
            *(uint4*)(sm + SKL + row * 264 + c8) = *(const uint4*)(g_Klo + (size_t)(kb + row) * HD + c8);
        }
#pragma unroll
        for (int i = 0; i < 4; i++) {
            int idx = tid + i * 256, n = idx >> 2, k8 = (idx & 3) * 8;
            *(uint4*)(sm + SVH + n * 40 + k8) = *(const uint4*)(g_Vthi + (size_t)n * NB + kb + k8);
            *(uint4*)(sm + SVL + n * 40 + k8) = *(const uint4*)(g_Vtlo + (size_t)n * NB + kb + k8);
        }
        __syncthreads();

        float Sc[4][4];
#pragma unroll
        for (int t = 0; t < 4; t++) { Sc[t][0]=0.f; Sc[t][1]=0.f; Sc[t][2]=0.f; Sc[t][3]=0.f; }
        const bf16* qh = sm + SQH + (wid * 16 + r) * 264 + cq;
        const bf16* ql = sm + SQL + (wid * 16 + r) * 264 + cq;
#pragma unroll
        for (int ks = 0; ks < 16; ks++) {
            uint32_t aH0 = *(const uint32_t*)(qh + ks * 16);
            uint32_t aH1 = *(const uint32_t*)(qh + 8 * 264 + ks * 16);
            uint32_t aH2 = *(const uint32_t*)(qh + ks * 16 + 8);
            uint32_t aH3 = *(const uint32_t*)(qh + 8 * 264 + ks * 16 + 8);
            uint32_t aL0 = *(const uint32_t*)(ql + ks * 16);
            uint32_t aL1 = *(const uint32_t*)(ql + 8 * 264 + ks * 16);
            uint32_t aL2 = *(const uint32_t*)(ql + ks * 16 + 8);
            uint32_t aL3 = *(const uint32_t*)(ql + 8 * 264 + ks * 16 + 8);
#pragma unroll
            for (int t = 0; t < 4; t++) {
                const bf16* kh = sm + SKH + (t * 8 + r) * 264 + ks * 16 + cq;
                const bf16* kl = sm + SKL + (t * 8 + r) * 264 + ks * 16 + cq;
                uint32_t bH0 = *(const uint32_t*)kh, bH1 = *(const uint32_t*)(kh + 8);
                uint32_t bL0 = *(const uint32_t*)kl, bL1 = *(const uint32_t*)(kl + 8);
                mma_bf16(Sc[t], aH0, aH1, aH2, aH3, bH0, bH1);
                mma_bf16(Sc[t], aH0, aH1, aH2, aH3, bL0, bL1);
                mma_bf16(Sc[t], aL0, aL1, aL2, aL3, bH0, bH1);
            }
        }
        uint32_t pH[2][4], pL[2][4];
        float rs0 = 0.f, rs1 = 0.f;
#pragma unroll
        for (int t = 0; t < 4; t++) {
            float e0 = __expf(Sc[t][0] - cs0);
            float e1 = __expf(Sc[t][1] - cs0);
            float e2 = __expf(Sc[t][2] - cs1);
            float e3 = __expf(Sc[t][3] - cs1);
            rs0 += e0 + e1; rs1 += e2 + e3;
            bf16 h0=__float2bfloat16(e0), h1=__float2bfloat16(e1);
            bf16 h2=__float2bfloat16(e2), h3=__float2bfloat16(e3);
            float q0=e0-__bfloat162float(h0), q1=e1-__bfloat162float(h1);
            float q2=e2-__bfloat162float(h2), q3=e3-__bfloat162float(h3);
            int ksp = t >> 1, hi2 = (t & 1) * 2;
            pH[ksp][hi2]     = ((uint32_t)__bfloat16_as_ushort(h1) << 16) | (uint32_t)__bfloat16_as_ushort(h0);
            pH[ksp][hi2 + 1] = ((uint32_t)__bfloat16_as_ushort(h3) << 16) | (uint32_t)__bfloat16_as_ushort(h2);
            pL[ksp][hi2]     = packbf(q0, q1);
            pL[ksp][hi2 + 1] = packbf(q2, q3);
        }
        rs0 += __shfl_xor_sync(0xffffffffu, rs0, 1);
        rs0 += __shfl_xor_sync(0xffffffffu, rs0, 2);
        rs1 += __shfl_xor_sync(0xffffffffu, rs1, 1);
        rs1 += __shfl_xor_sync(0xffffffffu, rs1, 2);
        l0 += rs0; l1 += rs1;

#pragma unroll
        for (int ks2 = 0; ks2 < 2; ks2++) {
#pragma unroll
            for (int t = 0; t < 32; t++) {
                const bf16* vh = sm + SVH + (t * 8 + r) * 40 + ks2 * 16 + cq;
                const bf16* vl = sm + SVL + (t * 8 + r) * 40 + ks2 * 16 + cq;
                uint32_t bH0 = *(const uint32_t*)vh, bH1 = *(const uint32_t*)(vh + 8);
                uint32_t bL0 = *(const uint32_t*)vl, bL1 = *(const uint32_t*)(vl + 8);
                mma_bf16(Oc[t], pH[ks2][0], pH[ks2][1], pH[ks2][2], pH[ks2][3], bH0, bH1);
                mma_bf16(Oc[t], pH[ks2][0], pH[ks2][1], pH[ks2][2], pH[ks2][3], bL0, bL1);
                mma_bf16(Oc[t], pL[ks2][0], pL[ks2][1], pL[ks2][2], pL[ks2][3], bH0, bH1);
            }
        }
    }
    {
        int rg = row0 + wid * 16 + r;
        float* O = g_Opart + (size_t)half * NB * HD;
#pragma unroll
        for (int t = 0; t < 32; t++) {
            int col = t * 8 + cq;
            O[(size_t)rg * HD + col]       = Oc[t][0];
            O[(size_t)rg * HD + col + 1]   = Oc[t][1];
            O[(size_t)(rg + 8) * HD + col]     = Oc[t][2];
            O[(size_t)(rg + 8) * HD + col + 1] = Oc[t][3];
        }
        if ((lane & 3) == 0) {
            g_lpart[half * NB + rg] = l0;
            g_lpart[half * NB + rg + 8] = l1;
        }
    }
}

__global__ void flash_merge_k(){
    int row = blockIdx.x, c = threadIdx.x;
    float li = 1.f / (g_lpart[row] + g_lpart[NB + row]);
    size_t o = (size_t)row * HD + c;
    float v = (g_Opart[o] + g_Opart[(size_t)NB * HD + o]) * li;
    bf16 h, l; split1(v, h, l);
    g_avhi[o] = h; g_avlo[o] = l;
}

// ---------------- atom self-attn + LN ----------------
#define AT_SMEM_FLOATS (4*64*136+64*64+512+128)
__global__ __launch_bounds__(256,1) void atom_attn_ln_k(const float* __restrict__ xg,
                                                        const float* __restrict__ gw,
                                                        const float* __restrict__ bw){
    extern __shared__ float smf[];
    float* sx=smf; float* sq=sx+64*136; float* sk=sq+64*136; float* sv=sk+64*136;
    float* ss=sv+64*136; float* sred=ss+4096; float* srow=sred+512;
    const int tid=threadIdx.x; const int base=blockIdx.x*64;
    for(int idx=tid;idx<64*FDIM;idx+=256){
        int a=idx/FDIM,f=idx-a*FDIM; size_t go=(size_t)(base+a)*FDIM+f;
        sx[a*136+f]=xg[go]; sq[a*136+f]=g_qa[go]; sk[a*136+f]=g_ka[go]; sv[a*136+f]=g_va[go];
    }
    __syncthreads();
    {
        int ty=tid>>4,tx=tid&15; float acc[4][4]={};
        for(int h=0;h<FDIM;h++){
            float qv[4],kv[4];
#pragma unroll
            for(int i=0;i<4;i++){qv[i]=sq[(ty*4+i)*136+h];kv[i]=sk[(tx*4+i)*136+h];}
#pragma unroll
            for(int i=0;i<4;i++)
#pragma unroll
                for(int j=0;j<4;j++)acc[i][j]+=qv[i]*kv[j];
        }
        float scl=rsqrtf(133.0f);
#pragma unroll
        for(int i=0;i<4;i++)
#pragma unroll
            for(int j=0;j<4;j++)ss[(ty*4+i)*64+tx*4+j]=acc[i][j]*scl;
    }
    __syncthreads();
    if(tid<64){
        float mx=-1e30f;
        for(int j=0;j<64;j++)mx=fmaxf(mx,ss[tid*64+j]);
        float s=0.f;
        for(int j=0;j<64;j++){float e=__expf(ss[tid*64+j]-mx);ss[tid*64+j]=e;s+=e;}
        float inv=1.f/s;
        for(int j=0;j<64;j++)ss[tid*64+j]*=inv;
    }
    __syncthreads();
    const int r=tid>>2,qd=tid&3,f0=qd*34;
    float tv[34];
#pragma unroll
    for(int f=0;f<34;f++)tv[f]=0.f;
    for(int b=0;b<64;b++){
        float p=ss[r*64+b]; const float* vb=&sv[b*136+f0];
#pragma unroll
        for(int f=0;f<34;f++)if(f0+f<FDIM)tv[f]+=p*vb[f];
    }
    float s1=0.f;
#pragma unroll
    for(int f=0;f<34;f++)if(f0+f<FDIM){tv[f]+=sx[r*136+f0+f];s1+=tv[f];}
    sred[tid]=s1; __syncthreads();
    if(qd==0)srow[r]=(sred[tid]+sred[tid+1]+sred[tid+2]+sred[tid+3])*(1.f/133.f);
    __syncthreads();
    float mu=srow[r],s2=0.f;
#pragma unroll
    for(int f=0;f<34;f++)if(f0+f<FDIM){float d=tv[f]-mu;s2+=d*d;}
    sred[tid]=s2; __syncthreads();
    if(qd==0){float var=(sred[tid]+sred[tid+1]+sred[tid+2]+sred[tid+3])*(1.f/133.f);srow[64+r]=rsqrtf(var+1e-5f);}
    __syncthreads();
    float rstd=srow[64+r];
#pragma unroll
    for(int f=0;f<34;f++){int fg=f0+f;
        if(fg<FDIM)g_fe[(size_t)(base+r)*FDIM+fg]=(tv[f]-mu)*rstd*gw[fg]+bw[fg];}
}

// ---------------- elementwise / gather ----------------
__global__ void gather_sum_k(const int* __restrict__ a2b){
    __shared__ int idx[MAXNB];
    int a=blockIdx.x,t=threadIdx.x;
    if(t<MAXNB)idx[t]=a2b[a*MAXNB+t];
    __syncthreads();
    float s=0.f;
#pragma unroll
    for(int j=0;j<MAXNB;j++)s+=g_msg[(size_t)idx[j]*HD+t];
    g_amsg[(size_t)a*HD+t]=s;
}
__global__ void dmpnn_pre_k(const int* __restrict__ b2a, const int* __restrict__ b2revb){
    int b=blockIdx.x,t=threadIdx.x;
    int ia=__ldg(&b2a[b]),ir=__ldg(&b2revb[b]);
    float v=g_amsg[(size_t)ia*HD+t]-g_msg[(size_t)ir*HD+t];
    bf16 h,l; split1(v,h,l);
    size_t o=(size_t)b*HD+t;
    g_tmphi[o]=h; g_tmplo[o]=l;
}
__global__ void combine_k(const float* __restrict__ wal, const float* __restrict__ walb){
    __shared__ float red[256];
    __shared__ float salpha;
    int b=blockIdx.x,t=threadIdx.x;
    size_t o=(size_t)b*HD+t;
    float d=g_dmpnn[o],am=g_attm[o];
    red[t]=d*wal[t]+am*wal[256+t];
    __syncthreads();
    for(int s=128;s>0;s>>=1){if(t<s)red[t]+=red[t+s];__syncthreads();}
    if(t==0)salpha=1.f/(1.f+__expf(-(red[0]+walb[0])));
    __syncthreads();
    float al=salpha;
    float v=fmaxf(g_inputs[o]+al*d+(1.f-al)*am,0.f);
    g_msg[o]=v;
    bf16 h,l; split1(v,h,l);
    g_msghi[o]=h; g_msglo[o]=l;
}
__global__ void concat_split_k(){
    int i=blockIdx.x*blockDim.x+threadIdx.x;
    if(i>=NA*KP_WO)return;
    int row=i/KP_WO,c=i-row*KP_WO;
    float x = (c<FDIM) ? g_fe[(size_t)row*FDIM+c]
             : (c<FDIM+HD ? g_amsg[(size_t)row*HD+(c-FDIM)] : 0.f);
    bf16 h,l; split1(x,h,l);
    g_cathi[i]=h; g_catlo[i]=l;
}

// ---------------- molecule pooling ----------------
#define MP_SMEM_FLOATS (2*64*260+4096)
__global__ __launch_bounds__(256,1) void mol_pool_k(const float* __restrict__ Wb,
                                                    const float* __restrict__ bb,
                                                    float* __restrict__ outg){
    extern __shared__ float smf[];
    float* shm=smf; float* sw=shm+64*260; float* ssc=sw+64*260;
    const int tid=threadIdx.x; const int base=blockIdx.x*64;
    for(int idx=tid;idx<64*HD;idx+=256){
        int a=idx>>8,c=idx&255;
        shm[a*260+c]=g_atomh[(size_t)(base+a)*HD+c];
        sw[a*260+c]=g_hmwa[(size_t)(base+a)*HD+c];
    }
    __syncthreads();
    {
        int ty=tid>>4,tx=tid&15; float acc[4][4]={};
        for(int h=0;h<HD;h++){
            float qv[4],kv[4];
#pragma unroll
            for(int i=0;i<4;i++){qv[i]=sw[(ty*4+i)*260+h];kv[i]=shm[(tx*4+i)*260+h];}
#pragma unroll
            for(int i=0;i<4;i++)
#pragma unroll
                for(int j=0;j<4;j++)acc[i][j]+=qv[i]*kv[j];
        }
#pragma unroll
        for(int i=0;i<4;i++)
#pragma unroll
            for(int j=0;j<4;j++)ssc[(ty*4+i)*64+tx*4+j]=acc[i][j];
    }
    __syncthreads();
    if(tid<64){
        float mx=-1e30f;
        for(int j=0;j<64;j++)mx=fmaxf(mx,ssc[tid*64+j]);
        float s=0.f;
        for(int j=0;j<64;j++){float e=__expf(ssc[tid*64+j]-mx);ssc[tid*64+j]=e;s+=e;}
        float inv=1.f/s;
        for(int j=0;j<64;j++)ssc[tid*64+j]*=inv;
    }
    __syncthreads();
    const int c=tid;
    float acc[64];
#pragma unroll
    for(int a=0;a<64;a++)acc[a]=0.f;
    for(int b=0;b<64;b++){
        float hv=shm[b*260+c];
#pragma unroll 16
        for(int a=0;a<64;a++)acc[a]+=ssc[a*64+b]*hv;
    }
    __syncthreads();
    for(int a=0;a<64;a++)sw[a*260+c]=acc[a];
    __syncthreads();
#pragma unroll
    for(int a=0;a<64;a++)acc[a]=0.f;
    for(int k=0;k<HD;k++){
        float wv=Wb[(size_t)k*HD+c];
#pragma unroll 16
        for(int a=0;a<64;a++)acc[a]+=sw[a*260+k]*wv;
    }
    float bv=bb[c],s=0.f;
    for(int a=0;a<64;a++){
        float t=fmaxf(acc[a]+bv,0.f);
        s+=shm[a*260+c]+t;
    }
    outg[(size_t)blockIdx.x*HD+c]=s*(1.f/64.f);
}

// ---------------- host driver ----------------
static float* symf(const void* s){ void* p=nullptr; cudaGetSymbolAddress(&p,s); return (float*)p; }
static bf16* symb(const void* s){ void* p=nullptr; cudaGetSymbolAddress(&p,s); return (bf16*)p; }

extern "C" void kernel_launch(void* const* d_in, const int* in_sizes, int n_in,
                              void* d_out, int out_size){
    const float* f_atoms=(const float*)d_in[0];
    const float* f_bonds=(const float*)d_in[1];
    const float* Wq_atom=(const float*)d_in[2];
    const float* Wk_atom=(const float*)d_in[3];
    const float* Wv_atom=(const float*)d_in[4];
    const float* ln_g=(const float*)d_in[5];
    const float* ln_b=(const float*)d_in[6];
    const float* Wi=(const float*)d_in[7];
    const float* Wh=(const float*)d_in[8];
    const float* Wq=(const float*)d_in[9];
    const float* Wk=(const float*)d_in[10];
    const float* Wv=(const float*)d_in[11];
    const float* Wa=(const float*)d_in[12];
    const float* Walw=(const float*)d_in[13];
    const float* Walb=(const float*)d_in[14];
    const float* Wow=(const float*)d_in[15];
    const float* Wob=(const float*)d_in[16];
    const float* Wbw=(const float*)d_in[17];
    const float* Wbb=(const float*)d_in[18];
    const int* a2b=(const int*)d_in[19];
    const int* b2a=(const int*)d_in[20];
    const int* b2revb=(const int*)d_in[21];
    float* out=(float*)d_out;

    float* p_qa=symf(g_qa); float* p_ka=symf(g_ka); float* p_va=symf(g_va);
    float* p_inputs=symf(g_inputs); float* p_msg=symf(g_msg);
    float* p_dmpnn=symf(g_dmpnn); float* p_V=symf(g_V); float* p_attm=symf(g_attm);
    float* p_atomh=symf(g_atomh); float* p_hmwa=symf(g_hmwa);
    bf16* p_Qhi=symb(g_Qhi); bf16* p_Qlo=symb(g_Qlo);
    bf16* p_Khi=symb(g_Khi); bf16* p_Klo=symb(g_Klo);
    bf16* p_msghi=symb(g_msghi); bf16* p_msglo=symb(g_msglo);
    bf16* p_tmphi=symb(g_tmphi); bf16* p_tmplo=symb(g_tmplo);
    bf16* p_avhi=symb(g_avhi); bf16* p_avlo=symb(g_avlo);
    bf16* p_fbhi=symb(g_fbhi); bf16* p_fblo=symb(g_fblo);
    bf16* p_cathi=symb(g_cathi); bf16* p_catlo=symb(g_catlo);
    bf16* p_ahhi=symb(g_ahhi); bf16* p_ahlo=symb(g_ahlo);
    bf16* p_Withi=symb(g_Withi); bf16* p_Witlo=symb(g_Witlo);
    bf16* p_Whthi=symb(g_Whthi); bf16* p_Whtlo=symb(g_Whtlo);
    bf16* p_Wqthi=symb(g_Wqthi); bf16* p_Wqtlo=symb(g_Wqtlo);
    bf16* p_Wkthi=symb(g_Wkthi); bf16* p_Wktlo=symb(g_Wktlo);
    bf16* p_Wvthi=symb(g_Wvthi); bf16* p_Wvtlo=symb(g_Wvtlo);
    bf16* p_Wathi=symb(g_Wathi); bf16* p_Watlo=symb(g_Watlo);
    bf16* p_Wothi=symb(g_Wothi); bf16* p_Wotlo=symb(g_Wotlo);

    const int AT_SMEM=AT_SMEM_FLOATS*4, MP_SMEM=MP_SMEM_FLOATS*4;
    const int FL_SMEM=FL_BF*2;
    cudaFuncSetAttribute(flash_mma,cudaFuncAttributeMaxDynamicSharedMemorySize,FL_SMEM);
    cudaFuncSetAttribute(atom_attn_ln_k,cudaFuncAttributeMaxDynamicSharedMemorySize,AT_SMEM);
    cudaFuncSetAttribute(mol_pool_k,cudaFuncAttributeMaxDynamicSharedMemorySize,MP_SMEM);

    // weight transpose+split (once per launch)
    wsplit_k<<<(HD*KP_WI+255)/256,256>>>(Wi,p_Withi,p_Witlo,BFDIM,HD,KP_WI);
    wsplit_k<<<(HD*HD+255)/256,256>>>(Wh,p_Whthi,p_Whtlo,HD,HD,HD);
    wsplit_k<<<(HD*HD+255)/256,256>>>(Wq,p_Wqthi,p_Wqtlo,HD,HD,HD);
    wsplit_k<<<(HD*HD+255)/256,256>>>(Wk,p_Wkthi,p_Wktlo,HD,HD,HD);
    wsplit_k<<<(HD*HD+255)/256,256>>>(Wv,p_Wvthi,p_Wvtlo,HD,HD,HD);
    wsplit_k<<<(HD*HD+255)/256,256>>>(Wa,p_Wathi,p_Watlo,HD,HD,HD);
    wsplit_k<<<(HD*KP_WO+255)/256,256>>>(Wow,p_Wothi,p_Wotlo,FDIM+HD,HD,KP_WO);
    asplit_k<<<(NB*KP_WI)/256,256>>>(f_bonds,p_fbhi,p_fblo,BFDIM,KP_WI);

    // atom enhancement (fp32 SIMT — small)
    dim3 gqa((FDIM+63)/64,(NA+63)/64);
    gemm_k<0,0><<<gqa,256>>>(f_atoms,Wq_atom,nullptr,p_qa,NA,FDIM,FDIM);
    gemm_k<0,0><<<gqa,256>>>(f_atoms,Wk_atom,nullptr,p_ka,NA,FDIM,FDIM);
    gemm_k<0,0><<<gqa,256>>>(f_atoms,Wv_atom,nullptr,p_va,NA,FDIM,FDIM);
    atom_attn_ln_k<<<NMOL,256,AT_SMEM>>>(f_atoms,ln_g,ln_b);

    // bond init: inputs=f_bonds@Wi (pre-relu aux), msg=relu fp32+split
    dim3 tgb(4,NB/128), tga(4,NA/128);
    tgemm<1,0,0,1,1,1><<<tgb,256>>>(p_fbhi,p_fblo,p_Withi,p_Witlo,nullptr,
                                    p_msg,p_msghi,p_msglo,p_inputs,NB,KP_WI);

    dim3 vtg(NB/32,HD/32), vtb(32,8);
    for(int it=0;it<3;it++){
        gather_sum_k<<<NA,256>>>(a2b);
        dmpnn_pre_k<<<NB,256>>>(b2a,b2revb);
        tgemm<0,0,0,1,0,0><<<tgb,256>>>(p_tmphi,p_tmplo,p_Whthi,p_Whtlo,nullptr,
                                        p_dmpnn,nullptr,nullptr,nullptr,NB,HD);
        tgemm<0,0,1,0,1,0><<<tgb,256>>>(p_msghi,p_msglo,p_Wqthi,p_Wqtlo,nullptr,
                                        nullptr,p_Qhi,p_Qlo,nullptr,NB,HD);
        tgemm<0,0,0,0,1,0><<<tgb,256>>>(p_msghi,p_msglo,p_Wkthi,p_Wktlo,nullptr,
                                        nullptr,p_Khi,p_Klo,nullptr,NB,HD);
        tgemm<0,0,0,1,0,0><<<tgb,256>>>(p_msghi,p_msglo,p_Wvthi,p_Wvtlo,nullptr,
                                        p_V,nullptr,nullptr,nullptr,NB,HD);
        vt_split_k<<<vtg,vtb>>>(p_V);
        flash_mma<<<dim3(NB/128,2),256,FL_SMEM>>>();
        flash_merge_k<<<NB,256>>>();
        tgemm<0,0,0,1,0,0><<<tgb,256>>>(p_avhi,p_avlo,p_Wathi,p_Watlo,nullptr,
                                        p_attm,nullptr,nullptr,nullptr,NB,HD);
        combine_k<<<NB,256>>>(Walw,Walb);
    }

    gather_sum_k<<<NA,256>>>(a2b);
    concat_split_k<<<(NA*KP_WO+255)/256,256>>>();
    tgemm<1,1,0,1,1,0><<<tga,256>>>(p_cathi,p_catlo,p_Wothi,p_Wotlo,Wob,
                                    p_atomh,p_ahhi,p_ahlo,nullptr,NA,KP_WO);
    tgemm<0,0,0,1,0,0><<<tga,256>>>(p_ahhi,p_ahlo,p_Wathi,p_Watlo,nullptr,
                                    p_hmwa,nullptr,nullptr,nullptr,NA,HD);
    mol_pool_k<<<NMOL,256,MP_SMEM>>>(Wbw,Wbb,out);
}

// round 6
// speedup vs baseline: 11.1677x; 1.0309x over previous
#include <cuda_runtime.h>
#include <cuda_bf16.h>
#include <math.h>
#include <stdint.h>

#define NA 4096
#define NB 8192
#define FDIM 133
#define BFDIM 147
#define HD 256
#define NMOL 64
#define MAXNB 6
#define KP_WI 160
#define KP_WO 416

typedef __nv_bfloat16 bf16;

// ---------------- device scratch ----------------
__device__ __align__(16) float g_qa[NA*FDIM];
__device__ __align__(16) float g_ka[NA*FDIM];
__device__ __align__(16) float g_va[NA*FDIM];
__device__ __align__(16) float g_fe[NA*FDIM];
__device__ __align__(16) float g_inputs[NB*HD];
__device__ __align__(16) float g_msg[NB*HD];
__device__ __align__(16) float g_amsg[NA*HD];
__device__ __align__(16) float g_dmpnn[NB*HD];
__device__ __align__(16) float g_V[NB*HD];
__device__ __align__(16) float g_attm[NB*HD];
__device__ __align__(16) float g_atomh[NA*HD];
__device__ __align__(16) float g_hmwa[NA*HD];
__device__ __align__(16) float g_Opart[2*NB*HD];
__device__ __align__(16) float g_lpart[2*NB];

__device__ __align__(16) bf16 g_Qhi[NB*HD];
__device__ __align__(16) bf16 g_Qlo[NB*HD];
__device__ __align__(16) bf16 g_Khi[NB*HD];
__device__ __align__(16) bf16 g_Klo[NB*HD];
__device__ __align__(16) bf16 g_Vthi[HD*NB];
__device__ __align__(16) bf16 g_Vtlo[HD*NB];
__device__ __align__(16) bf16 g_msghi[NB*HD];
__device__ __align__(16) bf16 g_msglo[NB*HD];
__device__ __align__(16) bf16 g_tmphi[NB*HD];
__device__ __align__(16) bf16 g_tmplo[NB*HD];
__device__ __align__(16) bf16 g_avhi[NB*HD];
__device__ __align__(16) bf16 g_avlo[NB*HD];
__device__ __align__(16) bf16 g_fbhi[NB*KP_WI];
__device__ __align__(16) bf16 g_fblo[NB*KP_WI];
__device__ __align__(16) bf16 g_cathi[NA*KP_WO];
__device__ __align__(16) bf16 g_catlo[NA*KP_WO];
__device__ __align__(16) bf16 g_ahhi[NA*HD];
__device__ __align__(16) bf16 g_ahlo[NA*HD];
__device__ __align__(16) bf16 g_Withi[HD*KP_WI];
__device__ __align__(16) bf16 g_Witlo[HD*KP_WI];
__device__ __align__(16) bf16 g_Whthi[HD*HD];
__device__ __align__(16) bf16 g_Whtlo[HD*HD];
__device__ __align__(16) bf16 g_Wqthi[HD*HD];
__device__ __align__(16) bf16 g_Wqtlo[HD*HD];
__device__ __align__(16) bf16 g_Wkthi[HD*HD];
__device__ __align__(16) bf16 g_Wktlo[HD*HD];
__device__ __align__(16) bf16 g_Wvthi[HD*HD];
__device__ __align__(16) bf16 g_Wvtlo[HD*HD];
__device__ __align__(16) bf16 g_Wathi[HD*HD];
__device__ __align__(16) bf16 g_Watlo[HD*HD];
__device__ __align__(16) bf16 g_Wothi[HD*KP_WO];
__device__ __align__(16) bf16 g_Wotlo[HD*KP_WO];

// ---------------- mma.sync / ldmatrix helpers ----------------
__device__ __forceinline__ void mma_bf16(float* c, uint32_t a0, uint32_t a1, uint32_t a2,
                                         uint32_t a3, uint32_t b0, uint32_t b1) {
    asm("mma.sync.aligned.m16n8k16.row.col.f32.bf16.bf16.f32 "
        "{%0,%1,%2,%3}, {%4,%5,%6,%7}, {%8,%9}, {%0,%1,%2,%3};\n"
        : "+f"(c[0]), "+f"(c[1]), "+f"(c[2]), "+f"(c[3])
        : "r"(a0), "r"(a1), "r"(a2), "r"(a3), "r"(b0), "r"(b1));
}
__device__ __forceinline__ uint32_t smaddr(const void* p) {
    return (uint32_t)__cvta_generic_to_shared(p);
}
__device__ __forceinline__ void ldsm4(uint32_t* r, uint32_t a) {
    asm volatile("ldmatrix.sync.aligned.m8n8.x4.shared.b16 {%0,%1,%2,%3}, [%4];"
                 : "=r"(r[0]), "=r"(r[1]), "=r"(r[2]), "=r"(r[3]) : "r"(a));
}
__device__ __forceinline__ uint32_t packbf(float x, float y) {
    bf16 h0 = __float2bfloat16(x), h1 = __float2bfloat16(y);
    return ((uint32_t)__bfloat16_as_ushort(h1) << 16) | (uint32_t)__bfloat16_as_ushort(h0);
}
__device__ __forceinline__ void split1(float x, bf16& h, bf16& l) {
    h = __float2bfloat16(x);
    l = __float2bfloat16(x - __bfloat162float(h));
}

// ---------------- bf16 hi/lo tensor GEMM (ldmatrix fragments) ----------------
template <int RELU, int HASBIAS, int SCALEQ, int OUTF32, int OUTSPLIT, int PREAUX>
__global__ __launch_bounds__(256) void tgemm(
    const bf16* __restrict__ Ah, const bf16* __restrict__ Al,
    const bf16* __restrict__ Bh, const bf16* __restrict__ Bl,
    const float* __restrict__ bias,
    float* __restrict__ Cf, bf16* __restrict__ Chi, bf16* __restrict__ Clo,
    float* __restrict__ Caux, int M, int K) {
    __shared__ __align__(16) bf16 sAh[128*40], sAl[128*40], sBh[64*40], sBl[64*40];
    const int tid = threadIdx.x, wid = tid >> 5, lane = tid & 31;
    const int r = lane >> 2, cq = (lane & 3) * 2;
    const int wm = wid >> 1, wn = wid & 1;
    const int m0 = blockIdx.y * 128, n0 = blockIdx.x * 64;
    // ldmatrix lane offsets
    const int a_ro = (lane & 7) + ((lane >> 3) & 1) * 8;
    const int a_ch = ((lane >> 4) & 1) * 8;
    const int b_no = (lane & 7) + ((lane >> 4) & 1) * 8;
    const int b_kh = ((lane >> 3) & 1) * 8;
    float acc[2][4][4] = {};
    for (int kc = 0; kc < K; kc += 32) {
        __syncthreads();
#pragma unroll
        for (int i = 0; i < 2; i++) {
            int idx = tid + i * 256, row = idx >> 2, q8 = (idx & 3) * 8;
            *(uint4*)(sAh + row * 40 + q8) = *(const uint4*)(Ah + (size_t)(m0 + row) * K + kc + q8);
            *(uint4*)(sAl + row * 40 + q8) = *(const uint4*)(Al + (size_t)(m0 + row) * K + kc + q8);
        }
        {
            int row = tid >> 2, q8 = (tid & 3) * 8;
            *(uint4*)(sBh + row * 40 + q8) = *(const uint4*)(Bh + (size_t)(n0 + row) * K + kc + q8);
            *(uint4*)(sBl + row * 40 + q8) = *(const uint4*)(Bl + (size_t)(n0 + row) * K + kc + q8);
        }
        __syncthreads();
        uint32_t aHb[2], aLb[2], bHb, bLb;
        aHb[0] = smaddr(sAh + (wm * 32 + a_ro) * 40 + a_ch);
        aHb[1] = smaddr(sAh + (wm * 32 + 16 + a_ro) * 40 + a_ch);
        aLb[0] = smaddr(sAl + (wm * 32 + a_ro) * 40 + a_ch);
        aLb[1] = smaddr(sAl + (wm * 32 + 16 + a_ro) * 40 + a_ch);
        bHb = smaddr(sBh + (wn * 32 + b_no) * 40 + b_kh);
        bLb = smaddr(sBl + (wn * 32 + b_no) * 40 + b_kh);
#pragma unroll
        for (int ks = 0; ks < 2; ks++) {
            uint32_t aH[2][4], aL[2][4];
#pragma unroll
            for (int mf = 0; mf < 2; mf++) {
                ldsm4(aH[mf], aHb[mf] + ks * 32);
                ldsm4(aL[mf], aLb[mf] + ks * 32);
            }
#pragma unroll
            for (int np = 0; np < 2; np++) {
                uint32_t bH[4], bL[4];
                ldsm4(bH, bHb + np * 1280 + ks * 32);
                ldsm4(bL, bLb + np * 1280 + ks * 32);
#pragma unroll
                for (int mf = 0; mf < 2; mf++) {
                    mma_bf16(acc[mf][np*2], aH[mf][0], aH[mf][1], aH[mf][2], aH[mf][3], bH[0], bH[1]);
                    mma_bf16(acc[mf][np*2], aH[mf][0], aH[mf][1], aH[mf][2], aH[mf][3], bL[0], bL[1]);
                    mma_bf16(acc[mf][np*2], aL[mf][0], aL[mf][1], aL[mf][2], aL[mf][3], bH[0], bH[1]);
                    mma_bf16(acc[mf][np*2+1], aH[mf][0], aH[mf][1], aH[mf][2], aH[mf][3], bH[2], bH[3]);
                    mma_bf16(acc[mf][np*2+1], aH[mf][0], aH[mf][1], aH[mf][2], aH[mf][3], bL[2], bL[3]);
                    mma_bf16(acc[mf][np*2+1], aL[mf][0], aL[mf][1], aL[mf][2], aL[mf][3], bH[2], bH[3]);
                }
            }
        }
    }
#pragma unroll
    for (int mf = 0; mf < 2; mf++) {
#pragma unroll
        for (int nf = 0; nf < 4; nf++) {
            int mrow = m0 + wm * 32 + mf * 16 + r;
            int col = n0 + wn * 32 + nf * 8 + cq;
            float c0 = acc[mf][nf][0], c1 = acc[mf][nf][1], c2 = acc[mf][nf][2], c3 = acc[mf][nf][3];
            if (HASBIAS) { float b0 = bias[col], b1 = bias[col + 1]; c0 += b0; c1 += b1; c2 += b0; c3 += b1; }
            if (SCALEQ) { c0 *= 0.0625f; c1 *= 0.0625f; c2 *= 0.0625f; c3 *= 0.0625f; }
            if (PREAUX) {
                Caux[(size_t)mrow * HD + col] = c0; Caux[(size_t)mrow * HD + col + 1] = c1;
                Caux[(size_t)(mrow + 8) * HD + col] = c2; Caux[(size_t)(mrow + 8) * HD + col + 1] = c3;
            }
            if (RELU) { c0 = fmaxf(c0, 0.f); c1 = fmaxf(c1, 0.f); c2 = fmaxf(c2, 0.f); c3 = fmaxf(c3, 0.f); }
            if (OUTF32) {
                Cf[(size_t)mrow * HD + col] = c0; Cf[(size_t)mrow * HD + col + 1] = c1;
                Cf[(size_t)(mrow + 8) * HD + col] = c2; Cf[(size_t)(mrow + 8) * HD + col + 1] = c3;
            }
            if (OUTSPLIT) {
                bf16 h0, l0b, h1, l1b, h2, l2b, h3, l3b;
                split1(c0, h0, l0b); split1(c1, h1, l1b); split1(c2, h2, l2b); split1(c3, h3, l3b);
                *(uint32_t*)(Chi + (size_t)mrow * HD + col) = ((uint32_t)__bfloat16_as_ushort(h1) << 16) | __bfloat16_as_ushort(h0);
                *(uint32_t*)(Clo + (size_t)mrow * HD + col) = ((uint32_t)__bfloat16_as_ushort(l1b) << 16) | __bfloat16_as_ushort(l0b);
                *(uint32_t*)(Chi + (size_t)(mrow + 8) * HD + col) = ((uint32_t)__bfloat16_as_ushort(h3) << 16) | __bfloat16_as_ushort(h2);
                *(uint32_t*)(Clo + (size_t)(mrow + 8) * HD + col) = ((uint32_t)__bfloat16_as_ushort(l3b) << 16) | __bfloat16_as_ushort(l2b);
            }
        }
    }
}

// ---------------- weight / activation splits ----------------
__global__ void wsplit_k(const float* __restrict__ W, bf16* __restrict__ th,
                         bf16* __restrict__ tl, int K, int N, int KPp) {
    int idx = blockIdx.x * blockDim.x + threadIdx.x;
    if (idx >= N * KPp) return;
    int k = idx % KPp, n = idx / KPp;
    float x = (k < K) ? W[(size_t)k * N + n] : 0.f;
    bf16 h, l; split1(x, h, l);
    th[idx] = h; tl[idx] = l;
}
__global__ void asplit_k(const float* __restrict__ A, bf16* __restrict__ hi,
                         bf16* __restrict__ lo, int K, int KPp) {
    int idx = blockIdx.x * blockDim.x + threadIdx.x;
    int k = idx % KPp, m = idx / KPp;
    float x = (k < K) ? A[(size_t)m * K + k] : 0.f;
    bf16 h, l; split1(x, h, l);
    hi[idx] = h; lo[idx] = l;
}

// ---------------- fp32 GEMM (atom-side small matmuls) ----------------
template <int RELU, int HASBIAS>
__global__ __launch_bounds__(256) void gemm_k(const float* __restrict__ A, const float* __restrict__ B,
                                              const float* __restrict__ bias, float* __restrict__ C,
                                              int Mm, int Nn, int Kk){
    __shared__ float As[16*68];
    __shared__ float Bs[16*68];
    const int tid=threadIdx.x, tm=tid>>4, tn=tid&15;
    const int m0=blockIdx.y*64, n0=blockIdx.x*64;
    float acc[4][4]={};
    for(int k0=0;k0<Kk;k0+=16){
#pragma unroll
        for(int i=0;i<4;i++){int idx=tid+i*256,row=idx>>4,col=idx&15;float v=0.f;
            if(m0+row<Mm&&k0+col<Kk)v=A[(size_t)(m0+row)*Kk+k0+col];As[col*68+row]=v;}
#pragma unroll
        for(int i=0;i<4;i++){int idx=tid+i*256,row=idx>>6,col=idx&63;float v=0.f;
            if(k0+row<Kk&&n0+col<Nn)v=B[(size_t)(k0+row)*Nn+n0+col];Bs[row*68+col]=v;}
        __syncthreads();
#pragma unroll
        for(int kk=0;kk<16;kk++){
            float4 a4=*(const float4*)&As[kk*68+tm*4];
            float4 b4=*(const float4*)&Bs[kk*68+tn*4];
            float av[4]={a4.x,a4.y,a4.z,a4.w},bv[4]={b4.x,b4.y,b4.z,b4.w};
#pragma unroll
            for(int i=0;i<4;i++)
#pragma unroll
                for(int j=0;j<4;j++)acc[i][j]+=av[i]*bv[j];
        }
        __syncthreads();
    }
#pragma unroll
    for(int i=0;i<4;i++){int m=m0+tm*4+i;if(m>=Mm)continue;
#pragma unroll
        for(int j=0;j<4;j++){int n=n0+tn*4+j;if(n>=Nn)continue;
            float v=acc[i][j];if(HASBIAS)v+=bias[n];if(RELU)v=fmaxf(v,0.f);
            C[(size_t)m*Nn+n]=v;}}
}

// ---------------- V transpose + split ----------------
__global__ void vt_split_k(const float* __restrict__ V){
    __shared__ float t[32][33];
    int bx=blockIdx.x, by=blockIdx.y, tx=threadIdx.x, ty=threadIdx.y;
    for(int i=ty;i<32;i+=8) t[i][tx]=V[(size_t)(bx*32+i)*HD+by*32+tx];
    __syncthreads();
    for(int i=ty;i<32;i+=8){
        float x=t[tx][i];
        bf16 h,l; split1(x,h,l);
        size_t o=(size_t)(by*32+i)*NB+bx*32+tx;
        g_Vthi[o]=h; g_Vtlo[o]=l;
    }
}

// ---------------- mma.sync flash attention (ldmatrix fragments) ----------------------
#define FL_BF 104960
#define SQH 0
#define SQL 33792
#define SKH 67584
#define SKL 76032
#define SVH 84480
#define SVL 94720
__global__ __launch_bounds__(256, 1) void flash_mma(){
    extern __shared__ __align__(16) bf16 sm[];
    const int tid = threadIdx.x, wid = tid >> 5, lane = tid & 31;
    const int r = lane >> 2, cq = (lane & 3) * 2;
    const int row0 = blockIdx.x * 128;
    const int half = blockIdx.y;
    const int kb0 = half * (NB / 2);
    const int a_ro = (lane & 7) + ((lane >> 3) & 1) * 8;
    const int a_ch = ((lane >> 4) & 1) * 8;
    const int b_no = (lane & 7) + ((lane >> 4) & 1) * 8;
    const int b_kh = ((lane >> 3) & 1) * 8;

    // exact self-logit per row from hi+lo (Q already scaled 1/16)
    float cs0 = 0.f, cs1 = 0.f;
    {
        int rg = row0 + wid * 16 + r;
        const bf16 *q0h=&g_Qhi[(size_t)rg*HD], *q0l=&g_Qlo[(size_t)rg*HD];
        const bf16 *k0h=&g_Khi[(size_t)rg*HD], *k0l=&g_Klo[(size_t)rg*HD];
        const bf16 *q1h=&g_Qhi[(size_t)(rg+8)*HD], *q1l=&g_Qlo[(size_t)(rg+8)*HD];
        const bf16 *k1h=&g_Khi[(size_t)(rg+8)*HD], *k1l=&g_Klo[(size_t)(rg+8)*HD];
        int f0 = (lane & 3) * 64;
#pragma unroll 16
        for (int f = 0; f < 64; f++) {
            float q0 = __bfloat162float(q0h[f0+f]) + __bfloat162float(q0l[f0+f]);
            float k0 = __bfloat162float(k0h[f0+f]) + __bfloat162float(k0l[f0+f]);
            float q1 = __bfloat162float(q1h[f0+f]) + __bfloat162float(q1l[f0+f]);
            float k1 = __bfloat162float(k1h[f0+f]) + __bfloat162float(k1l[f0+f]);
            cs0 += q0 * k0; cs1 += q1 * k1;
        }
        cs0 += __shfl_xor_sync(0xffffffffu, cs0, 1);
        cs0 += __shfl_xor_sync(0xffffffffu, cs0, 2);
        cs1 += __shfl_xor_sync(0xffffffffu, cs1, 1);
        cs1 += __shfl_xor_sync(0xffffffffu, cs1, 2);
    }

#pragma unroll
    for (int i = 0; i < 16; i++) {
        int idx = tid + i * 256, row = idx >> 5, c8 = (idx & 31) * 8;
        *(uint4*)(sm + SQH + row * 264 + c8) = *(const uint4*)(g_Qhi + (size_t)(row0 + row) * HD + c8);
        *(uint4*)(sm + SQL + row * 264 + c8) = *(const uint4*)(g_Qlo + (size_t)(row0 + row) * HD + c8);
    }

    // ldmatrix base addresses (fixed per thread)
    const uint32_t qh_a = smaddr(sm + SQH + (wid * 16 + a_ro) * 264 + a_ch);
    const uint32_t ql_a = smaddr(sm + SQL + (wid * 16 + a_ro) * 264 + a_ch);
    const uint32_t kh_b = smaddr(sm + SKH + b_no * 264 + b_kh);
    const uint32_t kl_b = smaddr(sm + SKL + b_no * 264 + b_kh);
    const uint32_t vh_b = smaddr(sm + SVH + b_no * 40 + b_kh);
    const uint32_t vl_b = smaddr(sm + SVL + b_no * 40 + b_kh);

    float Oc[32][4];
#pragma unroll
    for (int t = 0; t < 32; t++) { Oc[t][0]=0.f; Oc[t][1]=0.f; Oc[t][2]=0.f; Oc[t][3]=0.f; }
    float l0 = 0.f, l1 = 0.f;

    for (int kt = 0; kt < 128; kt++) {
        const int kb = kb0 + kt * 32;
        __syncthreads();
#pragma unroll
        for (int i = 0; i < 4; i++) {
            int idx = tid + i * 256, row = idx >> 5, c8 = (idx & 31) * 8;
            *(uint4*)(sm + SKH + row * 264 + c8) = *(const uint4*)(g_Khi + (size_t)(kb + row) * HD + c8);
            *(uint4*)(sm + SKL + row * 264 + c8) = *(const uint4*)(g_Klo + (size_t)(kb + row) * HD + c8);
        }
#pragma unroll
        for (int i = 0; i < 4; i++) {
            int idx = tid + i * 256, n = idx >> 2, k8 = (idx & 3) * 8;
            *(uint4*)(sm + SVH + n * 40 + k8) = *(const uint4*)(g_Vthi + (size_t)n * NB + kb + k8);
            *(uint4*)(sm + SVL + n * 40 + k8) = *(const uint4*)(g_Vtlo + (size_t)n * NB + kb + k8);
        }
        __syncthreads();

        // ---- S = Q K^T (3 hi/lo combos) ----
        float Sc[4][4];
#pragma unroll
        for (int t = 0; t < 4; t++) { Sc[t][0]=0.f; Sc[t][1]=0.f; Sc[t][2]=0.f; Sc[t][3]=0.f; }
#pragma unroll
        for (int ks = 0; ks < 16; ks++) {
            uint32_t aH[4], aL[4];
            ldsm4(aH, qh_a + ks * 32);
            ldsm4(aL, ql_a + ks * 32);
#pragma unroll
            for (int tp = 0; tp < 2; tp++) {
                uint32_t bH[4], bL[4];
                ldsm4(bH, kh_b + tp * 8448 + ks * 32);
                ldsm4(bL, kl_b + tp * 8448 + ks * 32);
                mma_bf16(Sc[tp*2], aH[0], aH[1], aH[2], aH[3], bH[0], bH[1]);
                mma_bf16(Sc[tp*2], aH[0], aH[1], aH[2], aH[3], bL[0], bL[1]);
                mma_bf16(Sc[tp*2], aL[0], aL[1], aL[2], aL[3], bH[0], bH[1]);
                mma_bf16(Sc[tp*2+1], aH[0], aH[1], aH[2], aH[3], bH[2], bH[3]);
                mma_bf16(Sc[tp*2+1], aH[0], aH[1], aH[2], aH[3], bL[2], bL[3]);
                mma_bf16(Sc[tp*2+1], aL[0], aL[1], aL[2], aL[3], bH[2], bH[3]);
            }
        }
        // ---- softmax + P fragments ----
        uint32_t pH[2][4], pL[2][4];
        float rs0 = 0.f, rs1 = 0.f;
#pragma unroll
        for (int t = 0; t < 4; t++) {
            float e0 = __expf(Sc[t][0] - cs0);
            float e1 = __expf(Sc[t][1] - cs0);
            float e2 = __expf(Sc[t][2] - cs1);
            float e3 = __expf(Sc[t][3] - cs1);
            rs0 += e0 + e1; rs1 += e2 + e3;
            bf16 h0=__float2bfloat16(e0), h1=__float2bfloat16(e1);
            bf16 h2=__float2bfloat16(e2), h3=__float2bfloat16(e3);
            float q0=e0-__bfloat162float(h0), q1=e1-__bfloat162float(h1);
            float q2=e2-__bfloat162float(h2), q3=e3-__bfloat162float(h3);
            int ksp = t >> 1, hi2 = (t & 1) * 2;
            pH[ksp][hi2]     = ((uint32_t)__bfloat16_as_ushort(h1) << 16) | (uint32_t)__bfloat16_as_ushort(h0);
            pH[ksp][hi2 + 1] = ((uint32_t)__bfloat16_as_ushort(h3) << 16) | (uint32_t)__bfloat16_as_ushort(h2);
            pL[ksp][hi2]     = packbf(q0, q1);
            pL[ksp][hi2 + 1] = packbf(q2, q3);
        }
        rs0 += __shfl_xor_sync(0xffffffffu, rs0, 1);
        rs0 += __shfl_xor_sync(0xffffffffu, rs0, 2);
        rs1 += __shfl_xor_sync(0xffffffffu, rs1, 1);
        rs1 += __shfl_xor_sync(0xffffffffu, rs1, 2);
        l0 += rs0; l1 += rs1;

        // ---- O += P V (3 combos) ----
#pragma unroll
        for (int ks2 = 0; ks2 < 2; ks2++) {
#pragma unroll
            for (int tp = 0; tp < 16; tp++) {
                uint32_t bH[4], bL[4];
                ldsm4(bH, vh_b + tp * 1280 + ks2 * 32);
                ldsm4(bL, vl_b + tp * 1280 + ks2 * 32);
                mma_bf16(Oc[tp*2], pH[ks2][0], pH[ks2][1], pH[ks2][2], pH[ks2][3], bH[0], bH[1]);
                mma_bf16(Oc[tp*2], pH[ks2][0], pH[ks2][1], pH[ks2][2], pH[ks2][3], bL[0], bL[1]);
                mma_bf16(Oc[tp*2], pL[ks2][0], pL[ks2][1], pL[ks2][2], pL[ks2][3], bH[0], bH[1]);
                mma_bf16(Oc[tp*2+1], pH[ks2][0], pH[ks2][1], pH[ks2][2], pH[ks2][3], bH[2], bH[3]);
                mma_bf16(Oc[tp*2+1], pH[ks2][0], pH[ks2][1], pH[ks2][2], pH[ks2][3], bL[2], bL[3]);
                mma_bf16(Oc[tp*2+1], pL[ks2][0], pL[ks2][1], pL[ks2][2], pL[ks2][3], bH[2], bH[3]);
            }
        }
    }
    {
        int rg = row0 + wid * 16 + r;
        float* O = g_Opart + (size_t)half * NB * HD;
#pragma unroll
        for (int t = 0; t < 32; t++) {
            int col = t * 8 + cq;
            O[(size_t)rg * HD + col]       = Oc[t][0];
            O[(size_t)rg * HD + col + 1]   = Oc[t][1];
            O[(size_t)(rg + 8) * HD + col]     = Oc[t][2];
            O[(size_t)(rg + 8) * HD + col + 1] = Oc[t][3];
        }
        if ((lane & 3) == 0) {
            g_lpart[half * NB + rg] = l0;
            g_lpart[half * NB + rg + 8] = l1;
        }
    }
}

__global__ void flash_merge_k(){
    int row = blockIdx.x, c = threadIdx.x;
    float li = 1.f / (g_lpart[row] + g_lpart[NB + row]);
    size_t o = (size_t)row * HD + c;
    float v = (g_Opart[o] + g_Opart[(size_t)NB * HD + o]) * li;
    bf16 h, l; split1(v, h, l);
    g_avhi[o] = h; g_avlo[o] = l;
}

// ---------------- atom self-attn + LN ----------------
#define AT_SMEM_FLOATS (4*64*136+64*64+512+128)
__global__ __launch_bounds__(256,1) void atom_attn_ln_k(const float* __restrict__ xg,
                                                        const float* __restrict__ gw,
                                                        const float* __restrict__ bw){
    extern __shared__ float smf[];
    float* sx=smf; float* sq=sx+64*136; float* sk=sq+64*136; float* sv=sk+64*136;
    float* ss=sv+64*136; float* sred=ss+4096; float* srow=sred+512;
    const int tid=threadIdx.x; const int base=blockIdx.x*64;
    for(int idx=tid;idx<64*FDIM;idx+=256){
        int a=idx/FDIM,f=idx-a*FDIM; size_t go=(size_t)(base+a)*FDIM+f;
        sx[a*136+f]=xg[go]; sq[a*136+f]=g_qa[go]; sk[a*136+f]=g_ka[go]; sv[a*136+f]=g_va[go];
    }
    __syncthreads();
    {
        int ty=tid>>4,tx=tid&15; float acc[4][4]={};
        for(int h=0;h<FDIM;h++){
            float qv[4],kv[4];
#pragma unroll
            for(int i=0;i<4;i++){qv[i]=sq[(ty*4+i)*136+h];kv[i]=sk[(tx*4+i)*136+h];}
#pragma unroll
            for(int i=0;i<4;i++)
#pragma unroll
                for(int j=0;j<4;j++)acc[i][j]+=qv[i]*kv[j];
        }
        float scl=rsqrtf(133.0f);
#pragma unroll
        for(int i=0;i<4;i++)
#pragma unroll
            for(int j=0;j<4;j++)ss[(ty*4+i)*64+tx*4+j]=acc[i][j]*scl;
    }
    __syncthreads();
    if(tid<64){
        float mx=-1e30f;
        for(int j=0;j<64;j++)mx=fmaxf(mx,ss[tid*64+j]);
        float s=0.f;
        for(int j=0;j<64;j++){float e=__expf(ss[tid*64+j]-mx);ss[tid*64+j]=e;s+=e;}
        float inv=1.f/s;
        for(int j=0;j<64;j++)ss[tid*64+j]*=inv;
    }
    __syncthreads();
    const int r=tid>>2,qd=tid&3,f0=qd*34;
    float tv[34];
#pragma unroll
    for(int f=0;f<34;f++)tv[f]=0.f;
    for(int b=0;b<64;b++){
        float p=ss[r*64+b]; const float* vb=&sv[b*136+f0];
#pragma unroll
        for(int f=0;f<34;f++)if(f0+f<FDIM)tv[f]+=p*vb[f];
    }
    float s1=0.f;
#pragma unroll
    for(int f=0;f<34;f++)if(f0+f<FDIM){tv[f]+=sx[r*136+f0+f];s1+=tv[f];}
    sred[tid]=s1; __syncthreads();
    if(qd==0)srow[r]=(sred[tid]+sred[tid+1]+sred[tid+2]+sred[tid+3])*(1.f/133.f);
    __syncthreads();
    float mu=srow[r],s2=0.f;
#pragma unroll
    for(int f=0;f<34;f++)if(f0+f<FDIM){float d=tv[f]-mu;s2+=d*d;}
    sred[tid]=s2; __syncthreads();
    if(qd==0){float var=(sred[tid]+sred[tid+1]+sred[tid+2]+sred[tid+3])*(1.f/133.f);srow[64+r]=rsqrtf(var+1e-5f);}
    __syncthreads();
    float rstd=srow[64+r];
#pragma unroll
    for(int f=0;f<34;f++){int fg=f0+f;
        if(fg<FDIM)g_fe[(size_t)(base+r)*FDIM+fg]=(tv[f]-mu)*rstd*gw[fg]+bw[fg];}
}

// ---------------- elementwise / gather ----------------
__global__ void gather_sum_k(const int* __restrict__ a2b){
    __shared__ int idx[MAXNB];
    int a=blockIdx.x,t=threadIdx.x;
    if(t<MAXNB)idx[t]=a2b[a*MAXNB+t];
    __syncthreads();
    float s=0.f;
#pragma unroll
    for(int j=0;j<MAXNB;j++)s+=g_msg[(size_t)idx[j]*HD+t];
    g_amsg[(size_t)a*HD+t]=s;
}
__global__ void dmpnn_pre_k(const int* __restrict__ b2a, const int* __restrict__ b2revb){
    int b=blockIdx.x,t=threadIdx.x;
    int ia=__ldg(&b2a[b]),ir=__ldg(&b2revb[b]);
    float v=g_amsg[(size_t)ia*HD+t]-g_msg[(size_t)ir*HD+t];
    bf16 h,l; split1(v,h,l);
    size_t o=(size_t)b*HD+t;
    g_tmphi[o]=h; g_tmplo[o]=l;
}
__global__ void combine_k(const float* __restrict__ wal, const float* __restrict__ walb){
    __shared__ float red[256];
    __shared__ float salpha;
    int b=blockIdx.x,t=threadIdx.x;
    size_t o=(size_t)b*HD+t;
    float d=g_dmpnn[o],am=g_attm[o];
    red[t]=d*wal[t]+am*wal[256+t];
    __syncthreads();
    for(int s=128;s>0;s>>=1){if(t<s)red[t]+=red[t+s];__syncthreads();}
    if(t==0)salpha=1.f/(1.f+__expf(-(red[0]+walb[0])));
    __syncthreads();
    float al=salpha;
    float v=fmaxf(g_inputs[o]+al*d+(1.f-al)*am,0.f);
    g_msg[o]=v;
    bf16 h,l; split1(v,h,l);
    g_msghi[o]=h; g_msglo[o]=l;
}
__global__ void concat_split_k(){
    int i=blockIdx.x*blockDim.x+threadIdx.x;
    if(i>=NA*KP_WO)return;
    int row=i/KP_WO,c=i-row*KP_WO;
    float x = (c<FDIM) ? g_fe[(size_t)row*FDIM+c]
             : (c<FDIM+HD ? g_amsg[(size_t)row*HD+(c-FDIM)] : 0.f);
    bf16 h,l; split1(x,h,l);
    g_cathi[i]=h; g_catlo[i]=l;
}

// ---------------- molecule pooling ----------------
#define MP_SMEM_FLOATS (2*64*260+4096)
__global__ __launch_bounds__(256,1) void mol_pool_k(const float* __restrict__ Wb,
                                                    const float* __restrict__ bb,
                                                    float* __restrict__ outg){
    extern __shared__ float smf[];
    float* shm=smf; float* sw=shm+64*260; float* ssc=sw+64*260;
    const int tid=threadIdx.x; const int base=blockIdx.x*64;
    for(int idx=tid;idx<64*HD;idx+=256){
        int a=idx>>8,c=idx&255;
        shm[a*260+c]=g_atomh[(size_t)(base+a)*HD+c];
        sw[a*260+c]=g_hmwa[(size_t)(base+a)*HD+c];
    }
    __syncthreads();
    {
        int ty=tid>>4,tx=tid&15; float acc[4][4]={};
        for(int h=0;h<HD;h++){
            float qv[4],kv[4];
#pragma unroll
            for(int i=0;i<4;i++){qv[i]=sw[(ty*4+i)*260+h];kv[i]=shm[(tx*4+i)*260+h];}
#pragma unroll
            for(int i=0;i<4;i++)
#pragma unroll
                for(int j=0;j<4;j++)acc[i][j]+=qv[i]*kv[j];
        }
#pragma unroll
        for(int i=0;i<4;i++)
#pragma unroll
            for(int j=0;j<4;j++)ssc[(ty*4+i)*64+tx*4+j]=acc[i][j];
    }
    __syncthreads();
    if(tid<64){
        float mx=-1e30f;
        for(int j=0;j<64;j++)mx=fmaxf(mx,ssc[tid*64+j]);
        float s=0.f;
        for(int j=0;j<64;j++){float e=__expf(ssc[tid*64+j]-mx);ssc[tid*64+j]=e;s+=e;}
        float inv=1.f/s;
        for(int j=0;j<64;j++)ssc[tid*64+j]*=inv;
    }
    __syncthreads();
    const int c=tid;
    float acc[64];
#pragma unroll
    for(int a=0;a<64;a++)acc[a]=0.f;
    for(int b=0;b<64;b++){
        float hv=shm[b*260+c];
#pragma unroll 16
        for(int a=0;a<64;a++)acc[a]+=ssc[a*64+b]*hv;
    }
    __syncthreads();
    for(int a=0;a<64;a++)sw[a*260+c]=acc[a];
    __syncthreads();
#pragma unroll
    for(int a=0;a<64;a++)acc[a]=0.f;
    for(int k=0;k<HD;k++){
        float wv=Wb[(size_t)k*HD+c];
#pragma unroll 16
        for(int a=0;a<64;a++)acc[a]+=sw[a*260+k]*wv;
    }
    float bv=bb[c],s=0.f;
    for(int a=0;a<64;a++){
        float t=fmaxf(acc[a]+bv,0.f);
        s+=shm[a*260+c]+t;
    }
    outg[(size_t)blockIdx.x*HD+c]=s*(1.f/64.f);
}

// ---------------- host driver ----------------
static float* symf(const void* s){ void* p=nullptr; cudaGetSymbolAddress(&p,s); return (float*)p; }
static bf16* symb(const void* s){ void* p=nullptr; cudaGetSymbolAddress(&p,s); return (bf16*)p; }

extern "C" void kernel_launch(void* const* d_in, const int* in_sizes, int n_in,
                              void* d_out, int out_size){
    const float* f_atoms=(const float*)d_in[0];
    const float* f_bonds=(const float*)d_in[1];
    const float* Wq_atom=(const float*)d_in[2];
    const float* Wk_atom=(const float*)d_in[3];
    const float* Wv_atom=(const float*)d_in[4];
    const float* ln_g=(const float*)d_in[5];
    const float* ln_b=(const float*)d_in[6];
    const float* Wi=(const float*)d_in[7];
    const float* Wh=(const float*)d_in[8];
    const float* Wq=(const float*)d_in[9];
    const float* Wk=(const float*)d_in[10];
    const float* Wv=(const float*)d_in[11];
    const float* Wa=(const float*)d_in[12];
    const float* Walw=(const float*)d_in[13];
    const float* Walb=(const float*)d_in[14];
    const float* Wow=(const float*)d_in[15];
    const float* Wob=(const float*)d_in[16];
    const float* Wbw=(const float*)d_in[17];
    const float* Wbb=(const float*)d_in[18];
    const int* a2b=(const int*)d_in[19];
    const int* b2a=(const int*)d_in[20];
    const int* b2revb=(const int*)d_in[21];
    float* out=(float*)d_out;

    float* p_qa=symf(g_qa); float* p_ka=symf(g_ka); float* p_va=symf(g_va);
    float* p_inputs=symf(g_inputs); float* p_msg=symf(g_msg);
    float* p_dmpnn=symf(g_dmpnn); float* p_V=symf(g_V); float* p_attm=symf(g_attm);
    float* p_atomh=symf(g_atomh); float* p_hmwa=symf(g_hmwa);
    bf16* p_Qhi=symb(g_Qhi); bf16* p_Qlo=symb(g_Qlo);
    bf16* p_Khi=symb(g_Khi); bf16* p_Klo=symb(g_Klo);
    bf16* p_msghi=symb(g_msghi); bf16* p_msglo=symb(g_msglo);
    bf16* p_tmphi=symb(g_tmphi); bf16* p_tmplo=symb(g_tmplo);
    bf16* p_avhi=symb(g_avhi); bf16* p_avlo=symb(g_avlo);
    bf16* p_fbhi=symb(g_fbhi); bf16* p_fblo=symb(g_fblo);
    bf16* p_cathi=symb(g_cathi); bf16* p_catlo=symb(g_catlo);
    bf16* p_ahhi=symb(g_ahhi); bf16* p_ahlo=symb(g_ahlo);
    bf16* p_Withi=symb(g_Withi); bf16* p_Witlo=symb(g_Witlo);
    bf16* p_Whthi=symb(g_Whthi); bf16* p_Whtlo=symb(g_Whtlo);
    bf16* p_Wqthi=symb(g_Wqthi); bf16* p_Wqtlo=symb(g_Wqtlo);
    bf16* p_Wkthi=symb(g_Wkthi); bf16* p_Wktlo=symb(g_Wktlo);
    bf16* p_Wvthi=symb(g_Wvthi); bf16* p_Wvtlo=symb(g_Wvtlo);
    bf16* p_Wathi=symb(g_Wathi); bf16* p_Watlo=symb(g_Watlo);
    bf16* p_Wothi=symb(g_Wothi); bf16* p_Wotlo=symb(g_Wotlo);

    const int AT_SMEM=AT_SMEM_FLOATS*4, MP_SMEM=MP_SMEM_FLOATS*4;
    const int FL_SMEM=FL_BF*2;
    cudaFuncSetAttribute(flash_mma,cudaFuncAttributeMaxDynamicSharedMemorySize,FL_SMEM);
    cudaFuncSetAttribute(atom_attn_ln_k,cudaFuncAttributeMaxDynamicSharedMemorySize,AT_SMEM);
    cudaFuncSetAttribute(mol_pool_k,cudaFuncAttributeMaxDynamicSharedMemorySize,MP_SMEM);

    wsplit_k<<<(HD*KP_WI+255)/256,256>>>(Wi,p_Withi,p_Witlo,BFDIM,HD,KP_WI);
    wsplit_k<<<(HD*HD+255)/256,256>>>(Wh,p_Whthi,p_Whtlo,HD,HD,HD);
    wsplit_k<<<(HD*HD+255)/256,256>>>(Wq,p_Wqthi,p_Wqtlo,HD,HD,HD);
    wsplit_k<<<(HD*HD+255)/256,256>>>(Wk,p_Wkthi,p_Wktlo,HD,HD,HD);
    wsplit_k<<<(HD*HD+255)/256,256>>>(Wv,p_Wvthi,p_Wvtlo,HD,HD,HD);
    wsplit_k<<<(HD*HD+255)/256,256>>>(Wa,p_Wathi,p_Watlo,HD,HD,HD);
    wsplit_k<<<(HD*KP_WO+255)/256,256>>>(Wow,p_Wothi,p_Wotlo,FDIM+HD,HD,KP_WO);
    asplit_k<<<(NB*KP_WI)/256,256>>>(f_bonds,p_fbhi,p_fblo,BFDIM,KP_WI);

    dim3 gqa((FDIM+63)/64,(NA+63)/64);
    gemm_k<0,0><<<gqa,256>>>(f_atoms,Wq_atom,nullptr,p_qa,NA,FDIM,FDIM);
    gemm_k<0,0><<<gqa,256>>>(f_atoms,Wk_atom,nullptr,p_ka,NA,FDIM,FDIM);
    gemm_k<0,0><<<gqa,256>>>(f_atoms,Wv_atom,nullptr,p_va,NA,FDIM,FDIM);
    atom_attn_ln_k<<<NMOL,256,AT_SMEM>>>(f_atoms,ln_g,ln_b);

    dim3 tgb(4,NB/128), tga(4,NA/128);
    tgemm<1,0,0,1,1,1><<<tgb,256>>>(p_fbhi,p_fblo,p_Withi,p_Witlo,nullptr,
                                    p_msg,p_msghi,p_msglo,p_inputs,NB,KP_WI);

    dim3 vtg(NB/32,HD/32), vtb(32,8);
    for(int it=0;it<3;it++){
        gather_sum_k<<<NA,256>>>(a2b);
        dmpnn_pre_k<<<NB,256>>>(b2a,b2revb);
        tgemm<0,0,0,1,0,0><<<tgb,256>>>(p_tmphi,p_tmplo,p_Whthi,p_Whtlo,nullptr,
                                        p_dmpnn,nullptr,nullptr,nullptr,NB,HD);
        tgemm<0,0,1,0,1,0><<<tgb,256>>>(p_msghi,p_msglo,p_Wqthi,p_Wqtlo,nullptr,
                                        nullptr,p_Qhi,p_Qlo,nullptr,NB,HD);
        tgemm<0,0,0,0,1,0><<<tgb,256>>>(p_msghi,p_msglo,p_Wkthi,p_Wktlo,nullptr,
                                        nullptr,p_Khi,p_Klo,nullptr,NB,HD);
        tgemm<0,0,0,1,0,0><<<tgb,256>>>(p_msghi,p_msglo,p_Wvthi,p_Wvtlo,nullptr,
                                        p_V,nullptr,nullptr,nullptr,NB,HD);
        vt_split_k<<<vtg,vtb>>>(p_V);
        flash_mma<<<dim3(NB/128,2),256,FL_SMEM>>>();
        flash_merge_k<<<NB,256>>>();
        tgemm<0,0,0,1,0,0><<<tgb,256>>>(p_avhi,p_avlo,p_Wathi,p_Watlo,nullptr,
                                        p_attm,nullptr,nullptr,nullptr,NB,HD);
        combine_k<<<NB,256>>>(Walw,Walb);
    }

    gather_sum_k<<<NA,256>>>(a2b);
    concat_split_k<<<(NA*KP_WO+255)/256,256>>>();
    tgemm<1,1,0,1,1,0><<<tga,256>>>(p_cathi,p_catlo,p_Wothi,p_Wotlo,Wob,
                                    p_atomh,p_ahhi,p_ahlo,nullptr,NA,KP_WO);
    tgemm<0,0,0,1,0,0><<<tga,256>>>(p_ahhi,p_ahlo,p_Wathi,p_Watlo,nullptr,
                                    p_hmwa,nullptr,nullptr,nullptr,NA,HD);
    mol_pool_k<<<NMOL,256,MP_SMEM>>>(Wbw,Wbb,out);
}

// round 7
// speedup vs baseline: 12.5391x; 1.1228x over previous
#include <cuda_runtime.h>
#include <cuda_bf16.h>
#include <cuda_fp16.h>
#include <math.h>
#include <stdint.h>

#define NA 4096
#define NB 8192
#define FDIM 133
#define BFDIM 147
#define HD 256
#define NMOL 64
#define MAXNB 6
#define KP_WI 160
#define KP_WO 416
#define LOSCL 2048.0f
#define INVLO (1.0f/2048.0f)

typedef __nv_bfloat16 bf16;
typedef __half f16;

// ---------------- device scratch ----------------
__device__ __align__(16) float g_qa[NA*FDIM];
__device__ __align__(16) float g_ka[NA*FDIM];
__device__ __align__(16) float g_va[NA*FDIM];
__device__ __align__(16) float g_fe[NA*FDIM];
__device__ __align__(16) float g_inputs[NB*HD];
__device__ __align__(16) float g_msg[NB*HD];
__device__ __align__(16) float g_amsg[NA*HD];
__device__ __align__(16) float g_dmpnn[NB*HD];
__device__ __align__(16) float g_V[NB*HD];
__device__ __align__(16) float g_attm[NB*HD];
__device__ __align__(16) float g_atomh[NA*HD];
__device__ __align__(16) float g_hmwa[NA*HD];
__device__ __align__(16) float g_Opart[2*NB*HD];
__device__ __align__(16) float g_lpart[2*NB];

__device__ __align__(16) f16 g_Qhi[NB*HD];
__device__ __align__(16) f16 g_Qlo[NB*HD];
__device__ __align__(16) f16 g_Khi[NB*HD];
__device__ __align__(16) f16 g_Klo[NB*HD];
__device__ __align__(16) bf16 g_Vthi[HD*NB];
__device__ __align__(16) bf16 g_Vtlo[HD*NB];
__device__ __align__(16) f16 g_msghi[NB*HD];
__device__ __align__(16) f16 g_msglo[NB*HD];
__device__ __align__(16) f16 g_tmphi[NB*HD];
__device__ __align__(16) f16 g_tmplo[NB*HD];
__device__ __align__(16) f16 g_avhi[NB*HD];
__device__ __align__(16) f16 g_avlo[NB*HD];
__device__ __align__(16) f16 g_fbhi[NB*KP_WI];
__device__ __align__(16) f16 g_fblo[NB*KP_WI];
__device__ __align__(16) f16 g_cathi[NA*KP_WO];
__device__ __align__(16) f16 g_catlo[NA*KP_WO];
__device__ __align__(16) f16 g_ahhi[NA*HD];
__device__ __align__(16) f16 g_ahlo[NA*HD];
// fp16 transposed weights [N][KP] (single precision copy; A-side lo corrects)
__device__ __align__(16) f16 g_Wit[HD*KP_WI];
__device__ __align__(16) f16 g_Wht[HD*HD];
__device__ __align__(16) f16 g_Wqt[HD*HD];
__device__ __align__(16) f16 g_Wkt[HD*HD];
__device__ __align__(16) f16 g_Wvt[HD*HD];
__device__ __align__(16) f16 g_Wat[HD*HD];
__device__ __align__(16) f16 g_Wot[HD*KP_WO];

// ---------------- mma / ldmatrix helpers ----------------
__device__ __forceinline__ void mma_bf16(float* c, uint32_t a0, uint32_t a1, uint32_t a2,
                                         uint32_t a3, uint32_t b0, uint32_t b1) {
    asm("mma.sync.aligned.m16n8k16.row.col.f32.bf16.bf16.f32 "
        "{%0,%1,%2,%3}, {%4,%5,%6,%7}, {%8,%9}, {%0,%1,%2,%3};\n"
        : "+f"(c[0]), "+f"(c[1]), "+f"(c[2]), "+f"(c[3])
        : "r"(a0), "r"(a1), "r"(a2), "r"(a3), "r"(b0), "r"(b1));
}
__device__ __forceinline__ void mma_f16(float* c, uint32_t a0, uint32_t a1, uint32_t a2,
                                        uint32_t a3, uint32_t b0, uint32_t b1) {
    asm("mma.sync.aligned.m16n8k16.row.col.f32.f16.f16.f32 "
        "{%0,%1,%2,%3}, {%4,%5,%6,%7}, {%8,%9}, {%0,%1,%2,%3};\n"
        : "+f"(c[0]), "+f"(c[1]), "+f"(c[2]), "+f"(c[3])
        : "r"(a0), "r"(a1), "r"(a2), "r"(a3), "r"(b0), "r"(b1));
}
__device__ __forceinline__ uint32_t smaddr(const void* p) {
    return (uint32_t)__cvta_generic_to_shared(p);
}
__device__ __forceinline__ void ldsm4(uint32_t* r, uint32_t a) {
    asm volatile("ldmatrix.sync.aligned.m8n8.x4.shared.b16 {%0,%1,%2,%3}, [%4];"
                 : "=r"(r[0]), "=r"(r[1]), "=r"(r[2]), "=r"(r[3]) : "r"(a));
}
__device__ __forceinline__ uint32_t packbf(float x, float y) {
    bf16 h0 = __float2bfloat16(x), h1 = __float2bfloat16(y);
    return ((uint32_t)__bfloat16_as_ushort(h1) << 16) | (uint32_t)__bfloat16_as_ushort(h0);
}
__device__ __forceinline__ void split1(float x, bf16& h, bf16& l) {
    h = __float2bfloat16(x);
    l = __float2bfloat16(x - __bfloat162float(h));
}
__device__ __forceinline__ void splith(float x, f16& h, f16& l) {
    h = __float2half(x);
    l = __float2half((x - __half2float(h)) * LOSCL);
}
__device__ __forceinline__ uint32_t packh(f16 a, f16 b) {
    return ((uint32_t)__half_as_ushort(b) << 16) | (uint32_t)__half_as_ushort(a);
}

// ---------------- fp16 hi/lo tensor GEMM (2 combos, scaled-lo accumulator) -----------
template <int RELU, int HASBIAS, int SCALEQ, int OUTF32, int OUTSPLIT, int PREAUX>
__global__ __launch_bounds__(256) void tgemm(
    const f16* __restrict__ Ah, const f16* __restrict__ Al,
    const f16* __restrict__ Bh, const float* __restrict__ bias,
    float* __restrict__ Cf, f16* __restrict__ Chi, f16* __restrict__ Clo,
    float* __restrict__ Caux, int M, int K) {
    __shared__ __align__(16) f16 sAh[128*40], sAl[128*40], sB[64*40];
    const int tid = threadIdx.x, wid = tid >> 5, lane = tid & 31;
    const int r = lane >> 2, cq = (lane & 3) * 2;
    const int wm = wid >> 1, wn = wid & 1;
    const int m0 = blockIdx.y * 128, n0 = blockIdx.x * 64;
    const int a_ro = (lane & 7) + ((lane >> 3) & 1) * 8;
    const int a_ch = ((lane >> 4) & 1) * 8;
    const int b_no = (lane & 7) + ((lane >> 4) & 1) * 8;
    const int b_kh = ((lane >> 3) & 1) * 8;
    float acc[2][4][4] = {};
    float acL[2][4][4] = {};
    for (int kc = 0; kc < K; kc += 32) {
        __syncthreads();
#pragma unroll
        for (int i = 0; i < 2; i++) {
            int idx = tid + i * 256, row = idx >> 2, q8 = (idx & 3) * 8;
            *(uint4*)(sAh + row * 40 + q8) = *(const uint4*)(Ah + (size_t)(m0 + row) * K + kc + q8);
            *(uint4*)(sAl + row * 40 + q8) = *(const uint4*)(Al + (size_t)(m0 + row) * K + kc + q8);
        }
        {
            int row = tid >> 2, q8 = (tid & 3) * 8;
            *(uint4*)(sB + row * 40 + q8) = *(const uint4*)(Bh + (size_t)(n0 + row) * K + kc + q8);
        }
        __syncthreads();
        uint32_t aHb[2], aLb[2], bHb;
        aHb[0] = smaddr(sAh + (wm * 32 + a_ro) * 40 + a_ch);
        aHb[1] = smaddr(sAh + (wm * 32 + 16 + a_ro) * 40 + a_ch);
        aLb[0] = smaddr(sAl + (wm * 32 + a_ro) * 40 + a_ch);
        aLb[1] = smaddr(sAl + (wm * 32 + 16 + a_ro) * 40 + a_ch);
        bHb = smaddr(sB + (wn * 32 + b_no) * 40 + b_kh);
#pragma unroll
        for (int ks = 0; ks < 2; ks++) {
            uint32_t aH[2][4], aL[2][4];
#pragma unroll
            for (int mf = 0; mf < 2; mf++) {
                ldsm4(aH[mf], aHb[mf] + ks * 32);
                ldsm4(aL[mf], aLb[mf] + ks * 32);
            }
#pragma unroll
            for (int np = 0; np < 2; np++) {
                uint32_t bH[4];
                ldsm4(bH, bHb + np * 1280 + ks * 32);
#pragma unroll
                for (int mf = 0; mf < 2; mf++) {
                    mma_f16(acc[mf][np*2], aH[mf][0], aH[mf][1], aH[mf][2], aH[mf][3], bH[0], bH[1]);
                    mma_f16(acL[mf][np*2], aL[mf][0], aL[mf][1], aL[mf][2], aL[mf][3], bH[0], bH[1]);
                    mma_f16(acc[mf][np*2+1], aH[mf][0], aH[mf][1], aH[mf][2], aH[mf][3], bH[2], bH[3]);
                    mma_f16(acL[mf][np*2+1], aL[mf][0], aL[mf][1], aL[mf][2], aL[mf][3], bH[2], bH[3]);
                }
            }
        }
    }
#pragma unroll
    for (int mf = 0; mf < 2; mf++) {
#pragma unroll
        for (int nf = 0; nf < 4; nf++) {
            int mrow = m0 + wm * 32 + mf * 16 + r;
            int col = n0 + wn * 32 + nf * 8 + cq;
            float c0 = acc[mf][nf][0] + acL[mf][nf][0] * INVLO;
            float c1 = acc[mf][nf][1] + acL[mf][nf][1] * INVLO;
            float c2 = acc[mf][nf][2] + acL[mf][nf][2] * INVLO;
            float c3 = acc[mf][nf][3] + acL[mf][nf][3] * INVLO;
            if (HASBIAS) { float b0 = bias[col], b1 = bias[col + 1]; c0 += b0; c1 += b1; c2 += b0; c3 += b1; }
            if (SCALEQ) { c0 *= 0.0625f; c1 *= 0.0625f; c2 *= 0.0625f; c3 *= 0.0625f; }
            if (PREAUX) {
                Caux[(size_t)mrow * HD + col] = c0; Caux[(size_t)mrow * HD + col + 1] = c1;
                Caux[(size_t)(mrow + 8) * HD + col] = c2; Caux[(size_t)(mrow + 8) * HD + col + 1] = c3;
            }
            if (RELU) { c0 = fmaxf(c0, 0.f); c1 = fmaxf(c1, 0.f); c2 = fmaxf(c2, 0.f); c3 = fmaxf(c3, 0.f); }
            if (OUTF32) {
                Cf[(size_t)mrow * HD + col] = c0; Cf[(size_t)mrow * HD + col + 1] = c1;
                Cf[(size_t)(mrow + 8) * HD + col] = c2; Cf[(size_t)(mrow + 8) * HD + col + 1] = c3;
            }
            if (OUTSPLIT) {
                f16 h0, l0b, h1, l1b, h2, l2b, h3, l3b;
                splith(c0, h0, l0b); splith(c1, h1, l1b); splith(c2, h2, l2b); splith(c3, h3, l3b);
                *(uint32_t*)(Chi + (size_t)mrow * HD + col) = packh(h0, h1);
                *(uint32_t*)(Clo + (size_t)mrow * HD + col) = packh(l0b, l1b);
                *(uint32_t*)(Chi + (size_t)(mrow + 8) * HD + col) = packh(h2, h3);
                *(uint32_t*)(Clo + (size_t)(mrow + 8) * HD + col) = packh(l2b, l3b);
            }
        }
    }
}

// ---------------- weight / activation splits ----------------
__global__ void wsplit_k(const float* __restrict__ W, f16* __restrict__ th,
                         int K, int N, int KPp) {
    int idx = blockIdx.x * blockDim.x + threadIdx.x;
    if (idx >= N * KPp) return;
    int k = idx % KPp, n = idx / KPp;
    float x = (k < K) ? W[(size_t)k * N + n] : 0.f;
    th[idx] = __float2half(x);
}
__global__ void asplit_k(const float* __restrict__ A, f16* __restrict__ hi,
                         f16* __restrict__ lo, int K, int KPp) {
    int idx = blockIdx.x * blockDim.x + threadIdx.x;
    int k = idx % KPp, m = idx / KPp;
    float x = (k < K) ? A[(size_t)m * K + k] : 0.f;
    f16 h, l; splith(x, h, l);
    hi[idx] = h; lo[idx] = l;
}

// ---------------- fp32 GEMM (atom-side small matmuls) ----------------
template <int RELU, int HASBIAS>
__global__ __launch_bounds__(256) void gemm_k(const float* __restrict__ A, const float* __restrict__ B,
                                              const float* __restrict__ bias, float* __restrict__ C,
                                              int Mm, int Nn, int Kk){
    __shared__ float As[16*68];
    __shared__ float Bs[16*68];
    const int tid=threadIdx.x, tm=tid>>4, tn=tid&15;
    const int m0=blockIdx.y*64, n0=blockIdx.x*64;
    float acc[4][4]={};
    for(int k0=0;k0<Kk;k0+=16){
#pragma unroll
        for(int i=0;i<4;i++){int idx=tid+i*256,row=idx>>4,col=idx&15;float v=0.f;
            if(m0+row<Mm&&k0+col<Kk)v=A[(size_t)(m0+row)*Kk+k0+col];As[col*68+row]=v;}
#pragma unroll
        for(int i=0;i<4;i++){int idx=tid+i*256,row=idx>>6,col=idx&63;float v=0.f;
            if(k0+row<Kk&&n0+col<Nn)v=B[(size_t)(k0+row)*Nn+n0+col];Bs[row*68+col]=v;}
        __syncthreads();
#pragma unroll
        for(int kk=0;kk<16;kk++){
            float4 a4=*(const float4*)&As[kk*68+tm*4];
            float4 b4=*(const float4*)&Bs[kk*68+tn*4];
            float av[4]={a4.x,a4.y,a4.z,a4.w},bv[4]={b4.x,b4.y,b4.z,b4.w};
#pragma unroll
            for(int i=0;i<4;i++)
#pragma unroll
                for(int j=0;j<4;j++)acc[i][j]+=av[i]*bv[j];
        }
        __syncthreads();
    }
#pragma unroll
    for(int i=0;i<4;i++){int m=m0+tm*4+i;if(m>=Mm)continue;
#pragma unroll
        for(int j=0;j<4;j++){int n=n0+tn*4+j;if(n>=Nn)continue;
            float v=acc[i][j];if(HASBIAS)v+=bias[n];if(RELU)v=fmaxf(v,0.f);
            C[(size_t)m*Nn+n]=v;}}
}

// ---------------- V transpose + split (bf16) ----------------
__global__ void vt_split_k(const float* __restrict__ V){
    __shared__ float t[32][33];
    int bx=blockIdx.x, by=blockIdx.y, tx=threadIdx.x, ty=threadIdx.y;
    for(int i=ty;i<32;i+=8) t[i][tx]=V[(size_t)(bx*32+i)*HD+by*32+tx];
    __syncthreads();
    for(int i=ty;i<32;i+=8){
        float x=t[tx][i];
        bf16 h,l; split1(x,h,l);
        size_t o=(size_t)(by*32+i)*NB+bx*32+tx;
        g_Vthi[o]=h; g_Vtlo[o]=l;
    }
}

// ---------------- flash attention: fp16 2-combo S, bf16 3-combo O --------------------
// smem byte offsets
#define SQH 0
#define SQL 67584
#define SKH 135168
#define SVH 152064
#define SVL 172544
#define FL_SMEM 193024
__global__ __launch_bounds__(256, 1) void flash_mma(){
    extern __shared__ __align__(16) char smem[];
    f16*  sQH = (f16*)(smem + SQH);
    f16*  sQL = (f16*)(smem + SQL);
    f16*  sKH = (f16*)(smem + SKH);
    bf16* sVH = (bf16*)(smem + SVH);
    bf16* sVL = (bf16*)(smem + SVL);
    const int tid = threadIdx.x, wid = tid >> 5, lane = tid & 31;
    const int r = lane >> 2, cq = (lane & 3) * 2;
    const int row0 = blockIdx.x * 128;
    const int half = blockIdx.y;
    const int kb0 = half * (NB / 2);
    const int a_ro = (lane & 7) + ((lane >> 3) & 1) * 8;
    const int a_ch = ((lane >> 4) & 1) * 8;
    const int b_no = (lane & 7) + ((lane >> 4) & 1) * 8;
    const int b_kh = ((lane >> 3) & 1) * 8;

    // exact self-logit per row (Q already scaled 1/16)
    float cs0 = 0.f, cs1 = 0.f;
    {
        int rg = row0 + wid * 16 + r;
        const f16 *q0h=&g_Qhi[(size_t)rg*HD], *q0l=&g_Qlo[(size_t)rg*HD];
        const f16 *k0h=&g_Khi[(size_t)rg*HD], *k0l=&g_Klo[(size_t)rg*HD];
        const f16 *q1h=&g_Qhi[(size_t)(rg+8)*HD], *q1l=&g_Qlo[(size_t)(rg+8)*HD];
        const f16 *k1h=&g_Khi[(size_t)(rg+8)*HD], *k1l=&g_Klo[(size_t)(rg+8)*HD];
        int f0 = (lane & 3) * 64;
#pragma unroll 16
        for (int f = 0; f < 64; f++) {
            float q0 = __half2float(q0h[f0+f]) + __half2float(q0l[f0+f]) * INVLO;
            float k0 = __half2float(k0h[f0+f]) + __half2float(k0l[f0+f]) * INVLO;
            float q1 = __half2float(q1h[f0+f]) + __half2float(q1l[f0+f]) * INVLO;
            float k1 = __half2float(k1h[f0+f]) + __half2float(k1l[f0+f]) * INVLO;
            cs0 += q0 * k0; cs1 += q1 * k1;
        }
        cs0 += __shfl_xor_sync(0xffffffffu, cs0, 1);
        cs0 += __shfl_xor_sync(0xffffffffu, cs0, 2);
        cs1 += __shfl_xor_sync(0xffffffffu, cs1, 1);
        cs1 += __shfl_xor_sync(0xffffffffu, cs1, 2);
    }

#pragma unroll
    for (int i = 0; i < 16; i++) {
        int idx = tid + i * 256, row = idx >> 5, c8 = (idx & 31) * 8;
        *(uint4*)(sQH + row * 264 + c8) = *(const uint4*)(g_Qhi + (size_t)(row0 + row) * HD + c8);
        *(uint4*)(sQL + row * 264 + c8) = *(const uint4*)(g_Qlo + (size_t)(row0 + row) * HD + c8);
    }

    const uint32_t qh_a = smaddr(sQH + (wid * 16 + a_ro) * 264 + a_ch);
    const uint32_t ql_a = smaddr(sQL + (wid * 16 + a_ro) * 264 + a_ch);
    const uint32_t kh_b = smaddr(sKH + b_no * 264 + b_kh);
    const uint32_t vh_b = smaddr(sVH + b_no * 40 + b_kh);
    const uint32_t vl_b = smaddr(sVL + b_no * 40 + b_kh);

    float Oc[32][4];
#pragma unroll
    for (int t = 0; t < 32; t++) { Oc[t][0]=0.f; Oc[t][1]=0.f; Oc[t][2]=0.f; Oc[t][3]=0.f; }
    float l0 = 0.f, l1 = 0.f;

    for (int kt = 0; kt < 128; kt++) {
        const int kb = kb0 + kt * 32;
        __syncthreads();
#pragma unroll
        for (int i = 0; i < 4; i++) {
            int idx = tid + i * 256, row = idx >> 5, c8 = (idx & 31) * 8;
            *(uint4*)(sKH + row * 264 + c8) = *(const uint4*)(g_Khi + (size_t)(kb + row) * HD + c8);
        }
#pragma unroll
        for (int i = 0; i < 4; i++) {
            int idx = tid + i * 256, n = idx >> 2, k8 = (idx & 3) * 8;
            *(uint4*)(sVH + n * 40 + k8) = *(const uint4*)(g_Vthi + (size_t)n * NB + kb + k8);
            *(uint4*)(sVL + n * 40 + k8) = *(const uint4*)(g_Vtlo + (size_t)n * NB + kb + k8);
        }
        __syncthreads();

        // ---- S = Q K^T: fp16, hi·hi + (lo·hi)/2048 ----
        float Sc[4][4], Sl[4][4];
#pragma unroll
        for (int t = 0; t < 4; t++) {
            Sc[t][0]=0.f; Sc[t][1]=0.f; Sc[t][2]=0.f; Sc[t][3]=0.f;
            Sl[t][0]=0.f; Sl[t][1]=0.f; Sl[t][2]=0.f; Sl[t][3]=0.f;
        }
#pragma unroll
        for (int ks = 0; ks < 16; ks++) {
            uint32_t aH[4], aL[4];
            ldsm4(aH, qh_a + ks * 32);
            ldsm4(aL, ql_a + ks * 32);
#pragma unroll
            for (int tp = 0; tp < 2; tp++) {
                uint32_t bH[4];
                ldsm4(bH, kh_b + tp * 8448 + ks * 32);
                mma_f16(Sc[tp*2],   aH[0], aH[1], aH[2], aH[3], bH[0], bH[1]);
                mma_f16(Sl[tp*2],   aL[0], aL[1], aL[2], aL[3], bH[0], bH[1]);
                mma_f16(Sc[tp*2+1], aH[0], aH[1], aH[2], aH[3], bH[2], bH[3]);
                mma_f16(Sl[tp*2+1], aL[0], aL[1], aL[2], aL[3], bH[2], bH[3]);
            }
        }
        // ---- softmax + P fragments (bf16 hi/lo) ----
        uint32_t pH[2][4], pL[2][4];
        float rs0 = 0.f, rs1 = 0.f;
#pragma unroll
        for (int t = 0; t < 4; t++) {
            float e0 = __expf(Sc[t][0] + Sl[t][0] * INVLO - cs0);
            float e1 = __expf(Sc[t][1] + Sl[t][1] * INVLO - cs0);
            float e2 = __expf(Sc[t][2] + Sl[t][2] * INVLO - cs1);
            float e3 = __expf(Sc[t][3] + Sl[t][3] * INVLO - cs1);
            rs0 += e0 + e1; rs1 += e2 + e3;
            bf16 h0=__float2bfloat16(e0), h1=__float2bfloat16(e1);
            bf16 h2=__float2bfloat16(e2), h3=__float2bfloat16(e3);
            float q0=e0-__bfloat162float(h0), q1=e1-__bfloat162float(h1);
            float q2=e2-__bfloat162float(h2), q3=e3-__bfloat162float(h3);
            int ksp = t >> 1, hi2 = (t & 1) * 2;
            pH[ksp][hi2]     = ((uint32_t)__bfloat16_as_ushort(h1) << 16) | (uint32_t)__bfloat16_as_ushort(h0);
            pH[ksp][hi2 + 1] = ((uint32_t)__bfloat16_as_ushort(h3) << 16) | (uint32_t)__bfloat16_as_ushort(h2);
            pL[ksp][hi2]     = packbf(q0, q1);
            pL[ksp][hi2 + 1] = packbf(q2, q3);
        }
        rs0 += __shfl_xor_sync(0xffffffffu, rs0, 1);
        rs0 += __shfl_xor_sync(0xffffffffu, rs0, 2);
        rs1 += __shfl_xor_sync(0xffffffffu, rs1, 1);
        rs1 += __shfl_xor_sync(0xffffffffu, rs1, 2);
        l0 += rs0; l1 += rs1;

        // ---- O += P V (bf16, 3 combos) ----
#pragma unroll
        for (int ks2 = 0; ks2 < 2; ks2++) {
#pragma unroll
            for (int tp = 0; tp < 16; tp++) {
                uint32_t bH[4], bL[4];
                ldsm4(bH, vh_b + tp * 1280 + ks2 * 32);
                ldsm4(bL, vl_b + tp * 1280 + ks2 * 32);
                mma_bf16(Oc[tp*2], pH[ks2][0], pH[ks2][1], pH[ks2][2], pH[ks2][3], bH[0], bH[1]);
                mma_bf16(Oc[tp*2], pH[ks2][0], pH[ks2][1], pH[ks2][2], pH[ks2][3], bL[0], bL[1]);
                mma_bf16(Oc[tp*2], pL[ks2][0], pL[ks2][1], pL[ks2][2], pL[ks2][3], bH[0], bH[1]);
                mma_bf16(Oc[tp*2+1], pH[ks2][0], pH[ks2][1], pH[ks2][2], pH[ks2][3], bH[2], bH[3]);
                mma_bf16(Oc[tp*2+1], pH[ks2][0], pH[ks2][1], pH[ks2][2], pH[ks2][3], bL[2], bL[3]);
                mma_bf16(Oc[tp*2+1], pL[ks2][0], pL[ks2][1], pL[ks2][2], pL[ks2][3], bH[2], bH[3]);
            }
        }
    }
    {
        int rg = row0 + wid * 16 + r;
        float* O = g_Opart + (size_t)half * NB * HD;
#pragma unroll
        for (int t = 0; t < 32; t++) {
            int col = t * 8 + cq;
            O[(size_t)rg * HD + col]       = Oc[t][0];
            O[(size_t)rg * HD + col + 1]   = Oc[t][1];
            O[(size_t)(rg + 8) * HD + col]     = Oc[t][2];
            O[(size_t)(rg + 8) * HD + col + 1] = Oc[t][3];
        }
        if ((lane & 3) == 0) {
            g_lpart[half * NB + rg] = l0;
            g_lpart[half * NB + rg + 8] = l1;
        }
    }
}

__global__ void flash_merge_k(){
    int row = blockIdx.x, c = threadIdx.x;
    float li = 1.f / (g_lpart[row] + g_lpart[NB + row]);
    size_t o = (size_t)row * HD + c;
    float v = (g_Opart[o] + g_Opart[(size_t)NB * HD + o]) * li;
    f16 h, l; splith(v, h, l);
    g_avhi[o] = h; g_avlo[o] = l;
}

// ---------------- atom self-attn + LN ----------------
#define AT_SMEM_FLOATS (4*64*136+64*64+512+128)
__global__ __launch_bounds__(256,1) void atom_attn_ln_k(const float* __restrict__ xg,
                                                        const float* __restrict__ gw,
                                                        const float* __restrict__ bw){
    extern __shared__ float smf[];
    float* sx=smf; float* sq=sx+64*136; float* sk=sq+64*136; float* sv=sk+64*136;
    float* ss=sv+64*136; float* sred=ss+4096; float* srow=sred+512;
    const int tid=threadIdx.x; const int base=blockIdx.x*64;
    for(int idx=tid;idx<64*FDIM;idx+=256){
        int a=idx/FDIM,f=idx-a*FDIM; size_t go=(size_t)(base+a)*FDIM+f;
        sx[a*136+f]=xg[go]; sq[a*136+f]=g_qa[go]; sk[a*136+f]=g_ka[go]; sv[a*136+f]=g_va[go];
    }
    __syncthreads();
    {
        int ty=tid>>4,tx=tid&15; float acc[4][4]={};
        for(int h=0;h<FDIM;h++){
            float qv[4],kv[4];
#pragma unroll
            for(int i=0;i<4;i++){qv[i]=sq[(ty*4+i)*136+h];kv[i]=sk[(tx*4+i)*136+h];}
#pragma unroll
            for(int i=0;i<4;i++)
#pragma unroll
                for(int j=0;j<4;j++)acc[i][j]+=qv[i]*kv[j];
        }
        float scl=rsqrtf(133.0f);
#pragma unroll
        for(int i=0;i<4;i++)
#pragma unroll
            for(int j=0;j<4;j++)ss[(ty*4+i)*64+tx*4+j]=acc[i][j]*scl;
    }
    __syncthreads();
    if(tid<64){
        float mx=-1e30f;
        for(int j=0;j<64;j++)mx=fmaxf(mx,ss[tid*64+j]);
        float s=0.f;
        for(int j=0;j<64;j++){float e=__expf(ss[tid*64+j]-mx);ss[tid*64+j]=e;s+=e;}
        float inv=1.f/s;
        for(int j=0;j<64;j++)ss[tid*64+j]*=inv;
    }
    __syncthreads();
    const int r=tid>>2,qd=tid&3,f0=qd*34;
    float tv[34];
#pragma unroll
    for(int f=0;f<34;f++)tv[f]=0.f;
    for(int b=0;b<64;b++){
        float p=ss[r*64+b]; const float* vb=&sv[b*136+f0];
#pragma unroll
        for(int f=0;f<34;f++)if(f0+f<FDIM)tv[f]+=p*vb[f];
    }
    float s1=0.f;
#pragma unroll
    for(int f=0;f<34;f++)if(f0+f<FDIM){tv[f]+=sx[r*136+f0+f];s1+=tv[f];}
    sred[tid]=s1; __syncthreads();
    if(qd==0)srow[r]=(sred[tid]+sred[tid+1]+sred[tid+2]+sred[tid+3])*(1.f/133.f);
    __syncthreads();
    float mu=srow[r],s2=0.f;
#pragma unroll
    for(int f=0;f<34;f++)if(f0+f<FDIM){float d=tv[f]-mu;s2+=d*d;}
    sred[tid]=s2; __syncthreads();
    if(qd==0){float var=(sred[tid]+sred[tid+1]+sred[tid+2]+sred[tid+3])*(1.f/133.f);srow[64+r]=rsqrtf(var+1e-5f);}
    __syncthreads();
    float rstd=srow[64+r];
#pragma unroll
    for(int f=0;f<34;f++){int fg=f0+f;
        if(fg<FDIM)g_fe[(size_t)(base+r)*FDIM+fg]=(tv[f]-mu)*rstd*gw[fg]+bw[fg];}
}

// ---------------- elementwise / gather ----------------
__global__ void gather_sum_k(const int* __restrict__ a2b){
    __shared__ int idx[MAXNB];
    int a=blockIdx.x,t=threadIdx.x;
    if(t<MAXNB)idx[t]=a2b[a*MAXNB+t];
    __syncthreads();
    float s=0.f;
#pragma unroll
    for(int j=0;j<MAXNB;j++)s+=g_msg[(size_t)idx[j]*HD+t];
    g_amsg[(size_t)a*HD+t]=s;
}
// fused per-bond: tmp = sum_j msg[a2b[b2a[b]][j]] - msg[b2revb[b]], split fp16
__global__ void dmpnn_fused_k(const int* __restrict__ a2b, const int* __restrict__ b2a,
                              const int* __restrict__ b2revb){
    __shared__ int idx[MAXNB+1];
    int b=blockIdx.x,t=threadIdx.x;
    if(t==0){
        int ia=__ldg(&b2a[b]);
#pragma unroll
        for(int j=0;j<MAXNB;j++) idx[j]=__ldg(&a2b[ia*MAXNB+j]);
        idx[MAXNB]=__ldg(&b2revb[b]);
    }
    __syncthreads();
    float s=0.f;
#pragma unroll
    for(int j=0;j<MAXNB;j++)s+=g_msg[(size_t)idx[j]*HD+t];
    float v=s-g_msg[(size_t)idx[MAXNB]*HD+t];
    f16 h,l; splith(v,h,l);
    size_t o=(size_t)b*HD+t;
    g_tmphi[o]=h; g_tmplo[o]=l;
}
__global__ void combine_k(const float* __restrict__ wal, const float* __restrict__ walb){
    __shared__ float red[256];
    __shared__ float salpha;
    int b=blockIdx.x,t=threadIdx.x;
    size_t o=(size_t)b*HD+t;
    float d=g_dmpnn[o],am=g_attm[o];
    red[t]=d*wal[t]+am*wal[256+t];
    __syncthreads();
    for(int s=128;s>0;s>>=1){if(t<s)red[t]+=red[t+s];__syncthreads();}
    if(t==0)salpha=1.f/(1.f+__expf(-(red[0]+walb[0])));
    __syncthreads();
    float al=salpha;
    float v=fmaxf(g_inputs[o]+al*d+(1.f-al)*am,0.f);
    g_msg[o]=v;
    f16 h,l; splith(v,h,l);
    g_msghi[o]=h; g_msglo[o]=l;
}
__global__ void concat_split_k(){
    int i=blockIdx.x*blockDim.x+threadIdx.x;
    if(i>=NA*KP_WO)return;
    int row=i/KP_WO,c=i-row*KP_WO;
    float x = (c<FDIM) ? g_fe[(size_t)row*FDIM+c]
             : (c<FDIM+HD ? g_amsg[(size_t)row*HD+(c-FDIM)] : 0.f);
    f16 h,l; splith(x,h,l);
    g_cathi[i]=h; g_catlo[i]=l;
}

// ---------------- molecule pooling ----------------
#define MP_SMEM_FLOATS (2*64*260+4096)
__global__ __launch_bounds__(256,1) void mol_pool_k(const float* __restrict__ Wb,
                                                    const float* __restrict__ bb,
                                                    float* __restrict__ outg){
    extern __shared__ float smf[];
    float* shm=smf; float* sw=shm+64*260; float* ssc=sw+64*260;
    const int tid=threadIdx.x; const int base=blockIdx.x*64;
    for(int idx=tid;idx<64*HD;idx+=256){
        int a=idx>>8,c=idx&255;
        shm[a*260+c]=g_atomh[(size_t)(base+a)*HD+c];
        sw[a*260+c]=g_hmwa[(size_t)(base+a)*HD+c];
    }
    __syncthreads();
    {
        int ty=tid>>4,tx=tid&15; float acc[4][4]={};
        for(int h=0;h<HD;h++){
            float qv[4],kv[4];
#pragma unroll
            for(int i=0;i<4;i++){qv[i]=sw[(ty*4+i)*260+h];kv[i]=shm[(tx*4+i)*260+h];}
#pragma unroll
            for(int i=0;i<4;i++)
#pragma unroll
                for(int j=0;j<4;j++)acc[i][j]+=qv[i]*kv[j];
        }
#pragma unroll
        for(int i=0;i<4;i++)
#pragma unroll
            for(int j=0;j<4;j++)ssc[(ty*4+i)*64+tx*4+j]=acc[i][j];
    }
    __syncthreads();
    if(tid<64){
        float mx=-1e30f;
        for(int j=0;j<64;j++)mx=fmaxf(mx,ssc[tid*64+j]);
        float s=0.f;
        for(int j=0;j<64;j++){float e=__expf(ssc[tid*64+j]-mx);ssc[tid*64+j]=e;s+=e;}
        float inv=1.f/s;
        for(int j=0;j<64;j++)ssc[tid*64+j]*=inv;
    }
    __syncthreads();
    const int c=tid;
    float acc[64];
#pragma unroll
    for(int a=0;a<64;a++)acc[a]=0.f;
    for(int b=0;b<64;b++){
        float hv=shm[b*260+c];
#pragma unroll 16
        for(int a=0;a<64;a++)acc[a]+=ssc[a*64+b]*hv;
    }
    __syncthreads();
    for(int a=0;a<64;a++)sw[a*260+c]=acc[a];
    __syncthreads();
#pragma unroll
    for(int a=0;a<64;a++)acc[a]=0.f;
    for(int k=0;k<HD;k++){
        float wv=Wb[(size_t)k*HD+c];
#pragma unroll 16
        for(int a=0;a<64;a++)acc[a]+=sw[a*260+k]*wv;
    }
    float bv=bb[c],s=0.f;
    for(int a=0;a<64;a++){
        float t=fmaxf(acc[a]+bv,0.f);
        s+=shm[a*260+c]+t;
    }
    outg[(size_t)blockIdx.x*HD+c]=s*(1.f/64.f);
}

// ---------------- host driver ----------------
static float* symf(const void* s){ void* p=nullptr; cudaGetSymbolAddress(&p,s); return (float*)p; }
static f16* symh(const void* s){ void* p=nullptr; cudaGetSymbolAddress(&p,s); return (f16*)p; }

extern "C" void kernel_launch(void* const* d_in, const int* in_sizes, int n_in,
                              void* d_out, int out_size){
    const float* f_atoms=(const float*)d_in[0];
    const float* f_bonds=(const float*)d_in[1];
    const float* Wq_atom=(const float*)d_in[2];
    const float* Wk_atom=(const float*)d_in[3];
    const float* Wv_atom=(const float*)d_in[4];
    const float* ln_g=(const float*)d_in[5];
    const float* ln_b=(const float*)d_in[6];
    const float* Wi=(const float*)d_in[7];
    const float* Wh=(const float*)d_in[8];
    const float* Wq=(const float*)d_in[9];
    const float* Wk=(const float*)d_in[10];
    const float* Wv=(const float*)d_in[11];
    const float* Wa=(const float*)d_in[12];
    const float* Walw=(const float*)d_in[13];
    const float* Walb=(const float*)d_in[14];
    const float* Wow=(const float*)d_in[15];
    const float* Wob=(const float*)d_in[16];
    const float* Wbw=(const float*)d_in[17];
    const float* Wbb=(const float*)d_in[18];
    const int* a2b=(const int*)d_in[19];
    const int* b2a=(const int*)d_in[20];
    const int* b2revb=(const int*)d_in[21];
    float* out=(float*)d_out;

    float* p_qa=symf(g_qa); float* p_ka=symf(g_ka); float* p_va=symf(g_va);
    float* p_inputs=symf(g_inputs); float* p_msg=symf(g_msg);
    float* p_dmpnn=symf(g_dmpnn); float* p_V=symf(g_V); float* p_attm=symf(g_attm);
    float* p_atomh=symf(g_atomh); float* p_hmwa=symf(g_hmwa);
    f16* p_Qhi=symh(g_Qhi); f16* p_Qlo=symh(g_Qlo);
    f16* p_Khi=symh(g_Khi); f16* p_Klo=symh(g_Klo);
    f16* p_msghi=symh(g_msghi); f16* p_msglo=symh(g_msglo);
    f16* p_tmphi=symh(g_tmphi); f16* p_tmplo=symh(g_tmplo);
    f16* p_avhi=symh(g_avhi); f16* p_avlo=symh(g_avlo);
    f16* p_fbhi=symh(g_fbhi); f16* p_fblo=symh(g_fblo);
    f16* p_cathi=symh(g_cathi); f16* p_catlo=symh(g_catlo);
    f16* p_ahhi=symh(g_ahhi); f16* p_ahlo=symh(g_ahlo);
    f16* p_Wit=symh(g_Wit); f16* p_Wht=symh(g_Wht);
    f16* p_Wqt=symh(g_Wqt); f16* p_Wkt=symh(g_Wkt);
    f16* p_Wvt=symh(g_Wvt); f16* p_Wat=symh(g_Wat);
    f16* p_Wot=symh(g_Wot);

    const int AT_SMEM=AT_SMEM_FLOATS*4, MP_SMEM=MP_SMEM_FLOATS*4;
    cudaFuncSetAttribute(flash_mma,cudaFuncAttributeMaxDynamicSharedMemorySize,FL_SMEM);
    cudaFuncSetAttribute(atom_attn_ln_k,cudaFuncAttributeMaxDynamicSharedMemorySize,AT_SMEM);
    cudaFuncSetAttribute(mol_pool_k,cudaFuncAttributeMaxDynamicSharedMemorySize,MP_SMEM);

    wsplit_k<<<(HD*KP_WI+255)/256,256>>>(Wi,p_Wit,BFDIM,HD,KP_WI);
    wsplit_k<<<(HD*HD+255)/256,256>>>(Wh,p_Wht,HD,HD,HD);
    wsplit_k<<<(HD*HD+255)/256,256>>>(Wq,p_Wqt,HD,HD,HD);
    wsplit_k<<<(HD*HD+255)/256,256>>>(Wk,p_Wkt,HD,HD,HD);
    wsplit_k<<<(HD*HD+255)/256,256>>>(Wv,p_Wvt,HD,HD,HD);
    wsplit_k<<<(HD*HD+255)/256,256>>>(Wa,p_Wat,HD,HD,HD);
    wsplit_k<<<(HD*KP_WO+255)/256,256>>>(Wow,p_Wot,FDIM+HD,HD,KP_WO);
    asplit_k<<<(NB*KP_WI)/256,256>>>(f_bonds,p_fbhi,p_fblo,BFDIM,KP_WI);

    dim3 gqa((FDIM+63)/64,(NA+63)/64);
    gemm_k<0,0><<<gqa,256>>>(f_atoms,Wq_atom,nullptr,p_qa,NA,FDIM,FDIM);
    gemm_k<0,0><<<gqa,256>>>(f_atoms,Wk_atom,nullptr,p_ka,NA,FDIM,FDIM);
    gemm_k<0,0><<<gqa,256>>>(f_atoms,Wv_atom,nullptr,p_va,NA,FDIM,FDIM);
    atom_attn_ln_k<<<NMOL,256,AT_SMEM>>>(f_atoms,ln_g,ln_b);

    dim3 tgb(4,NB/128), tga(4,NA/128);
    tgemm<1,0,0,1,1,1><<<tgb,256>>>(p_fbhi,p_fblo,p_Wit,nullptr,
                                    p_msg,p_msghi,p_msglo,p_inputs,NB,KP_WI);

    dim3 vtg(NB/32,HD/32), vtb(32,8);
    for(int it=0;it<3;it++){
        dmpnn_fused_k<<<NB,256>>>(a2b,b2a,b2revb);
        tgemm<0,0,0,1,0,0><<<tgb,256>>>(p_tmphi,p_tmplo,p_Wht,nullptr,
                                        p_dmpnn,nullptr,nullptr,nullptr,NB,HD);
        tgemm<0,0,1,0,1,0><<<tgb,256>>>(p_msghi,p_msglo,p_Wqt,nullptr,
                                        nullptr,p_Qhi,p_Qlo,nullptr,NB,HD);
        tgemm<0,0,0,0,1,0><<<tgb,256>>>(p_msghi,p_msglo,p_Wkt,nullptr,
                                        nullptr,p_Khi,p_Klo,nullptr,NB,HD);
        tgemm<0,0,0,1,0,0><<<tgb,256>>>(p_msghi,p_msglo,p_Wvt,nullptr,
                                        p_V,nullptr,nullptr,nullptr,NB,HD);
        vt_split_k<<<vtg,vtb>>>(p_V);
        flash_mma<<<dim3(NB/128,2),256,FL_SMEM>>>();
        flash_merge_k<<<NB,256>>>();
        tgemm<0,0,0,1,0,0><<<tgb,256>>>(p_avhi,p_avlo,p_Wat,nullptr,
                                        p_attm,nullptr,nullptr,nullptr,NB,HD);
        combine_k<<<NB,256>>>(Walw,Walb);
    }

    gather_sum_k<<<NA,256>>>(a2b);
    concat_split_k<<<(NA*KP_WO+255)/256,256>>>();
    tgemm<1,1,0,1,1,0><<<tga,256>>>(p_cathi,p_catlo,p_Wot,Wob,
                                    p_atomh,p_ahhi,p_ahlo,nullptr,NA,KP_WO);
    tgemm<0,0,0,1,0,0><<<tga,256>>>(p_ahhi,p_ahlo,p_Wat,nullptr,
                                    p_hmwa,nullptr,nullptr,nullptr,NA,HD);
    mol_pool_k<<<NMOL,256,MP_SMEM>>>(Wbw,Wbb,out);
}

// round 8
// speedup vs baseline: 12.9865x; 1.0357x over previous
#include <cuda_runtime.h>
#include <cuda_bf16.h>
#include <cuda_fp16.h>
#include <math.h>
#include <stdint.h>

#define NA 4096
#define NB 8192
#define FDIM 133
#define BFDIM 147
#define HD 256
#define NMOL 64
#define MAXNB 6
#define KP_WI 160
#define KP_WO 416
#define N3 399
#define LOSCL 2048.0f
#define INVLO (1.0f/2048.0f)

typedef __nv_bfloat16 bf16;
typedef __half f16;

// ---------------- device scratch ----------------
__device__ __align__(16) float g_W3[FDIM*N3];
__device__ __align__(16) float g_qkv[NA*N3];
__device__ __align__(16) float g_fe[NA*FDIM];
__device__ __align__(16) float g_inputs[NB*HD];
__device__ __align__(16) float g_msg[NB*HD];
__device__ __align__(16) float g_amsg[NA*HD];
__device__ __align__(16) float g_dmpnn[NB*HD];
__device__ __align__(16) float g_attm[NB*HD];
__device__ __align__(16) float g_atomh[NA*HD];
__device__ __align__(16) float g_hmwa[NA*HD];
__device__ __align__(16) float g_Opart[2*NB*HD];
__device__ __align__(16) float g_lpart[2*NB];

__device__ __align__(16) f16 g_Qhi[NB*HD];
__device__ __align__(16) f16 g_Qlo[NB*HD];
__device__ __align__(16) f16 g_Khi[NB*HD];
__device__ __align__(16) f16 g_Klo[NB*HD];
__device__ __align__(16) bf16 g_Vhi[NB*HD];
__device__ __align__(16) bf16 g_Vlo[NB*HD];
__device__ __align__(16) f16 g_msghi[NB*HD];
__device__ __align__(16) f16 g_msglo[NB*HD];
__device__ __align__(16) f16 g_tmphi[NB*HD];
__device__ __align__(16) f16 g_tmplo[NB*HD];
__device__ __align__(16) f16 g_avhi[NB*HD];
__device__ __align__(16) f16 g_avlo[NB*HD];
__device__ __align__(16) f16 g_fbhi[NB*KP_WI];
__device__ __align__(16) f16 g_fblo[NB*KP_WI];
__device__ __align__(16) f16 g_cathi[NA*KP_WO];
__device__ __align__(16) f16 g_catlo[NA*KP_WO];
__device__ __align__(16) f16 g_ahhi[NA*HD];
__device__ __align__(16) f16 g_ahlo[NA*HD];
// fp16 transposed+split weights [N][KP]
__device__ __align__(16) f16 g_Withi[HD*KP_WI];
__device__ __align__(16) f16 g_Witlo[HD*KP_WI];
__device__ __align__(16) f16 g_Whthi[HD*HD];
__device__ __align__(16) f16 g_Whtlo[HD*HD];
__device__ __align__(16) f16 g_Wqthi[HD*HD];
__device__ __align__(16) f16 g_Wqtlo[HD*HD];
__device__ __align__(16) f16 g_Wkthi[HD*HD];
__device__ __align__(16) f16 g_Wktlo[HD*HD];
__device__ __align__(16) f16 g_Wvthi[HD*HD];
__device__ __align__(16) f16 g_Wvtlo[HD*HD];
__device__ __align__(16) f16 g_Wathi[HD*HD];
__device__ __align__(16) f16 g_Watlo[HD*HD];
__device__ __align__(16) f16 g_Wothi[HD*KP_WO];
__device__ __align__(16) f16 g_Wotlo[HD*KP_WO];

// ---------------- mma / ldmatrix helpers ----------------
__device__ __forceinline__ void mma_bf16(float* c, uint32_t a0, uint32_t a1, uint32_t a2,
                                         uint32_t a3, uint32_t b0, uint32_t b1) {
    asm("mma.sync.aligned.m16n8k16.row.col.f32.bf16.bf16.f32 "
        "{%0,%1,%2,%3}, {%4,%5,%6,%7}, {%8,%9}, {%0,%1,%2,%3};\n"
        : "+f"(c[0]), "+f"(c[1]), "+f"(c[2]), "+f"(c[3])
        : "r"(a0), "r"(a1), "r"(a2), "r"(a3), "r"(b0), "r"(b1));
}
__device__ __forceinline__ void mma_f16(float* c, uint32_t a0, uint32_t a1, uint32_t a2,
                                        uint32_t a3, uint32_t b0, uint32_t b1) {
    asm("mma.sync.aligned.m16n8k16.row.col.f32.f16.f16.f32 "
        "{%0,%1,%2,%3}, {%4,%5,%6,%7}, {%8,%9}, {%0,%1,%2,%3};\n"
        : "+f"(c[0]), "+f"(c[1]), "+f"(c[2]), "+f"(c[3])
        : "r"(a0), "r"(a1), "r"(a2), "r"(a3), "r"(b0), "r"(b1));
}
__device__ __forceinline__ uint32_t smaddr(const void* p) {
    return (uint32_t)__cvta_generic_to_shared(p);
}
__device__ __forceinline__ void ldsm4(uint32_t* r, uint32_t a) {
    asm volatile("ldmatrix.sync.aligned.m8n8.x4.shared.b16 {%0,%1,%2,%3}, [%4];"
                 : "=r"(r[0]), "=r"(r[1]), "=r"(r[2]), "=r"(r[3]) : "r"(a));
}
__device__ __forceinline__ void ldsm4t(uint32_t* r, uint32_t a) {
    asm volatile("ldmatrix.sync.aligned.m8n8.x4.trans.shared.b16 {%0,%1,%2,%3}, [%4];"
                 : "=r"(r[0]), "=r"(r[1]), "=r"(r[2]), "=r"(r[3]) : "r"(a));
}
__device__ __forceinline__ uint32_t packbf(float x, float y) {
    bf16 h0 = __float2bfloat16(x), h1 = __float2bfloat16(y);
    return ((uint32_t)__bfloat16_as_ushort(h1) << 16) | (uint32_t)__bfloat16_as_ushort(h0);
}
__device__ __forceinline__ void split1(float x, bf16& h, bf16& l) {
    h = __float2bfloat16(x);
    l = __float2bfloat16(x - __bfloat162float(h));
}
__device__ __forceinline__ void splith(float x, f16& h, f16& l) {
    h = __float2half(x);
    l = __float2half((x - __half2float(h)) * LOSCL);
}
__device__ __forceinline__ uint32_t packh(f16 a, f16 b) {
    return ((uint32_t)__half_as_ushort(b) << 16) | (uint32_t)__half_as_ushort(a);
}

// ---------------- fp16 hi/lo tensor GEMM (3 combos: AhiBhi + AloBhi + AhiBlo) --------
template <int RELU, int HASBIAS, int SCALEQ, int OUTF32, int OUTSPLIT, int PREAUX, int OUTVB>
__global__ __launch_bounds__(256) void tgemm(
    const f16* __restrict__ Ah, const f16* __restrict__ Al,
    const f16* __restrict__ Bh, const f16* __restrict__ Bl,
    const float* __restrict__ bias,
    float* __restrict__ Cf, f16* __restrict__ Chi, f16* __restrict__ Clo,
    bf16* __restrict__ Vbh, bf16* __restrict__ Vbl,
    float* __restrict__ Caux, int M, int K) {
    __shared__ __align__(16) f16 sAh[128*40], sAl[128*40], sBh[64*40], sBl[64*40];
    const int tid = threadIdx.x, wid = tid >> 5, lane = tid & 31;
    const int r = lane >> 2, cq = (lane & 3) * 2;
    const int wm = wid >> 1, wn = wid & 1;
    const int m0 = blockIdx.y * 128, n0 = blockIdx.x * 64;
    const int a_ro = (lane & 7) + ((lane >> 3) & 1) * 8;
    const int a_ch = ((lane >> 4) & 1) * 8;
    const int b_no = (lane & 7) + ((lane >> 4) & 1) * 8;
    const int b_kh = ((lane >> 3) & 1) * 8;
    float acc[2][4][4] = {};
    float acL[2][4][4] = {};
    for (int kc = 0; kc < K; kc += 32) {
        __syncthreads();
#pragma unroll
        for (int i = 0; i < 2; i++) {
            int idx = tid + i * 256, row = idx >> 2, q8 = (idx & 3) * 8;
            *(uint4*)(sAh + row * 40 + q8) = *(const uint4*)(Ah + (size_t)(m0 + row) * K + kc + q8);
            *(uint4*)(sAl + row * 40 + q8) = *(const uint4*)(Al + (size_t)(m0 + row) * K + kc + q8);
        }
        {
            int row = tid >> 2, q8 = (tid & 3) * 8;
            *(uint4*)(sBh + row * 40 + q8) = *(const uint4*)(Bh + (size_t)(n0 + row) * K + kc + q8);
            *(uint4*)(sBl + row * 40 + q8) = *(const uint4*)(Bl + (size_t)(n0 + row) * K + kc + q8);
        }
        __syncthreads();
        uint32_t aHb[2], aLb[2], bHb, bLb;
        aHb[0] = smaddr(sAh + (wm * 32 + a_ro) * 40 + a_ch);
        aHb[1] = smaddr(sAh + (wm * 32 + 16 + a_ro) * 40 + a_ch);
        aLb[0] = smaddr(sAl + (wm * 32 + a_ro) * 40 + a_ch);
        aLb[1] = smaddr(sAl + (wm * 32 + 16 + a_ro) * 40 + a_ch);
        bHb = smaddr(sBh + (wn * 32 + b_no) * 40 + b_kh);
        bLb = smaddr(sBl + (wn * 32 + b_no) * 40 + b_kh);
#pragma unroll
        for (int ks = 0; ks < 2; ks++) {
            uint32_t aH[2][4], aL[2][4];
#pragma unroll
            for (int mf = 0; mf < 2; mf++) {
                ldsm4(aH[mf], aHb[mf] + ks * 32);
                ldsm4(aL[mf], aLb[mf] + ks * 32);
            }
#pragma unroll
            for (int np = 0; np < 2; np++) {
                uint32_t bH[4], bL[4];
                ldsm4(bH, bHb + np * 1280 + ks * 32);
                ldsm4(bL, bLb + np * 1280 + ks * 32);
#pragma unroll
                for (int mf = 0; mf < 2; mf++) {
                    mma_f16(acc[mf][np*2], aH[mf][0], aH[mf][1], aH[mf][2], aH[mf][3], bH[0], bH[1]);
                    mma_f16(acL[mf][np*2], aL[mf][0], aL[mf][1], aL[mf][2], aL[mf][3], bH[0], bH[1]);
                    mma_f16(acL[mf][np*2], aH[mf][0], aH[mf][1], aH[mf][2], aH[mf][3], bL[0], bL[1]);
                    mma_f16(acc[mf][np*2+1], aH[mf][0], aH[mf][1], aH[mf][2], aH[mf][3], bH[2], bH[3]);
                    mma_f16(acL[mf][np*2+1], aL[mf][0], aL[mf][1], aL[mf][2], aL[mf][3], bH[2], bH[3]);
                    mma_f16(acL[mf][np*2+1], aH[mf][0], aH[mf][1], aH[mf][2], aH[mf][3], bL[2], bL[3]);
                }
            }
        }
    }
#pragma unroll
    for (int mf = 0; mf < 2; mf++) {
#pragma unroll
        for (int nf = 0; nf < 4; nf++) {
            int mrow = m0 + wm * 32 + mf * 16 + r;
            int col = n0 + wn * 32 + nf * 8 + cq;
            float c0 = acc[mf][nf][0] + acL[mf][nf][0] * INVLO;
            float c1 = acc[mf][nf][1] + acL[mf][nf][1] * INVLO;
            float c2 = acc[mf][nf][2] + acL[mf][nf][2] * INVLO;
            float c3 = acc[mf][nf][3] + acL[mf][nf][3] * INVLO;
            if (HASBIAS) { float b0 = bias[col], b1 = bias[col + 1]; c0 += b0; c1 += b1; c2 += b0; c3 += b1; }
            if (SCALEQ) { c0 *= 0.0625f; c1 *= 0.0625f; c2 *= 0.0625f; c3 *= 0.0625f; }
            if (PREAUX) {
                Caux[(size_t)mrow * HD + col] = c0; Caux[(size_t)mrow * HD + col + 1] = c1;
                Caux[(size_t)(mrow + 8) * HD + col] = c2; Caux[(size_t)(mrow + 8) * HD + col + 1] = c3;
            }
            if (RELU) { c0 = fmaxf(c0, 0.f); c1 = fmaxf(c1, 0.f); c2 = fmaxf(c2, 0.f); c3 = fmaxf(c3, 0.f); }
            if (OUTF32) {
                Cf[(size_t)mrow * HD + col] = c0; Cf[(size_t)mrow * HD + col + 1] = c1;
                Cf[(size_t)(mrow + 8) * HD + col] = c2; Cf[(size_t)(mrow + 8) * HD + col + 1] = c3;
            }
            if (OUTSPLIT) {
                f16 h0, l0b, h1, l1b, h2, l2b, h3, l3b;
                splith(c0, h0, l0b); splith(c1, h1, l1b); splith(c2, h2, l2b); splith(c3, h3, l3b);
                *(uint32_t*)(Chi + (size_t)mrow * HD + col) = packh(h0, h1);
                *(uint32_t*)(Clo + (size_t)mrow * HD + col) = packh(l0b, l1b);
                *(uint32_t*)(Chi + (size_t)(mrow + 8) * HD + col) = packh(h2, h3);
                *(uint32_t*)(Clo + (size_t)(mrow + 8) * HD + col) = packh(l2b, l3b);
            }
            if (OUTVB) {
                bf16 h0, l0b, h1, l1b, h2, l2b, h3, l3b;
                split1(c0, h0, l0b); split1(c1, h1, l1b); split1(c2, h2, l2b); split1(c3, h3, l3b);
                *(uint32_t*)(Vbh + (size_t)mrow * HD + col) = ((uint32_t)__bfloat16_as_ushort(h1) << 16) | __bfloat16_as_ushort(h0);
                *(uint32_t*)(Vbl + (size_t)mrow * HD + col) = ((uint32_t)__bfloat16_as_ushort(l1b) << 16) | __bfloat16_as_ushort(l0b);
                *(uint32_t*)(Vbh + (size_t)(mrow + 8) * HD + col) = ((uint32_t)__bfloat16_as_ushort(h3) << 16) | __bfloat16_as_ushort(h2);
                *(uint32_t*)(Vbl + (size_t)(mrow + 8) * HD + col) = ((uint32_t)__bfloat16_as_ushort(l3b) << 16) | __bfloat16_as_ushort(l2b);
            }
        }
    }
}

// ---------------- mega weight transpose+split (all 7 weights, one launch) ------------
#define SZ_WI (HD*KP_WI)
#define SZ_H  (HD*HD)
#define SZ_WO (HD*KP_WO)
__global__ void wsplit_all_k(const float* __restrict__ Wi, const float* __restrict__ Wh,
                             const float* __restrict__ Wq, const float* __restrict__ Wk,
                             const float* __restrict__ Wv, const float* __restrict__ Wa,
                             const float* __restrict__ Wo) {
    int idx = blockIdx.x * blockDim.x + threadIdx.x;
    const float* W; f16 *th, *tl; int K, KPp, local;
    if (idx < SZ_WI) { W = Wi; th = g_Withi; tl = g_Witlo; K = BFDIM; KPp = KP_WI; local = idx; }
    else if (idx < SZ_WI + SZ_H)   { W = Wh; th = g_Whthi; tl = g_Whtlo; K = HD; KPp = HD; local = idx - SZ_WI; }
    else if (idx < SZ_WI + 2*SZ_H) { W = Wq; th = g_Wqthi; tl = g_Wqtlo; K = HD; KPp = HD; local = idx - SZ_WI - SZ_H; }
    else if (idx < SZ_WI + 3*SZ_H) { W = Wk; th = g_Wkthi; tl = g_Wktlo; K = HD; KPp = HD; local = idx - SZ_WI - 2*SZ_H; }
    else if (idx < SZ_WI + 4*SZ_H) { W = Wv; th = g_Wvthi; tl = g_Wvtlo; K = HD; KPp = HD; local = idx - SZ_WI - 3*SZ_H; }
    else if (idx < SZ_WI + 5*SZ_H) { W = Wa; th = g_Wathi; tl = g_Watlo; K = HD; KPp = HD; local = idx - SZ_WI - 4*SZ_H; }
    else if (idx < SZ_WI + 5*SZ_H + SZ_WO) { W = Wo; th = g_Wothi; tl = g_Wotlo; K = FDIM+HD; KPp = KP_WO; local = idx - SZ_WI - 5*SZ_H; }
    else return;
    int k = local % KPp, n = local / KPp;
    float x = (k < K) ? W[(size_t)k * HD + n] : 0.f;
    f16 h, l; splith(x, h, l);
    th[local] = h; tl[local] = l;
}
__global__ void asplit_k(const float* __restrict__ A, f16* __restrict__ hi,
                         f16* __restrict__ lo, int K, int KPp) {
    int idx = blockIdx.x * blockDim.x + threadIdx.x;
    int k = idx % KPp, m = idx / KPp;
    float x = (k < K) ? A[(size_t)m * K + k] : 0.f;
    f16 h, l; splith(x, h, l);
    hi[idx] = h; lo[idx] = l;
}
// concat Wq_atom|Wk_atom|Wv_atom -> g_W3 [FDIM][399]
__global__ void w3copy_k(const float* __restrict__ Wq, const float* __restrict__ Wk,
                         const float* __restrict__ Wv) {
    int idx = blockIdx.x * blockDim.x + threadIdx.x;
    if (idx >= FDIM * N3) return;
    int k = idx / N3, n = idx % N3;
    float v = (n < FDIM) ? Wq[k * FDIM + n]
            : (n < 2*FDIM) ? Wk[k * FDIM + n - FDIM]
            : Wv[k * FDIM + n - 2*FDIM];
    g_W3[idx] = v;
}

// ---------------- fp32 GEMM (atom-side) ----------------
template <int RELU, int HASBIAS>
__global__ __launch_bounds__(256) void gemm_k(const float* __restrict__ A, const float* __restrict__ B,
                                              const float* __restrict__ bias, float* __restrict__ C,
                                              int Mm, int Nn, int Kk){
    __shared__ float As[16*68];
    __shared__ float Bs[16*68];
    const int tid=threadIdx.x, tm=tid>>4, tn=tid&15;
    const int m0=blockIdx.y*64, n0=blockIdx.x*64;
    float acc[4][4]={};
    for(int k0=0;k0<Kk;k0+=16){
#pragma unroll
        for(int i=0;i<4;i++){int idx=tid+i*256,row=idx>>4,col=idx&15;float v=0.f;
            if(m0+row<Mm&&k0+col<Kk)v=A[(size_t)(m0+row)*Kk+k0+col];As[col*68+row]=v;}
#pragma unroll
        for(int i=0;i<4;i++){int idx=tid+i*256,row=idx>>6,col=idx&63;float v=0.f;
            if(k0+row<Kk&&n0+col<Nn)v=B[(size_t)(k0+row)*Nn+n0+col];Bs[row*68+col]=v;}
        __syncthreads();
#pragma unroll
        for(int kk=0;kk<16;kk++){
            float4 a4=*(const float4*)&As[kk*68+tm*4];
            float4 b4=*(const float4*)&Bs[kk*68+tn*4];
            float av[4]={a4.x,a4.y,a4.z,a4.w},bv[4]={b4.x,b4.y,b4.z,b4.w};
#pragma unroll
            for(int i=0;i<4;i++)
#pragma unroll
                for(int j=0;j<4;j++)acc[i][j]+=av[i]*bv[j];
        }
        __syncthreads();
    }
#pragma unroll
    for(int i=0;i<4;i++){int m=m0+tm*4+i;if(m>=Mm)continue;
#pragma unroll
        for(int j=0;j<4;j++){int n=n0+tn*4+j;if(n>=Nn)continue;
            float v=acc[i][j];if(HASBIAS)v+=bias[n];if(RELU)v=fmaxf(v,0.f);
            C[(size_t)m*Nn+n]=v;}}
}

// ---------------- flash attention: fp16 2-combo S, bf16 3-combo O (trans-ldmatrix V) -
#define SQH 0
#define SQL 67584
#define SKH 135168
#define SVH 152064
#define SVL 168960
#define FL_SMEM 185856
__global__ __launch_bounds__(256, 1) void flash_mma(){
    extern __shared__ __align__(16) char smem[];
    f16*  sQH = (f16*)(smem + SQH);
    f16*  sQL = (f16*)(smem + SQL);
    f16*  sKH = (f16*)(smem + SKH);
    bf16* sVH = (bf16*)(smem + SVH);
    bf16* sVL = (bf16*)(smem + SVL);
    const int tid = threadIdx.x, wid = tid >> 5, lane = tid & 31;
    const int r = lane >> 2, cq = (lane & 3) * 2;
    const int row0 = blockIdx.x * 128;
    const int half = blockIdx.y;
    const int kb0 = half * (NB / 2);
    const int a_ro = (lane & 7) + ((lane >> 3) & 1) * 8;
    const int a_ch = ((lane >> 4) & 1) * 8;
    const int b_no = (lane & 7) + ((lane >> 4) & 1) * 8;
    const int b_kh = ((lane >> 3) & 1) * 8;
    // V (trans) lane offsets: row = k, col = n
    const int v_ro = (lane & 7) + ((lane >> 3) & 1) * 8;
    const int v_co = ((lane >> 4) & 1) * 8;

    // exact self-logit per row (Q already scaled 1/16)
    float cs0 = 0.f, cs1 = 0.f;
    {
        int rg = row0 + wid * 16 + r;
        const f16 *q0h=&g_Qhi[(size_t)rg*HD], *q0l=&g_Qlo[(size_t)rg*HD];
        const f16 *k0h=&g_Khi[(size_t)rg*HD], *k0l=&g_Klo[(size_t)rg*HD];
        const f16 *q1h=&g_Qhi[(size_t)(rg+8)*HD], *q1l=&g_Qlo[(size_t)(rg+8)*HD];
        const f16 *k1h=&g_Khi[(size_t)(rg+8)*HD], *k1l=&g_Klo[(size_t)(rg+8)*HD];
        int f0 = (lane & 3) * 64;
#pragma unroll 16
        for (int f = 0; f < 64; f++) {
            float q0 = __half2float(q0h[f0+f]) + __half2float(q0l[f0+f]) * INVLO;
            float k0 = __half2float(k0h[f0+f]) + __half2float(k0l[f0+f]) * INVLO;
            float q1 = __half2float(q1h[f0+f]) + __half2float(q1l[f0+f]) * INVLO;
            float k1 = __half2float(k1h[f0+f]) + __half2float(k1l[f0+f]) * INVLO;
            cs0 += q0 * k0; cs1 += q1 * k1;
        }
        cs0 += __shfl_xor_sync(0xffffffffu, cs0, 1);
        cs0 += __shfl_xor_sync(0xffffffffu, cs0, 2);
        cs1 += __shfl_xor_sync(0xffffffffu, cs1, 1);
        cs1 += __shfl_xor_sync(0xffffffffu, cs1, 2);
    }

#pragma unroll
    for (int i = 0; i < 16; i++) {
        int idx = tid + i * 256, row = idx >> 5, c8 = (idx & 31) * 8;
        *(uint4*)(sQH + row * 264 + c8) = *(const uint4*)(g_Qhi + (size_t)(row0 + row) * HD + c8);
        *(uint4*)(sQL + row * 264 + c8) = *(const uint4*)(g_Qlo + (size_t)(row0 + row) * HD + c8);
    }

    const uint32_t qh_a = smaddr(sQH + (wid * 16 + a_ro) * 264 + a_ch);
    const uint32_t ql_a = smaddr(sQL + (wid * 16 + a_ro) * 264 + a_ch);
    const uint32_t kh_b = smaddr(sKH + b_no * 264 + b_kh);
    const uint32_t vh_b = smaddr(sVH + v_ro * 264 + v_co);
    const uint32_t vl_b = smaddr(sVL + v_ro * 264 + v_co);

    float Oc[32][4];
#pragma unroll
    for (int t = 0; t < 32; t++) { Oc[t][0]=0.f; Oc[t][1]=0.f; Oc[t][2]=0.f; Oc[t][3]=0.f; }
    float l0 = 0.f, l1 = 0.f;

    for (int kt = 0; kt < 128; kt++) {
        const int kb = kb0 + kt * 32;
        __syncthreads();
#pragma unroll
        for (int i = 0; i < 4; i++) {
            int idx = tid + i * 256, row = idx >> 5, c8 = (idx & 31) * 8;
            *(uint4*)(sKH + row * 264 + c8) = *(const uint4*)(g_Khi + (size_t)(kb + row) * HD + c8);
        }
#pragma unroll
        for (int i = 0; i < 4; i++) {
            int idx = tid + i * 256, row = idx >> 5, c8 = (idx & 31) * 8;
            *(uint4*)(sVH + row * 264 + c8) = *(const uint4*)(g_Vhi + (size_t)(kb + row) * HD + c8);
            *(uint4*)(sVL + row * 264 + c8) = *(const uint4*)(g_Vlo + (size_t)(kb + row) * HD + c8);
        }
        __syncthreads();

        // ---- S = Q K^T: fp16, hi·hi + (lo·hi)/2048 ----
        float Sc[4][4], Sl[4][4];
#pragma unroll
        for (int t = 0; t < 4; t++) {
            Sc[t][0]=0.f; Sc[t][1]=0.f; Sc[t][2]=0.f; Sc[t][3]=0.f;
            Sl[t][0]=0.f; Sl[t][1]=0.f; Sl[t][2]=0.f; Sl[t][3]=0.f;
        }
#pragma unroll
        for (int ks = 0; ks < 16; ks++) {
            uint32_t aH[4], aL[4];
            ldsm4(aH, qh_a + ks * 32);
            ldsm4(aL, ql_a + ks * 32);
#pragma unroll
            for (int tp = 0; tp < 2; tp++) {
                uint32_t bH[4];
                ldsm4(bH, kh_b + tp * 8448 + ks * 32);
                mma_f16(Sc[tp*2],   aH[0], aH[1], aH[2], aH[3], bH[0], bH[1]);
                mma_f16(Sl[tp*2],   aL[0], aL[1], aL[2], aL[3], bH[0], bH[1]);
                mma_f16(Sc[tp*2+1], aH[0], aH[1], aH[2], aH[3], bH[2], bH[3]);
                mma_f16(Sl[tp*2+1], aL[0], aL[1], aL[2], aL[3], bH[2], bH[3]);
            }
        }
        // ---- softmax + P fragments (bf16 hi/lo) ----
        uint32_t pH[2][4], pL[2][4];
        float rs0 = 0.f, rs1 = 0.f;
#pragma unroll
        for (int t = 0; t < 4; t++) {
            float e0 = __expf(Sc[t][0] + Sl[t][0] * INVLO - cs0);
            float e1 = __expf(Sc[t][1] + Sl[t][1] * INVLO - cs0);
            float e2 = __expf(Sc[t][2] + Sl[t][2] * INVLO - cs1);
            float e3 = __expf(Sc[t][3] + Sl[t][3] * INVLO - cs1);
            rs0 += e0 + e1; rs1 += e2 + e3;
            bf16 h0=__float2bfloat16(e0), h1=__float2bfloat16(e1);
            bf16 h2=__float2bfloat16(e2), h3=__float2bfloat16(e3);
            float q0=e0-__bfloat162float(h0), q1=e1-__bfloat162float(h1);
            float q2=e2-__bfloat162float(h2), q3=e3-__bfloat162float(h3);
            int ksp = t >> 1, hi2 = (t & 1) * 2;
            pH[ksp][hi2]     = ((uint32_t)__bfloat16_as_ushort(h1) << 16) | (uint32_t)__bfloat16_as_ushort(h0);
            pH[ksp][hi2 + 1] = ((uint32_t)__bfloat16_as_ushort(h3) << 16) | (uint32_t)__bfloat16_as_ushort(h2);
            pL[ksp][hi2]     = packbf(q0, q1);
            pL[ksp][hi2 + 1] = packbf(q2, q3);
        }
        rs0 += __shfl_xor_sync(0xffffffffu, rs0, 1);
        rs0 += __shfl_xor_sync(0xffffffffu, rs0, 2);
        rs1 += __shfl_xor_sync(0xffffffffu, rs1, 1);
        rs1 += __shfl_xor_sync(0xffffffffu, rs1, 2);
        l0 += rs0; l1 += rs1;

        // ---- O += P V (bf16, 3 combos; V via ldmatrix.trans from [k][n]) ----
#pragma unroll
        for (int ks2 = 0; ks2 < 2; ks2++) {
#pragma unroll
            for (int tp = 0; tp < 16; tp++) {
                uint32_t bH[4], bL[4];
                ldsm4t(bH, vh_b + ks2 * 8448 + tp * 32);
                ldsm4t(bL, vl_b + ks2 * 8448 + tp * 32);
                mma_bf16(Oc[tp*2], pH[ks2][0], pH[ks2][1], pH[ks2][2], pH[ks2][3], bH[0], bH[1]);
                mma_bf16(Oc[tp*2], pH[ks2][0], pH[ks2][1], pH[ks2][2], pH[ks2][3], bL[0], bL[1]);
                mma_bf16(Oc[tp*2], pL[ks2][0], pL[ks2][1], pL[ks2][2], pL[ks2][3], bH[0], bH[1]);
                mma_bf16(Oc[tp*2+1], pH[ks2][0], pH[ks2][1], pH[ks2][2], pH[ks2][3], bH[2], bH[3]);
                mma_bf16(Oc[tp*2+1], pH[ks2][0], pH[ks2][1], pH[ks2][2], pH[ks2][3], bL[2], bL[3]);
                mma_bf16(Oc[tp*2+1], pL[ks2][0], pL[ks2][1], pL[ks2][2], pL[ks2][3], bH[2], bH[3]);
            }
        }
    }
    {
        int rg = row0 + wid * 16 + r;
        float* O = g_Opart + (size_t)half * NB * HD;
#pragma unroll
        for (int t = 0; t < 32; t++) {
            int col = t * 8 + cq;
            O[(size_t)rg * HD + col]       = Oc[t][0];
            O[(size_t)rg * HD + col + 1]   = Oc[t][1];
            O[(size_t)(rg + 8) * HD + col]     = Oc[t][2];
            O[(size_t)(rg + 8) * HD + col + 1] = Oc[t][3];
        }
        if ((lane & 3) == 0) {
            g_lpart[half * NB + rg] = l0;
            g_lpart[half * NB + rg + 8] = l1;
        }
    }
}

__global__ void flash_merge_k(){
    int row = blockIdx.x, c = threadIdx.x;
    float li = 1.f / (g_lpart[row] + g_lpart[NB + row]);
    size_t o = (size_t)row * HD + c;
    float v = (g_Opart[o] + g_Opart[(size_t)NB * HD + o]) * li;
    f16 h, l; splith(v, h, l);
    g_avhi[o] = h; g_avlo[o] = l;
}

// ---------------- atom self-attn + LN (reads fused qkv) ----------------
#define AT_SMEM_FLOATS (4*64*136+64*64+512+128)
__global__ __launch_bounds__(256,1) void atom_attn_ln_k(const float* __restrict__ xg,
                                                        const float* __restrict__ gw,
                                                        const float* __restrict__ bw){
    extern __shared__ float smf[];
    float* sx=smf; float* sq=sx+64*136; float* sk=sq+64*136; float* sv=sk+64*136;
    float* ss=sv+64*136; float* sred=ss+4096; float* srow=sred+512;
    const int tid=threadIdx.x; const int base=blockIdx.x*64;
    for(int idx=tid;idx<64*FDIM;idx+=256){
        int a=idx/FDIM,f=idx-a*FDIM;
        sx[a*136+f]=xg[(size_t)(base+a)*FDIM+f];
        size_t go=(size_t)(base+a)*N3+f;
        sq[a*136+f]=g_qkv[go]; sk[a*136+f]=g_qkv[go+FDIM]; sv[a*136+f]=g_qkv[go+2*FDIM];
    }
    __syncthreads();
    {
        int ty=tid>>4,tx=tid&15; float acc[4][4]={};
        for(int h=0;h<FDIM;h++){
            float qv[4],kv[4];
#pragma unroll
            for(int i=0;i<4;i++){qv[i]=sq[(ty*4+i)*136+h];kv[i]=sk[(tx*4+i)*136+h];}
#pragma unroll
            for(int i=0;i<4;i++)
#pragma unroll
                for(int j=0;j<4;j++)acc[i][j]+=qv[i]*kv[j];
        }
        float scl=rsqrtf(133.0f);
#pragma unroll
        for(int i=0;i<4;i++)
#pragma unroll
            for(int j=0;j<4;j++)ss[(ty*4+i)*64+tx*4+j]=acc[i][j]*scl;
    }
    __syncthreads();
    if(tid<64){
        float mx=-1e30f;
        for(int j=0;j<64;j++)mx=fmaxf(mx,ss[tid*64+j]);
        float s=0.f;
        for(int j=0;j<64;j++){float e=__expf(ss[tid*64+j]-mx);ss[tid*64+j]=e;s+=e;}
        float inv=1.f/s;
        for(int j=0;j<64;j++)ss[tid*64+j]*=inv;
    }
    __syncthreads();
    const int r=tid>>2,qd=tid&3,f0=qd*34;
    float tv[34];
#pragma unroll
    for(int f=0;f<34;f++)tv[f]=0.f;
    for(int b=0;b<64;b++){
        float p=ss[r*64+b]; const float* vb=&sv[b*136+f0];
#pragma unroll
        for(int f=0;f<34;f++)if(f0+f<FDIM)tv[f]+=p*vb[f];
    }
    float s1=0.f;
#pragma unroll
    for(int f=0;f<34;f++)if(f0+f<FDIM){tv[f]+=sx[r*136+f0+f];s1+=tv[f];}
    sred[tid]=s1; __syncthreads();
    if(qd==0)srow[r]=(sred[tid]+sred[tid+1]+sred[tid+2]+sred[tid+3])*(1.f/133.f);
    __syncthreads();
    float mu=srow[r],s2=0.f;
#pragma unroll
    for(int f=0;f<34;f++)if(f0+f<FDIM){float d=tv[f]-mu;s2+=d*d;}
    sred[tid]=s2; __syncthreads();
    if(qd==0){float var=(sred[tid]+sred[tid+1]+sred[tid+2]+sred[tid+3])*(1.f/133.f);srow[64+r]=rsqrtf(var+1e-5f);}
    __syncthreads();
    float rstd=srow[64+r];
#pragma unroll
    for(int f=0;f<34;f++){int fg=f0+f;
        if(fg<FDIM)g_fe[(size_t)(base+r)*FDIM+fg]=(tv[f]-mu)*rstd*gw[fg]+bw[fg];}
}

// ---------------- elementwise / gather ----------------
__global__ void gather_sum_k(const int* __restrict__ a2b){
    __shared__ int idx[MAXNB];
    int a=blockIdx.x,t=threadIdx.x;
    if(t<MAXNB)idx[t]=a2b[a*MAXNB+t];
    __syncthreads();
    float s=0.f;
#pragma unroll
    for(int j=0;j<MAXNB;j++)s+=g_msg[(size_t)idx[j]*HD+t];
    g_amsg[(size_t)a*HD+t]=s;
}
__global__ void dmpnn_fused_k(const int* __restrict__ a2b, const int* __restrict__ b2a,
                              const int* __restrict__ b2revb){
    __shared__ int idx[MAXNB+1];
    int b=blockIdx.x,t=threadIdx.x;
    if(t==0){
        int ia=__ldg(&b2a[b]);
#pragma unroll
        for(int j=0;j<MAXNB;j++) idx[j]=__ldg(&a2b[ia*MAXNB+j]);
        idx[MAXNB]=__ldg(&b2revb[b]);
    }
    __syncthreads();
    float s=0.f;
#pragma unroll
    for(int j=0;j<MAXNB;j++)s+=g_msg[(size_t)idx[j]*HD+t];
    float v=s-g_msg[(size_t)idx[MAXNB]*HD+t];
    f16 h,l; splith(v,h,l);
    size_t o=(size_t)b*HD+t;
    g_tmphi[o]=h; g_tmplo[o]=l;
}
__global__ void combine_k(const float* __restrict__ wal, const float* __restrict__ walb){
    __shared__ float red[256];
    __shared__ float salpha;
    int b=blockIdx.x,t=threadIdx.x;
    size_t o=(size_t)b*HD+t;
    float d=g_dmpnn[o],am=g_attm[o];
    red[t]=d*wal[t]+am*wal[256+t];
    __syncthreads();
    for(int s=128;s>0;s>>=1){if(t<s)red[t]+=red[t+s];__syncthreads();}
    if(t==0)salpha=1.f/(1.f+__expf(-(red[0]+walb[0])));
    __syncthreads();
    float al=salpha;
    float v=fmaxf(g_inputs[o]+al*d+(1.f-al)*am,0.f);
    g_msg[o]=v;
    f16 h,l; splith(v,h,l);
    g_msghi[o]=h; g_msglo[o]=l;
}
__global__ void concat_split_k(){
    int i=blockIdx.x*blockDim.x+threadIdx.x;
    if(i>=NA*KP_WO)return;
    int row=i/KP_WO,c=i-row*KP_WO;
    float x = (c<FDIM) ? g_fe[(size_t)row*FDIM+c]
             : (c<FDIM+HD ? g_amsg[(size_t)row*HD+(c-FDIM)] : 0.f);
    f16 h,l; splith(x,h,l);
    g_cathi[i]=h; g_catlo[i]=l;
}

// ---------------- molecule pooling ----------------
#define MP_SMEM_FLOATS (2*64*260+4096)
__global__ __launch_bounds__(256,1) void mol_pool_k(const float* __restrict__ Wb,
                                                    const float* __restrict__ bb,
                                                    float* __restrict__ outg){
    extern __shared__ float smf[];
    float* shm=smf; float* sw=shm+64*260; float* ssc=sw+64*260;
    const int tid=threadIdx.x; const int base=blockIdx.x*64;
    for(int idx=tid;idx<64*HD;idx+=256){
        int a=idx>>8,c=idx&255;
        shm[a*260+c]=g_atomh[(size_t)(base+a)*HD+c];
        sw[a*260+c]=g_hmwa[(size_t)(base+a)*HD+c];
    }
    __syncthreads();
    {
        int ty=tid>>4,tx=tid&15; float acc[4][4]={};
        for(int h=0;h<HD;h++){
            float qv[4],kv[4];
#pragma unroll
            for(int i=0;i<4;i++){qv[i]=sw[(ty*4+i)*260+h];kv[i]=shm[(tx*4+i)*260+h];}
#pragma unroll
            for(int i=0;i<4;i++)
#pragma unroll
                for(int j=0;j<4;j++)acc[i][j]+=qv[i]*kv[j];
        }
#pragma unroll
        for(int i=0;i<4;i++)
#pragma unroll
            for(int j=0;j<4;j++)ssc[(ty*4+i)*64+tx*4+j]=acc[i][j];
    }
    __syncthreads();
    if(tid<64){
        float mx=-1e30f;
        for(int j=0;j<64;j++)mx=fmaxf(mx,ssc[tid*64+j]);
        float s=0.f;
        for(int j=0;j<64;j++){float e=__expf(ssc[tid*64+j]-mx);ssc[tid*64+j]=e;s+=e;}
        float inv=1.f/s;
        for(int j=0;j<64;j++)ssc[tid*64+j]*=inv;
    }
    __syncthreads();
    const int c=tid;
    float acc[64];
#pragma unroll
    for(int a=0;a<64;a++)acc[a]=0.f;
    for(int b=0;b<64;b++){
        float hv=shm[b*260+c];
#pragma unroll 16
        for(int a=0;a<64;a++)acc[a]+=ssc[a*64+b]*hv;
    }
    __syncthreads();
    for(int a=0;a<64;a++)sw[a*260+c]=acc[a];
    __syncthreads();
#pragma unroll
    for(int a=0;a<64;a++)acc[a]=0.f;
    for(int k=0;k<HD;k++){
        float wv=Wb[(size_t)k*HD+c];
#pragma unroll 16
        for(int a=0;a<64;a++)acc[a]+=sw[a*260+k]*wv;
    }
    float bv=bb[c],s=0.f;
    for(int a=0;a<64;a++){
        float t=fmaxf(acc[a]+bv,0.f);
        s+=shm[a*260+c]+t;
    }
    outg[(size_t)blockIdx.x*HD+c]=s*(1.f/64.f);
}

// ---------------- host driver ----------------
static float* symf(const void* s){ void* p=nullptr; cudaGetSymbolAddress(&p,s); return (float*)p; }
static f16* symh(const void* s){ void* p=nullptr; cudaGetSymbolAddress(&p,s); return (f16*)p; }
static bf16* symb(const void* s){ void* p=nullptr; cudaGetSymbolAddress(&p,s); return (bf16*)p; }

extern "C" void kernel_launch(void* const* d_in, const int* in_sizes, int n_in,
                              void* d_out, int out_size){
    const float* f_atoms=(const float*)d_in[0];
    const float* f_bonds=(const float*)d_in[1];
    const float* Wq_atom=(const float*)d_in[2];
    const float* Wk_atom=(const float*)d_in[3];
    const float* Wv_atom=(const float*)d_in[4];
    const float* ln_g=(const float*)d_in[5];
    const float* ln_b=(const float*)d_in[6];
    const float* Wi=(const float*)d_in[7];
    const float* Wh=(const float*)d_in[8];
    const float* Wq=(const float*)d_in[9];
    const float* Wk=(const float*)d_in[10];
    const float* Wv=(const float*)d_in[11];
    const float* Wa=(const float*)d_in[12];
    const float* Walw=(const float*)d_in[13];
    const float* Walb=(const float*)d_in[14];
    const float* Wow=(const float*)d_in[15];
    const float* Wob=(const float*)d_in[16];
    const float* Wbw=(const float*)d_in[17];
    const float* Wbb=(const float*)d_in[18];
    const int* a2b=(const int*)d_in[19];
    const int* b2a=(const int*)d_in[20];
    const int* b2revb=(const int*)d_in[21];
    float* out=(float*)d_out;

    float* p_W3=symf(g_W3); float* p_qkv=symf(g_qkv);
    float* p_inputs=symf(g_inputs); float* p_msg=symf(g_msg);
    float* p_dmpnn=symf(g_dmpnn); float* p_attm=symf(g_attm);
    float* p_atomh=symf(g_atomh); float* p_hmwa=symf(g_hmwa);
    f16* p_Qhi=symh(g_Qhi); f16* p_Qlo=symh(g_Qlo);
    f16* p_Khi=symh(g_Khi); f16* p_Klo=symh(g_Klo);
    bf16* p_Vhi=symb(g_Vhi); bf16* p_Vlo=symb(g_Vlo);
    f16* p_msghi=symh(g_msghi); f16* p_msglo=symh(g_msglo);
    f16* p_tmphi=symh(g_tmphi); f16* p_tmplo=symh(g_tmplo);
    f16* p_avhi=symh(g_avhi); f16* p_avlo=symh(g_avlo);
    f16* p_fbhi=symh(g_fbhi); f16* p_fblo=symh(g_fblo);
    f16* p_cathi=symh(g_cathi); f16* p_catlo=symh(g_catlo);
    f16* p_ahhi=symh(g_ahhi); f16* p_ahlo=symh(g_ahlo);
    f16* p_Withi=symh(g_Withi); f16* p_Witlo=symh(g_Witlo);
    f16* p_Whthi=symh(g_Whthi); f16* p_Whtlo=symh(g_Whtlo);
    f16* p_Wqthi=symh(g_Wqthi); f16* p_Wqtlo=symh(g_Wqtlo);
    f16* p_Wkthi=symh(g_Wkthi); f16* p_Wktlo=symh(g_Wktlo);
    f16* p_Wvthi=symh(g_Wvthi); f16* p_Wvtlo=symh(g_Wvtlo);
    f16* p_Wathi=symh(g_Wathi); f16* p_Watlo=symh(g_Watlo);
    f16* p_Wothi=symh(g_Wothi); f16* p_Wotlo=symh(g_Wotlo);

    const int AT_SMEM=AT_SMEM_FLOATS*4, MP_SMEM=MP_SMEM_FLOATS*4;
    cudaFuncSetAttribute(flash_mma,cudaFuncAttributeMaxDynamicSharedMemorySize,FL_SMEM);
    cudaFuncSetAttribute(atom_attn_ln_k,cudaFuncAttributeMaxDynamicSharedMemorySize,AT_SMEM);
    cudaFuncSetAttribute(mol_pool_k,cudaFuncAttributeMaxDynamicSharedMemorySize,MP_SMEM);

    const int WALL = SZ_WI + 5*SZ_H + SZ_WO;
    wsplit_all_k<<<(WALL+255)/256,256>>>(Wi,Wh,Wq,Wk,Wv,Wa,Wow);
    asplit_k<<<(NB*KP_WI)/256,256>>>(f_bonds,p_fbhi,p_fblo,BFDIM,KP_WI);
    w3copy_k<<<(FDIM*N3+255)/256,256>>>(Wq_atom,Wk_atom,Wv_atom);

    dim3 gqa((N3+63)/64,(NA+63)/64);
    gemm_k<0,0><<<gqa,256>>>(f_atoms,p_W3,nullptr,p_qkv,NA,N3,FDIM);
    atom_attn_ln_k<<<NMOL,256,AT_SMEM>>>(f_atoms,ln_g,ln_b);

    dim3 tgb(4,NB/128), tga(4,NA/128);
    tgemm<1,0,0,1,1,1,0><<<tgb,256>>>(p_fbhi,p_fblo,p_Withi,p_Witlo,nullptr,
                                      p_msg,p_msghi,p_msglo,nullptr,nullptr,p_inputs,NB,KP_WI);

    for(int it=0;it<3;it++){
        dmpnn_fused_k<<<NB,256>>>(a2b,b2a,b2revb);
        tgemm<0,0,0,1,0,0,0><<<tgb,256>>>(p_tmphi,p_tmplo,p_Whthi,p_Whtlo,nullptr,
                                          p_dmpnn,nullptr,nullptr,nullptr,nullptr,nullptr,NB,HD);
        tgemm<0,0,1,0,1,0,0><<<tgb,256>>>(p_msghi,p_msglo,p_Wqthi,p_Wqtlo,nullptr,
                                          nullptr,p_Qhi,p_Qlo,nullptr,nullptr,nullptr,NB,HD);
        tgemm<0,0,0,0,1,0,0><<<tgb,256>>>(p_msghi,p_msglo,p_Wkthi,p_Wktlo,nullptr,
                                          nullptr,p_Khi,p_Klo,nullptr,nullptr,nullptr,NB,HD);
        tgemm<0,0,0,0,0,0,1><<<tgb,256>>>(p_msghi,p_msglo,p_Wvthi,p_Wvtlo,nullptr,
                                          nullptr,nullptr,nullptr,p_Vhi,p_Vlo,nullptr,NB,HD);
        flash_mma<<<dim3(NB/128,2),256,FL_SMEM>>>();
        flash_merge_k<<<NB,256>>>();
        tgemm<0,0,0,1,0,0,0><<<tgb,256>>>(p_avhi,p_avlo,p_Wathi,p_Watlo,nullptr,
                                          p_attm,nullptr,nullptr,nullptr,nullptr,nullptr,NB,HD);
        combine_k<<<NB,256>>>(Walw,Walb);
    }

    gather_sum_k<<<NA,256>>>(a2b);
    concat_split_k<<<(NA*KP_WO+255)/256,256>>>();
    tgemm<1,1,0,1,1,0,0><<<tga,256>>>(p_cathi,p_catlo,p_Wothi,p_Wotlo,Wob,
                                      p_atomh,p_ahhi,p_ahlo,nullptr,nullptr,nullptr,NA,KP_WO);
    tgemm<0,0,0,1,0,0,0><<<tga,256>>>(p_ahhi,p_ahlo,p_Wathi,p_Watlo,nullptr,
                                      p_hmwa,nullptr,nullptr,nullptr,nullptr,nullptr,NA,HD);
    mol_pool_k<<<NMOL,256,MP_SMEM>>>(Wbw,Wbb,out);
}